// round 12
// baseline (speedup 1.0000x reference)
#include <cuda_runtime.h>
#include <cuda_bf16.h>
#include <math.h>
#include <stdint.h>

#define NBATCH 2
#define CDIM 320
#define NTOK 16384
#define DIN 1352
#define DINNER 640
#define CONVD 704
#define DSTATE 32
#define NH 8
#define HP 80
#define NCHUNK 256
#define INNERD 160
#define MLPD 1024

typedef __nv_bfloat16 bf16;

constexpr size_t SZ_XF   = (size_t)NBATCH*NTOK*CDIM;
constexpr size_t SZ_ZX   = (size_t)NBATCH*NTOK*DIN;
constexpr size_t SZ_XBC  = (size_t)NBATCH*NTOK*CONVD;
constexpr size_t SZ_DTB  = (size_t)NBATCH*NH*NTOK;
constexpr size_t SZ_SL   = (size_t)NBATCH*NH*NCHUNK*DSTATE*HP;
constexpr size_t SZ_Y    = (size_t)NBATCH*NTOK*DINNER;
constexpr size_t SZ_KPE  = (size_t)NTOK*CDIM;
constexpr size_t SZ_I160 = (size_t)NBATCH*NTOK*INNERD;
constexpr size_t SZ_ATT  = (size_t)48*NTOK;

constexpr size_t OFF_XF    = 0;
constexpr size_t OFF_ZX    = OFF_XF    + SZ_XF;
constexpr size_t OFF_XBC   = OFF_ZX    + SZ_ZX;
constexpr size_t OFF_DTB   = OFF_XBC   + SZ_XBC;
constexpr size_t OFF_CUM   = OFF_DTB   + SZ_DTB;
constexpr size_t OFF_CSUM  = OFF_CUM   + SZ_DTB;
constexpr size_t OFF_SLOC  = OFF_CSUM  + (size_t)NBATCH*NH*NCHUNK;
constexpr size_t OFF_SBEG  = OFF_SLOC  + SZ_SL;
constexpr size_t OFF_Y     = OFF_SBEG  + SZ_SL;
constexpr size_t OFF_KEYS  = OFF_Y     + SZ_Y;
constexpr size_t OFF_KPE   = OFF_KEYS  + SZ_XF;
constexpr size_t OFF_TKIQ  = OFF_KPE   + SZ_KPE;
constexpr size_t OFF_TV    = OFF_TKIQ  + 2 * SZ_I160;
constexpr size_t OFF_ATT   = OFF_TV    + SZ_I160;
constexpr size_t OFF_Q     = OFF_ATT   + SZ_ATT;
constexpr size_t OFF_QPE   = OFF_Q     + 3840;
constexpr size_t OFF_SQ    = OFF_QPE   + 3840;
constexpr size_t OFF_SK    = OFF_SQ    + 3840;
constexpr size_t OFF_SV    = OFF_SK    + 3840;
constexpr size_t OFF_SO    = OFF_SV    + 3840;
constexpr size_t OFF_QS160 = OFF_SO    + 3840;
constexpr size_t OFF_KS160 = OFF_QS160 + 1920;
constexpr size_t OFF_VS160 = OFF_KS160 + 1920;
constexpr size_t OFF_TATT  = OFF_VS160 + 1920;
constexpr size_t OFF_MLPH  = OFF_TATT  + 1920;
constexpr size_t OFF_XNH   = OFF_MLPH + 12288;
constexpr size_t OFF_XNL   = OFF_XNH + 5242880;
constexpr size_t OFF_YH    = OFF_XNL + 5242880;
constexpr size_t OFF_YL    = OFF_YH  + 10485760;
constexpr size_t OFF_KH    = OFF_YL  + 10485760;
constexpr size_t OFF_KL    = OFF_KH  + 5242880;
constexpr size_t OFF_KPH   = OFF_KL  + 5242880;
constexpr size_t OFF_KPL   = OFF_KPH + 5242880;
constexpr size_t OFF_IAH   = OFF_KPL + 5242880;
constexpr size_t OFF_IAL   = OFF_IAH + 3145728;
constexpr size_t OFF_INWH  = OFF_IAL + 3145728;
constexpr size_t OFF_INWL  = OFF_INWH + 225280;
constexpr size_t OFF_OUTWH = OFF_INWL + 225280;
constexpr size_t OFF_OUTWL = OFF_OUTWH + 122880;
constexpr size_t OFF_T2IV  = OFF_OUTWL + 122880;
constexpr size_t OFF_I2TOW = OFF_T2IV + 163840;
constexpr size_t OFF_XPART = OFF_I2TOW + 147456;
constexpr size_t OFF_WKQ   = OFF_XPART + 16384;
constexpr size_t OFF_BKQ   = OFF_WKQ + 245760;
constexpr size_t ARENA_FLOATS = OFF_BKQ + 768;

__device__ __align__(128) float g_arena[ARENA_FLOATS];

__device__ __forceinline__ uint32_t smem_u32(const void* p) {
    uint32_t a;
    asm("{ .reg .u64 t; cvta.to.shared.u64 t, %1; cvt.u32.u64 %0, t; }" : "=r"(a) : "l"(p));
    return a;
}
__device__ __forceinline__ void ldm_x4(uint32_t* r, uint32_t a) {
    asm volatile("ldmatrix.sync.aligned.m8n8.x4.shared.b16 {%0,%1,%2,%3}, [%4];"
        : "=r"(r[0]), "=r"(r[1]), "=r"(r[2]), "=r"(r[3]) : "r"(a));
}
__device__ __forceinline__ void mma16816(float* c, const uint32_t* a, const uint32_t* b) {
    asm volatile("mma.sync.aligned.m16n8k16.row.col.f32.bf16.bf16.f32 "
        "{%0,%1,%2,%3}, {%4,%5,%6,%7}, {%8,%9}, {%0,%1,%2,%3};"
        : "+f"(c[0]), "+f"(c[1]), "+f"(c[2]), "+f"(c[3])
        : "r"(a[0]), "r"(a[1]), "r"(a[2]), "r"(a[3]), "r"(b[0]), "r"(b[1]));
}
__device__ __forceinline__ void cpasync16(uint32_t dst, const void* src) {
    asm volatile("cp.async.cg.shared.global [%0], [%1], 16;" :: "r"(dst), "l"(src));
}
__device__ __forceinline__ void split_bf16(float v, bf16& h, bf16& l) {
    h = __float2bfloat16(v);
    l = __float2bfloat16(v - __bfloat162float(h));
}

__device__ __forceinline__ float blockReduceSum(float v) {
    __shared__ float sh[33];
    int lane = threadIdx.x & 31, wid = threadIdx.x >> 5;
#pragma unroll
    for (int o = 16; o; o >>= 1) v += __shfl_down_sync(0xffffffffu, v, o);
    if (lane == 0) sh[wid] = v;
    __syncthreads();
    int nw = (blockDim.x + 31) >> 5;
    if (wid == 0) {
        v = (lane < nw) ? sh[lane] : 0.f;
#pragma unroll
        for (int o = 16; o; o >>= 1) v += __shfl_down_sync(0xffffffffu, v, o);
        if (lane == 0) sh[32] = v;
    }
    __syncthreads();
    v = sh[32];
    __syncthreads();
    return v;
}
__device__ __forceinline__ float2 blockReduceSum2(float a, float b) {
    __shared__ float sh[66];
    int lane = threadIdx.x & 31, wid = threadIdx.x >> 5;
#pragma unroll
    for (int o = 16; o; o >>= 1) {
        a += __shfl_down_sync(0xffffffffu, a, o);
        b += __shfl_down_sync(0xffffffffu, b, o);
    }
    if (lane == 0) { sh[wid * 2] = a; sh[wid * 2 + 1] = b; }
    __syncthreads();
    int nw = (blockDim.x + 31) >> 5;
    if (wid == 0) {
        a = (lane < nw) ? sh[lane * 2] : 0.f;
        b = (lane < nw) ? sh[lane * 2 + 1] : 0.f;
#pragma unroll
        for (int o = 16; o; o >>= 1) {
            a += __shfl_down_sync(0xffffffffu, a, o);
            b += __shfl_down_sync(0xffffffffu, b, o);
        }
        if (lane == 0) { sh[64] = a; sh[65] = b; }
    }
    __syncthreads();
    float2 r = make_float2(sh[64], sh[65]);
    __syncthreads();
    return r;
}
__device__ __forceinline__ float blockReduceMax(float v) {
    __shared__ float sh[33];
    int lane = threadIdx.x & 31, wid = threadIdx.x >> 5;
#pragma unroll
    for (int o = 16; o; o >>= 1) v = fmaxf(v, __shfl_down_sync(0xffffffffu, v, o));
    if (lane == 0) sh[wid] = v;
    __syncthreads();
    int nw = (blockDim.x + 31) >> 5;
    if (wid == 0) {
        v = (lane < nw) ? sh[lane] : -1e30f;
#pragma unroll
        for (int o = 16; o; o >>= 1) v = fmaxf(v, __shfl_down_sync(0xffffffffu, v, o));
        if (lane == 0) sh[32] = v;
    }
    __syncthreads();
    v = sh[32];
    __syncthreads();
    return v;
}
__device__ __forceinline__ float siluf(float x) { return x / (1.f + expf(-x)); }

// ---- tensor-core split GEMM (stable since R9) ----
__global__ void __launch_bounds__(256, 2)
k_mma(const bf16* __restrict__ aH, const bf16* __restrict__ aL,
      const bf16* __restrict__ wH, const bf16* __restrict__ wL,
      const float* __restrict__ bias, const float* __restrict__ R,
      float* __restrict__ C, bf16* __restrict__ cH, bf16* __restrict__ cL,
      const float* __restrict__ pe, bf16* __restrict__ peH, bf16* __restrict__ peL,
      int Nact, int Kd, int nkb) {
    extern __shared__ bf16 sm[];
    constexpr int TSZ = 128 * 40;
    const int tid = threadIdx.x;
    const int wid = tid >> 5, lane = tid & 31;
    const int wm = wid & 1, wn = wid >> 1;
    const int m0 = blockIdx.y * 128, n0 = blockIdx.x * 128;

    const bf16* srcs[4] = { aH + (size_t)m0 * Kd, aL + (size_t)m0 * Kd,
                            wH + (size_t)n0 * Kd, wL + (size_t)n0 * Kd };
    const int lrow = tid >> 2, lc8 = (tid & 3) * 8;

    auto prefetch = [&](int kb, int buf) {
#pragma unroll
        for (int q = 0; q < 4; q++) {
            bf16* t = sm + buf * 4 * TSZ + q * TSZ;
#pragma unroll
            for (int l = 0; l < 2; l++) {
                int row = lrow + l * 64;
                cpasync16(smem_u32(t + row * 40 + lc8),
                          srcs[q] + (size_t)row * Kd + kb * 32 + lc8);
            }
        }
        asm volatile("cp.async.commit_group;");
    };

    float acc[4][4][4];
#pragma unroll
    for (int i = 0; i < 4; i++)
#pragma unroll
        for (int j = 0; j < 4; j++)
#pragma unroll
            for (int r = 0; r < 4; r++) acc[i][j][r] = 0.f;

    prefetch(0, 0);
    if (nkb > 1) prefetch(1, 1);

    const int arow = wm * 64 + (((lane >> 3) & 1) << 3) + (lane & 7);
    const int acol = ((lane >> 4) << 3);
    const int brow = wn * 32 + ((lane >> 4) << 3) + (lane & 7);
    const int bcol = (((lane >> 3) & 1) << 3);

    for (int kb = 0; kb < nkb; kb++) {
        if (kb + 1 < nkb) asm volatile("cp.async.wait_group 1;");
        else              asm volatile("cp.async.wait_group 0;");
        __syncthreads();
        const int buf = kb & 1;
        const bf16* tAH = sm + buf * 4 * TSZ;
        const bf16* tAL = tAH + TSZ;
        const bf16* tWH = tAH + 2 * TSZ;
        const bf16* tWL = tAH + 3 * TSZ;
#pragma unroll
        for (int ks = 0; ks < 2; ks++) {
            uint32_t aHf[4][4], aLf[4][4];
#pragma unroll
            for (int mi = 0; mi < 4; mi++) {
                int off = (arow + mi * 16) * 40 + ks * 16 + acol;
                ldm_x4(aHf[mi], smem_u32(tAH + off));
                ldm_x4(aLf[mi], smem_u32(tAL + off));
            }
#pragma unroll
            for (int nfp = 0; nfp < 2; nfp++) {
                uint32_t bHf[4], bLf[4];
                int off = (brow + nfp * 16) * 40 + ks * 16 + bcol;
                ldm_x4(bHf, smem_u32(tWH + off));
                ldm_x4(bLf, smem_u32(tWL + off));
#pragma unroll
                for (int mi = 0; mi < 4; mi++) {
                    mma16816(acc[mi][nfp * 2 + 0], aHf[mi], bHf);
                    mma16816(acc[mi][nfp * 2 + 1], aHf[mi], bHf + 2);
                }
#pragma unroll
                for (int mi = 0; mi < 4; mi++) {
                    mma16816(acc[mi][nfp * 2 + 0], aHf[mi], bLf);
                    mma16816(acc[mi][nfp * 2 + 1], aHf[mi], bLf + 2);
                }
#pragma unroll
                for (int mi = 0; mi < 4; mi++) {
                    mma16816(acc[mi][nfp * 2 + 0], aLf[mi], bHf);
                    mma16816(acc[mi][nfp * 2 + 1], aLf[mi], bHf + 2);
                }
            }
        }
        __syncthreads();
        if (kb + 2 < nkb) prefetch(kb + 2, buf);
    }

    const int qr = lane >> 2, qc = (lane & 3) * 2;
#pragma unroll
    for (int mi = 0; mi < 4; mi++)
#pragma unroll
        for (int nf = 0; nf < 4; nf++) {
            int n = n0 + wn * 32 + nf * 8 + qc;
            if (n >= Nact) continue;
#pragma unroll
            for (int h = 0; h < 2; h++) {
                int m = m0 + wm * 64 + mi * 16 + qr + h * 8;
                float v0 = acc[mi][nf][h * 2 + 0];
                float v1 = acc[mi][nf][h * 2 + 1];
                if (bias) { v0 += bias[n]; v1 += bias[n + 1]; }
                size_t o = (size_t)m * Nact + n;
                if (R) { v0 += R[o]; v1 += R[o + 1]; }
                C[o] = v0; C[o + 1] = v1;
                bf16 hh, ll;
                if (cH) {
                    split_bf16(v0, hh, ll); cH[o] = hh;     cL[o] = ll;
                    split_bf16(v1, hh, ll); cH[o + 1] = hh; cL[o + 1] = ll;
                }
                if (peH) {
                    size_t pi = (size_t)(m & (NTOK - 1)) * Nact + n;
                    split_bf16(v0 + pe[pi], hh, ll);     peH[o] = hh;     peL[o] = ll;
                    split_bf16(v1 + pe[pi + 1], hh, ll); peH[o + 1] = hh; peL[o + 1] = ll;
                }
            }
        }
}

__global__ void k_wsplit(const float* __restrict__ W, bf16* __restrict__ hi,
                         bf16* __restrict__ lo, int N, int K, int Npad, int Kpad) {
    int idx = blockIdx.x * 256 + threadIdx.x;
    if (idx >= Npad * Kpad) return;
    int n = idx / Kpad, k = idx % Kpad;
    float v = (n < N && k < K) ? W[(size_t)n * K + k] : 0.f;
    bf16 h, l;
    split_bf16(v, h, l);
    hi[idx] = h; lo[idx] = l;
}

__global__ void k_wsplit_cat(const float* __restrict__ W1, const float* __restrict__ W2,
                             bf16* __restrict__ hi, bf16* __restrict__ lo) {
    int idx = blockIdx.x * 256 + threadIdx.x;
    if (idx >= 384 * 320) return;
    int n = idx / 320, k = idx % 320;
    float v = 0.f;
    if (n < 160) v = W1[(size_t)n * 320 + k];
    else if (n < 320) v = W2[(size_t)(n - 160) * 320 + k];
    bf16 h, l;
    split_bf16(v, h, l);
    hi[idx] = h; lo[idx] = l;
}

__global__ void k_biascat(const float* __restrict__ b1, const float* __restrict__ b2,
                          float* __restrict__ dst) {
    int n = threadIdx.x;
    dst[n] = (n < 160) ? b1[n] : ((n < 320) ? b2[n - 160] : 0.f);
}

__global__ void k_tln(const float* __restrict__ x, const float* __restrict__ w,
                      const float* __restrict__ b, bf16* __restrict__ hi,
                      bf16* __restrict__ lo) {
    __shared__ float tile[320 * 33];
    __shared__ float mu[32], rs[32];
    int bq = blockIdx.y;
    int t0 = blockIdx.x * 32;
    int tid = threadIdx.x;
    for (int e = tid; e < 320 * 32; e += 256) {
        int c = e >> 5, tok = e & 31;
        tile[c * 33 + tok] = x[((size_t)(bq * CDIM + c)) * NTOK + t0 + tok];
    }
    __syncthreads();
    int wid = tid >> 5, lane = tid & 31;
#pragma unroll
    for (int k = 0; k < 4; k++) {
        int tok = wid * 4 + k;
        float s = 0.f, v = 0.f;
        for (int c = lane; c < 320; c += 32) {
            float t = tile[c * 33 + tok];
            s += t; v += t * t;
        }
#pragma unroll
        for (int o = 16; o; o >>= 1) {
            s += __shfl_down_sync(0xffffffffu, s, o);
            v += __shfl_down_sync(0xffffffffu, v, o);
        }
        if (lane == 0) {
            float m = s / 320.f;
            mu[tok] = m;
            rs[tok] = rsqrtf(v / 320.f - m * m + 1e-5f);
        }
    }
    __syncthreads();
    for (int e = tid; e < 10240; e += 256) {
        int tok = e / 320, c = e % 320;
        float r = (tile[c * 33 + tok] - mu[tok]) * rs[tok] * w[c] + b[c];
        size_t o = ((size_t)(bq * NTOK + t0 + tok)) * 320 + c;
        bf16 h, l;
        split_bf16(r, h, l);
        hi[o] = h; lo[o] = l;
    }
}

__global__ void k_transpose_out(const float* __restrict__ keys, float* __restrict__ out) {
    __shared__ float tile[32][33];
    int b = blockIdx.z;
    int t0 = blockIdx.x * 32, c0 = blockIdx.y * 32;
#pragma unroll
    for (int i = 0; i < 4; i++) {
        int tt = threadIdx.y + i * 8;
        tile[threadIdx.x][tt] = keys[((size_t)(b * NTOK + t0 + tt)) * CDIM + c0 + threadIdx.x];
    }
    __syncthreads();
#pragma unroll
    for (int i = 0; i < 4; i++) {
        int cc = threadIdx.y + i * 8;
        out[((size_t)(b * CDIM + c0 + cc)) * NTOK + t0 + threadIdx.x] = tile[cc][threadIdx.x];
    }
}

__global__ void k_ln(const float* __restrict__ src, float* __restrict__ dst,
                     const float* __restrict__ w, const float* __restrict__ b,
                     bf16* __restrict__ hi, bf16* __restrict__ lo,
                     const float* __restrict__ pe, bf16* __restrict__ peH,
                     bf16* __restrict__ peL) {
    int row = blockIdx.x;
    int D = blockDim.x;
    float v = src[(size_t)row * D + threadIdx.x];
    float2 sv = blockReduceSum2(v, v * v);
    float m = sv.x / D;
    float var = sv.y / D - m * m;
    float r = (v - m) * rsqrtf(var + 1e-5f) * w[threadIdx.x] + b[threadIdx.x];
    size_t o = (size_t)row * D + threadIdx.x;
    if (dst) dst[o] = r;
    bf16 h, l;
    if (hi) { split_bf16(r, h, l); hi[o] = h; lo[o] = l; }
    if (peH) {
        float pv = r + pe[(size_t)(row & (NTOK - 1)) * D + threadIdx.x];
        split_bf16(pv, h, l);
        peH[o] = h; peL[o] = l;
    }
}

// 12-row batched small GEMM: coalesced W (read once), A staged in smem.
// grid = ceil(N/64), block = 256. dyn smem = 12*K*4 + 64*65*4.
__global__ void k_tiny12(const float* __restrict__ A1, const float* __restrict__ A2,
                         const float* __restrict__ W, const float* __restrict__ bias,
                         const float* __restrict__ R, float* __restrict__ C,
                         int N, int K, int act) {
    extern __shared__ float smem[];
    float* sA = smem;             // 12*K
    float* sW = smem + 12 * K;    // 64*65
    int tid = threadIdx.x;
    for (int e = tid; e < 12 * K; e += 256) {
        float v = A1[e];
        if (A2) v += A2[e];
        sA[e] = v;
    }
    int n0 = blockIdx.x * 64;
    int i = tid & 63;
    int rg = tid >> 6;  // 0..3, rows rg*3..rg*3+2
    float acc0 = 0.f, acc1 = 0.f, acc2 = 0.f;
    const float* a0 = sA + (rg * 3 + 0) * K;
    const float* a1 = sA + (rg * 3 + 1) * K;
    const float* a2 = sA + (rg * 3 + 2) * K;
    for (int k0 = 0; k0 < K; k0 += 64) {
        __syncthreads();
        for (int e = tid; e < 4096; e += 256) {
            int rr = e >> 6, kk = e & 63;
            int n = n0 + rr;
            sW[rr * 65 + kk] = (n < N) ? W[(size_t)n * K + k0 + kk] : 0.f;
        }
        __syncthreads();
#pragma unroll 8
        for (int k = 0; k < 64; k++) {
            float wv = sW[i * 65 + k];
            acc0 += a0[k0 + k] * wv;
            acc1 += a1[k0 + k] * wv;
            acc2 += a2[k0 + k] * wv;
        }
    }
    int n = n0 + i;
    if (n >= N) return;
    float av[3] = {acc0, acc1, acc2};
#pragma unroll
    for (int j = 0; j < 3; j++) {
        int r = rg * 3 + j;
        float v = av[j];
        if (bias) v += bias[n];
        if (act == 1) v = fmaxf(v, 0.f);
        if (R) v += R[(size_t)r * N + n];
        C[(size_t)r * N + n] = v;
    }
}

// 8-token tiled conv + dt
__global__ void k_convdt8(const float* __restrict__ zx, const float* __restrict__ conv_w,
                          const float* __restrict__ conv_b, const float* __restrict__ dt_bias,
                          float* __restrict__ xbc, float* __restrict__ dtb) {
    __shared__ float sxr[11][CONVD];
    int blk = blockIdx.x;
    int b = blk >> 11;                 // NTOK/8 = 2048 per batch
    int t0 = (blk & 2047) * 8;
    int tid = threadIdx.x;
#pragma unroll
    for (int r = 0; r < 11; r++) {
        int ts = t0 + r - 3;
        const float* src = zx + ((size_t)(b * NTOK + ts)) * DIN + DINNER;
        for (int c = tid; c < CONVD; c += 256)
            sxr[r][c] = (ts >= 0) ? src[c] : 0.f;
    }
    __syncthreads();
    for (int c = tid; c < CONVD; c += 256) {
        float w0 = conv_w[c * 4], w1 = conv_w[c * 4 + 1];
        float w2 = conv_w[c * 4 + 2], w3 = conv_w[c * 4 + 3];
        float cb = conv_b[c];
#pragma unroll
        for (int q = 0; q < 8; q++) {
            float acc = cb + sxr[q][c] * w0 + sxr[q + 1][c] * w1
                      + sxr[q + 2][c] * w2 + sxr[q + 3][c] * w3;
            xbc[((size_t)(b * NTOK + t0 + q)) * CONVD + c] = siluf(acc);
        }
    }
    if (tid < 64) {
        int q = tid >> 3, h = tid & 7;
        float xv = zx[((size_t)(b * NTOK + t0 + q)) * DIN + DINNER + CONVD + h] + dt_bias[h];
        float dt = (xv > 20.f) ? xv : log1pf(expf(xv));
        dtb[(((size_t)(b * NH + h)) << 14) + t0 + q] = dt;
    }
}

__global__ void k_cumsum(const float* __restrict__ dtb, const float* __restrict__ A_log,
                         float* __restrict__ cum, float* __restrict__ csum) {
    int bh = blockIdx.x;
    int h = bh & 7;
    float A = -expf(A_log[h]);
    int c = threadIdx.x;
    size_t base = ((size_t)bh << 14) + (size_t)c * 64;
    float run = 0.f;
    for (int t = 0; t < 64; t++) {
        run += dtb[base + t] * A;
        cum[base + t] = run;
    }
    csum[bh * NCHUNK + c] = run;
}

__global__ void k_chunkstate(const float* __restrict__ xbc, const float* __restrict__ cum,
                             const float* __restrict__ dtb, float* __restrict__ sloc) {
    int idx = blockIdx.x;
    int c = idx & 255, bh = idx >> 8;
    int b = bh >> 3, h = bh & 7;
    __shared__ float sB[64 * 32];
    __shared__ float sx[64 * 80];
    __shared__ float coef[64];
    int tid = threadIdx.x;
    size_t tbase = (size_t)b * NTOK + (size_t)c * 64;
    for (int e = tid; e < 64 * 32; e += 256) {
        int t = e >> 5, n = e & 31;
        sB[e] = xbc[(tbase + t) * CONVD + DINNER + n];
    }
    for (int e = tid; e < 64 * 80; e += 256) {
        int t = e / 80, p = e % 80;
        sx[e] = xbc[(tbase + t) * CONVD + h * HP + p];
    }
    if (tid < 64) {
        size_t cb = ((size_t)bh << 14) + (size_t)c * 64;
        float cl = cum[cb + 63];
        coef[tid] = expf(cl - cum[cb + tid]) * dtb[cb + tid];
    }
    __syncthreads();
    int n = tid >> 3, p0 = (tid & 7) * 10;
    float2 a2[5] = {};
    for (int t = 0; t < 64; t++) {
        float bc = coef[t] * sB[t * 32 + n];
        const float2* xr = (const float2*)&sx[t * 80 + p0];
#pragma unroll
        for (int j = 0; j < 5; j++) {
            float2 xv = xr[j];
            a2[j].x += bc * xv.x;
            a2[j].y += bc * xv.y;
        }
    }
    float2* so = (float2*)&sloc[((size_t)bh * NCHUNK + c) * 2560 + n * 80 + p0];
#pragma unroll
    for (int j = 0; j < 5; j++) so[j] = a2[j];
}

// inter-chunk scan: smem decay cache + unroll-4 prefetch
__global__ void k_scan(const float* __restrict__ sloc, const float* __restrict__ csum,
                       float* __restrict__ sbeg) {
    __shared__ float sdec[256];
    int bh = blockIdx.x;
    int e = blockIdx.y * 256 + threadIdx.x;
    sdec[threadIdx.x] = expf(csum[bh * NCHUNK + threadIdx.x]);
    __syncthreads();
    float S = 0.f;
    size_t base = (size_t)bh * NCHUNK * 2560 + e;
    for (int c = 0; c < NCHUNK; c += 4) {
        size_t b0 = base + (size_t)c * 2560;
        float x0 = sloc[b0];
        float x1 = sloc[b0 + 2560];
        float x2 = sloc[b0 + 5120];
        float x3 = sloc[b0 + 7680];
        sbeg[b0] = S;        S = S * sdec[c]     + x0;
        sbeg[b0 + 2560] = S; S = S * sdec[c + 1] + x1;
        sbeg[b0 + 5120] = S; S = S * sdec[c + 2] + x2;
        sbeg[b0 + 7680] = S; S = S * sdec[c + 3] + x3;
    }
}

__global__ void k_chunkout(const float* __restrict__ xbc, const float* __restrict__ cum,
                           const float* __restrict__ dtb, const float* __restrict__ sbeg,
                           const float* __restrict__ Dp, float* __restrict__ y) {
    int idx = blockIdx.x;
    int c = idx & 255, bh = idx >> 8;
    int b = bh >> 3, h = bh & 7;
    __shared__ float sM[64 * 65];
    __shared__ float sC[64 * 33];
    __shared__ float sR[5120];
    __shared__ float sCum[64];
    __shared__ float sDt[64];
    int tid = threadIdx.x;
    size_t tbase = (size_t)b * NTOK + (size_t)c * 64;
    size_t cb = ((size_t)bh << 14) + (size_t)c * 64;
    size_t sb_base = ((size_t)bh * NCHUNK + c) * 2560;
    for (int e = tid; e < 2048; e += 256) {
        int t = e >> 5, n = e & 31;
        sC[t * 33 + n] = xbc[(tbase + t) * CONVD + DINNER + DSTATE + n];
    }
    for (int e = tid; e < 2560; e += 256) sR[e] = sbeg[sb_base + e];
    if (tid < 64) { sCum[tid] = cum[cb + tid]; sDt[tid] = dtb[cb + tid]; }
    __syncthreads();
    int t = tid >> 2, p0 = (tid & 3) * 20;
    float4 a4[5] = {};
    for (int n = 0; n < 32; n++) {
        float cv = sC[t * 33 + n];
        const float4* rr = (const float4*)&sR[n * 80 + p0];
#pragma unroll
        for (int j = 0; j < 5; j++) {
            float4 rv = rr[j];
            a4[j].x += cv * rv.x; a4[j].y += cv * rv.y;
            a4[j].z += cv * rv.z; a4[j].w += cv * rv.w;
        }
    }
    float et = expf(sCum[t]);
#pragma unroll
    for (int j = 0; j < 5; j++) {
        a4[j].x *= et; a4[j].y *= et; a4[j].z *= et; a4[j].w *= et;
    }
    __syncthreads();
    for (int e = tid; e < 2048; e += 256) {
        int s = e >> 5, n = e & 31;
        sR[s * 33 + n] = xbc[(tbase + s) * CONVD + DINNER + n];
    }
    __syncthreads();
    for (int e = tid; e < 4096; e += 256) {
        int tt = e >> 6, s = e & 63;
        float m = 0.f;
        if (s <= tt) {
            float d = 0.f;
#pragma unroll 8
            for (int n = 0; n < 32; n++) d += sC[tt * 33 + n] * sR[s * 33 + n];
            m = d * expf(sCum[tt] - sCum[s]) * sDt[s];
        }
        sM[tt * 65 + s] = m;
    }
    __syncthreads();
    for (int e = tid; e < 5120; e += 256) {
        int s = e / 80, p = e % 80;
        sR[e] = xbc[(tbase + s) * CONVD + h * HP + p];
    }
    __syncthreads();
    for (int s = 0; s < 64; s++) {
        float m = sM[t * 65 + s];
        const float4* rr = (const float4*)&sR[s * 80 + p0];
#pragma unroll
        for (int j = 0; j < 5; j++) {
            float4 rv = rr[j];
            a4[j].x += m * rv.x; a4[j].y += m * rv.y;
            a4[j].z += m * rv.z; a4[j].w += m * rv.w;
        }
    }
    float dph = Dp[h];
    const float4* xr = (const float4*)&sR[t * 80 + p0];
    float4* yo = (float4*)&y[(tbase + t) * DINNER + h * HP + p0];
#pragma unroll
    for (int j = 0; j < 5; j++) {
        float4 xv = xr[j];
        float4 o;
        o.x = a4[j].x + dph * xv.x; o.y = a4[j].y + dph * xv.y;
        o.z = a4[j].z + dph * xv.z; o.w = a4[j].w + dph * xv.w;
        yo[j] = o;
    }
}

__global__ void k_gaterms(const float* __restrict__ y, const float* __restrict__ zx,
                          const float* __restrict__ rms_w,
                          bf16* __restrict__ hi, bf16* __restrict__ lo) {
    size_t row = blockIdx.x;
    int e = threadIdx.x;
    float v = y[row * DINNER + e];
    float z = zx[row * DIN + e];
    v = v * siluf(z);
    float ms = blockReduceSum(v * v) / DINNER;
    float r = v * rsqrtf(ms + 1e-5f) * rms_w[e];
    bf16 h, l;
    split_bf16(r, h, l);
    hi[row * DINNER + e] = h;
    lo[row * DINNER + e] = l;
}

__global__ void k_kpe(const float* __restrict__ gauss, float* __restrict__ kpe) {
    int t = blockIdx.x;
    int j = threadIdx.x;
    int d = t >> 10, hh = (t >> 5) & 31, w = t & 31;
    float g0 = 2.f * ((d + 0.5f) / 16.f) - 1.f;
    float g1 = 2.f * ((hh + 0.5f) / 32.f) - 1.f;
    float g2 = 2.f * ((w + 0.5f) / 32.f) - 1.f;
    float ang = 6.283185307179586f * (g0 * gauss[j] + g1 * gauss[160 + j] + g2 * gauss[320 + j]);
    kpe[(size_t)t * CDIM + j] = sinf(ang);
    kpe[(size_t)t * CDIM + 160 + j] = cosf(ang);
}

__global__ void k_pointemb(const float* __restrict__ coords, const int* __restrict__ labels,
                           const float* __restrict__ gauss, const float* __restrict__ ptab,
                           float* __restrict__ q, float* __restrict__ qpe) {
    int r = blockIdx.x;
    int j = threadIdx.x;
    float c0 = coords[r * 3 + 0] * (2.f / 128.f) - 1.f;
    float c1 = coords[r * 3 + 1] * (2.f / 256.f) - 1.f;
    float c2 = coords[r * 3 + 2] * (2.f / 256.f) - 1.f;
    float ang = 6.283185307179586f * (c0 * gauss[j] + c1 * gauss[160 + j] + c2 * gauss[320 + j]);
    int lab = labels[r];
    float s = sinf(ang) + ptab[lab * CDIM + j];
    float cc = cosf(ang) + ptab[lab * CDIM + 160 + j];
    q[r * CDIM + j] = s;      q[r * CDIM + 160 + j] = cc;
    qpe[r * CDIM + j] = s;    qpe[r * CDIM + 160 + j] = cc;
}

__global__ void k_selfattn(const float* __restrict__ q, const float* __restrict__ k,
                           const float* __restrict__ v, float* __restrict__ o) {
    int b = blockIdx.x >> 2, h = blockIdx.x & 3;
    __shared__ float sc[6][6];
    int tid = threadIdx.x;
    if (tid < 36) {
        int qi = tid / 6, ki = tid % 6;
        float s = 0.f;
        for (int d = 0; d < 80; d++)
            s += q[(b * 6 + qi) * CDIM + h * 80 + d] * k[(b * 6 + ki) * CDIM + h * 80 + d];
        sc[qi][ki] = s * 0.11180339887498948f;
    }
    __syncthreads();
    if (tid < 6) {
        float mx = -1e30f;
        for (int j = 0; j < 6; j++) mx = fmaxf(mx, sc[tid][j]);
        float sum = 0.f;
        for (int j = 0; j < 6; j++) { float e = expf(sc[tid][j] - mx); sc[tid][j] = e; sum += e; }
        float inv = 1.f / sum;
        for (int j = 0; j < 6; j++) sc[tid][j] *= inv;
    }
    __syncthreads();
    for (int e = tid; e < 480; e += 128) {
        int qi = e / 80, d = e % 80;
        float a = 0.f;
        for (int j = 0; j < 6; j++) a += sc[qi][j] * v[(b * 6 + j) * CDIM + h * 80 + d];
        o[(b * 6 + qi) * CDIM + h * 80 + d] = a;
    }
}

__global__ void k_xscore6(const float* __restrict__ q, const float* __restrict__ kimg,
                          float* __restrict__ att, int kstride) {
    int bh = blockIdx.x;
    int b = bh >> 2, h = bh & 3;
    __shared__ float sq[6][40];
    int tid = threadIdx.x;
    if (tid < 240) sq[tid / 40][tid % 40] = q[(b * 6 + tid / 40) * INNERD + h * 40 + tid % 40];
    __syncthreads();
    int key = blockIdx.y * 256 + tid;
    const float* kr = kimg + ((size_t)b * NTOK + key) * kstride + h * 40;
    float kv[40];
#pragma unroll
    for (int d = 0; d < 40; d++) kv[d] = kr[d];
    int r0 = b * 24 + h * 6;
#pragma unroll
    for (int qi = 0; qi < 6; qi++) {
        float s = 0.f;
#pragma unroll
        for (int d = 0; d < 40; d++) s += sq[qi][d] * kv[d];
        att[(size_t)(r0 + qi) * NTOK + key] = s * 0.15811388300841897f;
    }
}

__global__ void k_xsoftmax(float* __restrict__ att) {
    int r = blockIdx.x, tid = threadIdx.x;
    float* row = att + (size_t)r * NTOK;
    float mx = -1e30f;
    for (int i = tid; i < NTOK; i += 256) mx = fmaxf(mx, row[i]);
    mx = blockReduceMax(mx);
    float s = 0.f;
    for (int i = tid; i < NTOK; i += 256) s += expf(row[i] - mx);
    s = blockReduceSum(s);
    float inv = 1.f / s;
    for (int i = tid; i < NTOK; i += 256) row[i] = expf(row[i] - mx) * inv;
}

__global__ void k_xout6(const float* __restrict__ att, const float* __restrict__ v,
                        float* __restrict__ part) {
    int bh = blockIdx.x, seg = blockIdx.y;
    int b = bh >> 2, h = bh & 3;
    int r0 = b * 24 + h * 6;
    __shared__ float svv[64 * 40];
    __shared__ float sa[6 * 64];
    int tid = threadIdx.x;
    int qi = tid / 40, d = tid % 40;
    float acc = 0.f;
    int key0 = seg * 2048;
    for (int c = 0; c < 32; c++) {
        int kc = key0 + c * 64;
        for (int e = tid; e < 2560; e += 240) {
            int k = e / 40, dd = e % 40;
            svv[e] = v[((size_t)b * NTOK + kc + k) * INNERD + h * 40 + dd];
        }
        for (int e = tid; e < 384; e += 240)
            sa[e] = att[(size_t)(r0 + e / 64) * NTOK + kc + (e & 63)];
        __syncthreads();
#pragma unroll 8
        for (int k = 0; k < 64; k++) acc += sa[qi * 64 + k] * svv[k * 40 + d];
        __syncthreads();
    }
    part[((bh * 8 + seg) * 6 + qi) * 40 + d] = acc;
}

__global__ void k_xout_c6(const float* __restrict__ part, float* __restrict__ o) {
    int bh = blockIdx.x;
    int b = bh >> 2, h = bh & 3;
    int tid = threadIdx.x;
    int qi = tid / 40, d = tid % 40;
    float s = 0.f;
#pragma unroll
    for (int g = 0; g < 8; g++) s += part[((bh * 8 + g) * 6 + qi) * 40 + d];
    o[(b * 6 + qi) * INNERD + h * 40 + d] = s;
}

__global__ void k_i2t(const float* __restrict__ qimg, const float* __restrict__ ks,
                      const float* __restrict__ vs,
                      bf16* __restrict__ ohi, bf16* __restrict__ olo) {
    __shared__ float sk[960], sv[960];
    int b = blockIdx.y;
    int tid = threadIdx.x;
    for (int e = tid; e < 960; e += 128) { sk[e] = ks[b * 960 + e]; sv[e] = vs[b * 960 + e]; }
    __syncthreads();
    int tok = blockIdx.x * 32 + (tid >> 2);
    int h = tid & 3;
    const float* qrow = qimg + ((size_t)b * NTOK + tok) * 320 + 160 + h * 40;
    float qv[40];
#pragma unroll
    for (int d = 0; d < 40; d++) qv[d] = qrow[d];
    float sc[6];
    float mx = -1e30f;
#pragma unroll
    for (int j = 0; j < 6; j++) {
        float s = 0.f;
#pragma unroll
        for (int d = 0; d < 40; d++) s += qv[d] * sk[j * INNERD + h * 40 + d];
        sc[j] = s * 0.15811388300841897f;
        mx = fmaxf(mx, sc[j]);
    }
    float sum = 0.f;
#pragma unroll
    for (int j = 0; j < 6; j++) { sc[j] = expf(sc[j] - mx); sum += sc[j]; }
    float inv = 1.f / sum;
    size_t rowo = ((size_t)b * NTOK + tok) * 192;
#pragma unroll
    for (int d = 0; d < 40; d++) {
        float a = 0.f;
#pragma unroll
        for (int j = 0; j < 6; j++) a += sc[j] * sv[j * INNERD + h * 40 + d];
        a *= inv;
        bf16 hh, ll;
        split_bf16(a, hh, ll);
        ohi[rowo + h * 40 + d] = hh;
        olo[rowo + h * 40 + d] = ll;
    }
    if (h == 0) {
        bf16 z = __float2bfloat16(0.f);
#pragma unroll
        for (int d = 160; d < 192; d++) { ohi[rowo + d] = z; olo[rowo + d] = z; }
    }
}

extern "C" void kernel_launch(void* const* d_in, const int* in_sizes, int n_in,
                              void* d_out, int out_size) {
    const float* x        = (const float*)d_in[0];
    const float* coords   = (const float*)d_in[1];
    const int*   labels   = (const int*)  d_in[2];
    const float* ln_w     = (const float*)d_in[3];
    const float* ln_b     = (const float*)d_in[4];
    const float* in_w     = (const float*)d_in[5];
    const float* conv_w   = (const float*)d_in[6];
    const float* conv_b   = (const float*)d_in[7];
    const float* dt_bias  = (const float*)d_in[8];
    const float* A_log    = (const float*)d_in[9];
    const float* Dp       = (const float*)d_in[10];
    const float* rms_w    = (const float*)d_in[11];
    const float* out_w    = (const float*)d_in[12];
    const float* pe_gauss = (const float*)d_in[13];
    const float* point_tab= (const float*)d_in[14];
    const float* sa_w     = (const float*)d_in[15];
    const float* sa_b     = (const float*)d_in[16];
    const float* t2i_w    = (const float*)d_in[17];
    const float* t2i_b    = (const float*)d_in[18];
    const float* t2i_ow   = (const float*)d_in[19];
    const float* t2i_ob   = (const float*)d_in[20];
    const float* i2t_w    = (const float*)d_in[21];
    const float* i2t_b    = (const float*)d_in[22];
    const float* i2t_ow   = (const float*)d_in[23];
    const float* i2t_ob   = (const float*)d_in[24];
    const float* norms_w  = (const float*)d_in[25];
    const float* norms_b  = (const float*)d_in[26];
    const float* mlp_w1   = (const float*)d_in[27];
    const float* mlp_b1   = (const float*)d_in[28];
    const float* mlp_w2   = (const float*)d_in[29];
    const float* mlp_b2   = (const float*)d_in[30];
    float* out = (float*)d_out;

    const int SMEM_DYN = 2 * 4 * 128 * 40 * 2;  // 81920
    cudaFuncSetAttribute(k_mma, cudaFuncAttributeMaxDynamicSharedMemorySize, SMEM_DYN);
    cudaFuncSetAttribute(k_tiny12, cudaFuncAttributeMaxDynamicSharedMemorySize, 65792);
    const int TSM_K320 = 12 * 320 * 4 + 64 * 65 * 4;   // 32000
    const int TSM_K1024 = 12 * 1024 * 4 + 64 * 65 * 4; // 65792

    float* ar = nullptr;
    cudaGetSymbolAddress((void**)&ar, g_arena);

    float* zx     = ar + OFF_ZX;
    float* xbc    = ar + OFF_XBC;
    float* dtb    = ar + OFF_DTB;
    float* cum    = ar + OFF_CUM;
    float* csum   = ar + OFF_CSUM;
    float* sloc   = ar + OFF_SLOC;
    float* sbeg   = ar + OFF_SBEG;
    float* ybuf   = ar + OFF_Y;
    float* keys   = ar + OFF_KEYS;
    float* kpe    = ar + OFF_KPE;
    float* tkiq   = ar + OFF_TKIQ;
    float* tv     = ar + OFF_TV;
    float* att    = ar + OFF_ATT;
    float* queries= ar + OFF_Q;
    float* qpe    = ar + OFF_QPE;
    float* sq     = ar + OFF_SQ;
    float* sk     = ar + OFF_SK;
    float* sv     = ar + OFF_SV;
    float* so     = ar + OFF_SO;
    float* qs160  = ar + OFF_QS160;
    float* ks160  = ar + OFF_KS160;
    float* vs160  = ar + OFF_VS160;
    float* tatt   = ar + OFF_TATT;
    float* mlph   = ar + OFF_MLPH;
    float* xpart  = ar + OFF_XPART;
    float* bkq    = ar + OFF_BKQ;

    bf16* xnH  = (bf16*)(ar + OFF_XNH);
    bf16* xnL  = (bf16*)(ar + OFF_XNL);
    bf16* yH   = (bf16*)(ar + OFF_YH);
    bf16* yL   = (bf16*)(ar + OFF_YL);
    bf16* kH   = (bf16*)(ar + OFF_KH);
    bf16* kL   = (bf16*)(ar + OFF_KL);
    bf16* kpH  = (bf16*)(ar + OFF_KPH);
    bf16* kpL  = (bf16*)(ar + OFF_KPL);
    bf16* iaH  = (bf16*)(ar + OFF_IAH);
    bf16* iaL  = (bf16*)(ar + OFF_IAL);
    bf16* inwH = (bf16*)(ar + OFF_INWH);
    bf16* inwL = (bf16*)(ar + OFF_INWL);
    bf16* outwH= (bf16*)(ar + OFF_OUTWH);
    bf16* outwL= (bf16*)(ar + OFF_OUTWL);
    bf16* t2iv = (bf16*)(ar + OFF_T2IV);
    bf16* i2tow= (bf16*)(ar + OFF_I2TOW);
    bf16* wkq  = (bf16*)(ar + OFF_WKQ);

    const int MROWS = NBATCH * NTOK;

    // launch #4 = k_mma (profiled)
    k_tln<<<dim3(NTOK / 32, NBATCH), 256>>>(x, ln_w, ln_b, xnH, xnL);
    k_wsplit<<<1760, 256>>>(in_w, inwH, inwL, DIN, CDIM, 1408, 320);
    k_wsplit<<<960, 256>>>(out_w, outwH, outwL, CDIM, DINNER, 384, 640);
    k_mma<<<dim3(11, 256), 256, SMEM_DYN>>>(xnH, xnL, inwH, inwL, nullptr, nullptr,
                                            zx, nullptr, nullptr, nullptr, nullptr, nullptr,
                                            DIN, 320, 10);
    k_convdt8<<<MROWS / 8, 256>>>(zx, conv_w, conv_b, dt_bias, xbc, dtb);

    for (int i = 0; i < 2; i++) {
        k_wsplit_cat<<<480, 256>>>(t2i_w + (size_t)(i * 3 + 1) * INNERD * CDIM,
                                   i2t_w + (size_t)(i * 3 + 0) * INNERD * CDIM,
                                   wkq + i * 245760, wkq + i * 245760 + 122880);
        k_biascat<<<1, 384>>>(t2i_b + (i * 3 + 1) * INNERD, i2t_b + (i * 3 + 0) * INNERD,
                              bkq + i * 384);
        k_wsplit<<<320, 256>>>(t2i_w + (size_t)(i * 3 + 2) * INNERD * CDIM,
                               t2iv + i * 163840, t2iv + i * 163840 + 81920, INNERD, CDIM, 256, 320);
        k_wsplit<<<288, 256>>>(i2t_ow + (size_t)i * CDIM * INNERD,
                               i2tow + i * 147456, i2tow + i * 147456 + 73728, CDIM, INNERD, 384, 192);
    }
    k_kpe<<<NTOK, 160>>>(pe_gauss, kpe);
    k_pointemb<<<12, 160>>>(coords, labels, pe_gauss, point_tab, queries, qpe);

    k_cumsum<<<NBATCH * NH, NCHUNK>>>(dtb, A_log, cum, csum);
    k_chunkstate<<<NBATCH * NH * NCHUNK, 256>>>(xbc, cum, dtb, sloc);
    k_scan<<<dim3(NBATCH * NH, 10), 256>>>(sloc, csum, sbeg);
    k_chunkout<<<NBATCH * NH * NCHUNK, 256>>>(xbc, cum, dtb, sbeg, Dp, ybuf);
    k_gaterms<<<MROWS, DINNER>>>(ybuf, zx, rms_w, yH, yL);
    k_mma<<<dim3(3, 256), 256, SMEM_DYN>>>(yH, yL, outwH, outwL, nullptr, nullptr,
                                           keys, kH, kL, kpe, kpH, kpL, CDIM, 640, 20);

    for (int i = 0; i < 2; i++) {
        const float* swq = sa_w + (size_t)(i * 4 + 0) * CDIM * CDIM;
        const float* swk = sa_w + (size_t)(i * 4 + 1) * CDIM * CDIM;
        const float* swv = sa_w + (size_t)(i * 4 + 2) * CDIM * CDIM;
        const float* swo = sa_w + (size_t)(i * 4 + 3) * CDIM * CDIM;
        const float* sbq = sa_b + (i * 4 + 0) * CDIM;
        const float* sbk = sa_b + (i * 4 + 1) * CDIM;
        const float* sbv = sa_b + (i * 4 + 2) * CDIM;
        const float* sbo = sa_b + (i * 4 + 3) * CDIM;

        const float* pe_q = (i == 0) ? nullptr : qpe;
        k_tiny12<<<5, 256, TSM_K320>>>(queries, pe_q, swq, sbq, nullptr, sq, CDIM, CDIM, 0);
        k_tiny12<<<5, 256, TSM_K320>>>(queries, pe_q, swk, sbk, nullptr, sk, CDIM, CDIM, 0);
        k_tiny12<<<5, 256, TSM_K320>>>(queries, nullptr, swv, sbv, nullptr, sv, CDIM, CDIM, 0);
        k_selfattn<<<8, 128>>>(sq, sk, sv, so);
        k_tiny12<<<5, 256, TSM_K320>>>(so, nullptr, swo, sbo, (i == 0) ? nullptr : queries,
                                       queries, CDIM, CDIM, 0);
        k_ln<<<12, CDIM>>>(queries, queries, norms_w + (i * 4 + 0) * CDIM,
                           norms_b + (i * 4 + 0) * CDIM, nullptr, nullptr,
                           nullptr, nullptr, nullptr);

        k_tiny12<<<3, 256, TSM_K320>>>(queries, qpe, t2i_w + (size_t)(i * 3 + 0) * INNERD * CDIM,
                                       t2i_b + (i * 3 + 0) * INNERD, nullptr, qs160, INNERD, CDIM, 0);
        k_mma<<<dim3(3, 256), 256, SMEM_DYN>>>(kpH, kpL, wkq + i * 245760, wkq + i * 245760 + 122880,
                                               bkq + i * 384, nullptr,
                                               tkiq, nullptr, nullptr, nullptr, nullptr, nullptr,
                                               320, 320, 10);
        k_mma<<<dim3(2, 256), 256, SMEM_DYN>>>(kH, kL, t2iv + i * 163840, t2iv + i * 163840 + 81920,
                                               t2i_b + (i * 3 + 2) * INNERD, nullptr,
                                               tv, nullptr, nullptr, nullptr, nullptr, nullptr,
                                               INNERD, 320, 10);
        k_xscore6<<<dim3(8, 64), 256>>>(qs160, tkiq, att, 320);
        k_xsoftmax<<<48, 256>>>(att);
        k_xout6<<<dim3(8, 8), 240>>>(att, tv, xpart);
        k_xout_c6<<<8, 240>>>(xpart, tatt);
        k_tiny12<<<5, 256, TSM_K320>>>(tatt, nullptr, t2i_ow + (size_t)i * CDIM * INNERD,
                                       t2i_ob + i * CDIM, queries, queries, CDIM, INNERD, 0);
        k_ln<<<12, CDIM>>>(queries, queries, norms_w + (i * 4 + 1) * CDIM,
                           norms_b + (i * 4 + 1) * CDIM, nullptr, nullptr,
                           nullptr, nullptr, nullptr);

        k_tiny12<<<16, 256, TSM_K320>>>(queries, nullptr, mlp_w1 + (size_t)i * MLPD * CDIM,
                                        mlp_b1 + i * MLPD, nullptr, mlph, MLPD, CDIM, 1);
        k_tiny12<<<5, 256, TSM_K1024>>>(mlph, nullptr, mlp_w2 + (size_t)i * CDIM * MLPD,
                                        mlp_b2 + i * CDIM, queries, queries, CDIM, MLPD, 0);
        k_ln<<<12, CDIM>>>(queries, queries, norms_w + (i * 4 + 2) * CDIM,
                           norms_b + (i * 4 + 2) * CDIM, nullptr, nullptr,
                           nullptr, nullptr, nullptr);

        k_tiny12<<<3, 256, TSM_K320>>>(queries, qpe, i2t_w + (size_t)(i * 3 + 1) * INNERD * CDIM,
                                       i2t_b + (i * 3 + 1) * INNERD, nullptr, ks160, INNERD, CDIM, 0);
        k_tiny12<<<3, 256, TSM_K320>>>(queries, nullptr, i2t_w + (size_t)(i * 3 + 2) * INNERD * CDIM,
                                       i2t_b + (i * 3 + 2) * INNERD, nullptr, vs160, INNERD, CDIM, 0);
        k_i2t<<<dim3(NTOK / 32, NBATCH), 128>>>(tkiq, ks160, vs160, iaH, iaL);
        k_mma<<<dim3(3, 256), 256, SMEM_DYN>>>(iaH, iaL, i2tow + i * 147456, i2tow + i * 147456 + 73728,
                                               i2t_ob + i * CDIM, keys,
                                               keys, nullptr, nullptr, nullptr, nullptr, nullptr,
                                               CDIM, 192, 6);
        if (i == 0) {
            k_ln<<<MROWS, CDIM>>>(keys, keys, norms_w + (i * 4 + 3) * CDIM,
                                  norms_b + (i * 4 + 3) * CDIM, kH, kL,
                                  kpe, kpH, kpL);
        } else {
            k_ln<<<MROWS, CDIM>>>(keys, keys, norms_w + (i * 4 + 3) * CDIM,
                                  norms_b + (i * 4 + 3) * CDIM, nullptr, nullptr,
                                  nullptr, nullptr, nullptr);
        }
    }

    k_transpose_out<<<dim3(NTOK / 32, CDIM / 32, NBATCH), dim3(32, 8)>>>(keys, out);
}

// round 13
// speedup vs baseline: 1.0605x; 1.0605x over previous
#include <cuda_runtime.h>
#include <cuda_bf16.h>
#include <math.h>
#include <stdint.h>

#define NBATCH 2
#define CDIM 320
#define NTOK 16384
#define DIN 1352
#define DINNER 640
#define CONVD 704
#define DSTATE 32
#define NH 8
#define HP 80
#define NCHUNK 256
#define INNERD 160
#define MLPD 1024

typedef __nv_bfloat16 bf16;

constexpr size_t SZ_XF   = (size_t)NBATCH*NTOK*CDIM;
constexpr size_t SZ_ZX   = (size_t)NBATCH*NTOK*DIN;
constexpr size_t SZ_XBC  = (size_t)NBATCH*NTOK*CONVD;
constexpr size_t SZ_DTB  = (size_t)NBATCH*NH*NTOK;
constexpr size_t SZ_SL   = (size_t)NBATCH*NH*NCHUNK*DSTATE*HP;
constexpr size_t SZ_Y    = (size_t)NBATCH*NTOK*DINNER;
constexpr size_t SZ_KPE  = (size_t)NTOK*CDIM;
constexpr size_t SZ_I160 = (size_t)NBATCH*NTOK*INNERD;
constexpr size_t SZ_ATT  = (size_t)48*NTOK;

constexpr size_t OFF_XF    = 0;
constexpr size_t OFF_ZX    = OFF_XF    + SZ_XF;
constexpr size_t OFF_XBC   = OFF_ZX    + SZ_ZX;
constexpr size_t OFF_DTB   = OFF_XBC   + SZ_XBC;
constexpr size_t OFF_CUM   = OFF_DTB   + SZ_DTB;
constexpr size_t OFF_CSUM  = OFF_CUM   + SZ_DTB;
constexpr size_t OFF_SLOC  = OFF_CSUM  + (size_t)NBATCH*NH*NCHUNK;
constexpr size_t OFF_SBEG  = OFF_SLOC  + SZ_SL;
constexpr size_t OFF_Y     = OFF_SBEG  + SZ_SL;
constexpr size_t OFF_KEYS  = OFF_Y     + SZ_Y;
constexpr size_t OFF_KPE   = OFF_KEYS  + SZ_XF;
constexpr size_t OFF_TKIQ  = OFF_KPE   + SZ_KPE;
constexpr size_t OFF_TV    = OFF_TKIQ  + 2 * SZ_I160;
constexpr size_t OFF_ATT   = OFF_TV    + SZ_I160;
constexpr size_t OFF_Q     = OFF_ATT   + SZ_ATT;
constexpr size_t OFF_QPE   = OFF_Q     + 3840;
constexpr size_t OFF_SQ    = OFF_QPE   + 3840;
constexpr size_t OFF_SK    = OFF_SQ    + 3840;
constexpr size_t OFF_SV    = OFF_SK    + 3840;
constexpr size_t OFF_SO    = OFF_SV    + 3840;
constexpr size_t OFF_QS160 = OFF_SO    + 3840;
constexpr size_t OFF_KS160 = OFF_QS160 + 1920;
constexpr size_t OFF_VS160 = OFF_KS160 + 1920;
constexpr size_t OFF_TATT  = OFF_VS160 + 1920;
constexpr size_t OFF_MLPH  = OFF_TATT  + 1920;
constexpr size_t OFF_XNH   = OFF_MLPH + 12288;
constexpr size_t OFF_XNL   = OFF_XNH + 5242880;
constexpr size_t OFF_YH    = OFF_XNL + 5242880;
constexpr size_t OFF_YL    = OFF_YH  + 10485760;
constexpr size_t OFF_KH    = OFF_YL  + 10485760;
constexpr size_t OFF_KL    = OFF_KH  + 5242880;
constexpr size_t OFF_KPH   = OFF_KL  + 5242880;
constexpr size_t OFF_KPL   = OFF_KPH + 5242880;
constexpr size_t OFF_IAH   = OFF_KPL + 5242880;
constexpr size_t OFF_IAL   = OFF_IAH + 3145728;
constexpr size_t OFF_INWH  = OFF_IAL + 3145728;
constexpr size_t OFF_INWL  = OFF_INWH + 225280;
constexpr size_t OFF_OUTWH = OFF_INWL + 225280;
constexpr size_t OFF_OUTWL = OFF_OUTWH + 122880;
constexpr size_t OFF_T2IV  = OFF_OUTWL + 122880;
constexpr size_t OFF_I2TOW = OFF_T2IV + 163840;
constexpr size_t OFF_XPART = OFF_I2TOW + 147456;
constexpr size_t OFF_WKQ   = OFF_XPART + 16384;
constexpr size_t OFF_BKQ   = OFF_WKQ + 245760;
constexpr size_t ARENA_FLOATS = OFF_BKQ + 768;

__device__ __align__(128) float g_arena[ARENA_FLOATS];

__device__ __forceinline__ uint32_t smem_u32(const void* p) {
    uint32_t a;
    asm("{ .reg .u64 t; cvta.to.shared.u64 t, %1; cvt.u32.u64 %0, t; }" : "=r"(a) : "l"(p));
    return a;
}
__device__ __forceinline__ void ldm_x4(uint32_t* r, uint32_t a) {
    asm volatile("ldmatrix.sync.aligned.m8n8.x4.shared.b16 {%0,%1,%2,%3}, [%4];"
        : "=r"(r[0]), "=r"(r[1]), "=r"(r[2]), "=r"(r[3]) : "r"(a));
}
__device__ __forceinline__ void mma16816(float* c, const uint32_t* a, const uint32_t* b) {
    asm volatile("mma.sync.aligned.m16n8k16.row.col.f32.bf16.bf16.f32 "
        "{%0,%1,%2,%3}, {%4,%5,%6,%7}, {%8,%9}, {%0,%1,%2,%3};"
        : "+f"(c[0]), "+f"(c[1]), "+f"(c[2]), "+f"(c[3])
        : "r"(a[0]), "r"(a[1]), "r"(a[2]), "r"(a[3]), "r"(b[0]), "r"(b[1]));
}
__device__ __forceinline__ void cpasync16(uint32_t dst, const void* src) {
    asm volatile("cp.async.cg.shared.global [%0], [%1], 16;" :: "r"(dst), "l"(src));
}
__device__ __forceinline__ void split_bf16(float v, bf16& h, bf16& l) {
    h = __float2bfloat16(v);
    l = __float2bfloat16(v - __bfloat162float(h));
}

__device__ __forceinline__ float blockReduceSum(float v) {
    __shared__ float sh[33];
    int lane = threadIdx.x & 31, wid = threadIdx.x >> 5;
#pragma unroll
    for (int o = 16; o; o >>= 1) v += __shfl_down_sync(0xffffffffu, v, o);
    if (lane == 0) sh[wid] = v;
    __syncthreads();
    int nw = (blockDim.x + 31) >> 5;
    if (wid == 0) {
        v = (lane < nw) ? sh[lane] : 0.f;
#pragma unroll
        for (int o = 16; o; o >>= 1) v += __shfl_down_sync(0xffffffffu, v, o);
        if (lane == 0) sh[32] = v;
    }
    __syncthreads();
    v = sh[32];
    __syncthreads();
    return v;
}
__device__ __forceinline__ float2 blockReduceSum2(float a, float b) {
    __shared__ float sh[66];
    int lane = threadIdx.x & 31, wid = threadIdx.x >> 5;
#pragma unroll
    for (int o = 16; o; o >>= 1) {
        a += __shfl_down_sync(0xffffffffu, a, o);
        b += __shfl_down_sync(0xffffffffu, b, o);
    }
    if (lane == 0) { sh[wid * 2] = a; sh[wid * 2 + 1] = b; }
    __syncthreads();
    int nw = (blockDim.x + 31) >> 5;
    if (wid == 0) {
        a = (lane < nw) ? sh[lane * 2] : 0.f;
        b = (lane < nw) ? sh[lane * 2 + 1] : 0.f;
#pragma unroll
        for (int o = 16; o; o >>= 1) {
            a += __shfl_down_sync(0xffffffffu, a, o);
            b += __shfl_down_sync(0xffffffffu, b, o);
        }
        if (lane == 0) { sh[64] = a; sh[65] = b; }
    }
    __syncthreads();
    float2 r = make_float2(sh[64], sh[65]);
    __syncthreads();
    return r;
}
__device__ __forceinline__ float blockReduceMax(float v) {
    __shared__ float sh[33];
    int lane = threadIdx.x & 31, wid = threadIdx.x >> 5;
#pragma unroll
    for (int o = 16; o; o >>= 1) v = fmaxf(v, __shfl_down_sync(0xffffffffu, v, o));
    if (lane == 0) sh[wid] = v;
    __syncthreads();
    int nw = (blockDim.x + 31) >> 5;
    if (wid == 0) {
        v = (lane < nw) ? sh[lane] : -1e30f;
#pragma unroll
        for (int o = 16; o; o >>= 1) v = fmaxf(v, __shfl_down_sync(0xffffffffu, v, o));
        if (lane == 0) sh[32] = v;
    }
    __syncthreads();
    v = sh[32];
    __syncthreads();
    return v;
}
__device__ __forceinline__ float siluf(float x) { return x / (1.f + expf(-x)); }

// ---- tensor-core split GEMM (stable since R9) ----
__global__ void __launch_bounds__(256, 2)
k_mma(const bf16* __restrict__ aH, const bf16* __restrict__ aL,
      const bf16* __restrict__ wH, const bf16* __restrict__ wL,
      const float* __restrict__ bias, const float* __restrict__ R,
      float* __restrict__ C, bf16* __restrict__ cH, bf16* __restrict__ cL,
      const float* __restrict__ pe, bf16* __restrict__ peH, bf16* __restrict__ peL,
      int Nact, int Kd, int nkb) {
    extern __shared__ bf16 sm[];
    constexpr int TSZ = 128 * 40;
    const int tid = threadIdx.x;
    const int wid = tid >> 5, lane = tid & 31;
    const int wm = wid & 1, wn = wid >> 1;
    const int m0 = blockIdx.y * 128, n0 = blockIdx.x * 128;

    const bf16* srcs[4] = { aH + (size_t)m0 * Kd, aL + (size_t)m0 * Kd,
                            wH + (size_t)n0 * Kd, wL + (size_t)n0 * Kd };
    const int lrow = tid >> 2, lc8 = (tid & 3) * 8;

    auto prefetch = [&](int kb, int buf) {
#pragma unroll
        for (int q = 0; q < 4; q++) {
            bf16* t = sm + buf * 4 * TSZ + q * TSZ;
#pragma unroll
            for (int l = 0; l < 2; l++) {
                int row = lrow + l * 64;
                cpasync16(smem_u32(t + row * 40 + lc8),
                          srcs[q] + (size_t)row * Kd + kb * 32 + lc8);
            }
        }
        asm volatile("cp.async.commit_group;");
    };

    float acc[4][4][4];
#pragma unroll
    for (int i = 0; i < 4; i++)
#pragma unroll
        for (int j = 0; j < 4; j++)
#pragma unroll
            for (int r = 0; r < 4; r++) acc[i][j][r] = 0.f;

    prefetch(0, 0);
    if (nkb > 1) prefetch(1, 1);

    const int arow = wm * 64 + (((lane >> 3) & 1) << 3) + (lane & 7);
    const int acol = ((lane >> 4) << 3);
    const int brow = wn * 32 + ((lane >> 4) << 3) + (lane & 7);
    const int bcol = (((lane >> 3) & 1) << 3);

    for (int kb = 0; kb < nkb; kb++) {
        if (kb + 1 < nkb) asm volatile("cp.async.wait_group 1;");
        else              asm volatile("cp.async.wait_group 0;");
        __syncthreads();
        const int buf = kb & 1;
        const bf16* tAH = sm + buf * 4 * TSZ;
        const bf16* tAL = tAH + TSZ;
        const bf16* tWH = tAH + 2 * TSZ;
        const bf16* tWL = tAH + 3 * TSZ;
#pragma unroll
        for (int ks = 0; ks < 2; ks++) {
            uint32_t aHf[4][4], aLf[4][4];
#pragma unroll
            for (int mi = 0; mi < 4; mi++) {
                int off = (arow + mi * 16) * 40 + ks * 16 + acol;
                ldm_x4(aHf[mi], smem_u32(tAH + off));
                ldm_x4(aLf[mi], smem_u32(tAL + off));
            }
#pragma unroll
            for (int nfp = 0; nfp < 2; nfp++) {
                uint32_t bHf[4], bLf[4];
                int off = (brow + nfp * 16) * 40 + ks * 16 + bcol;
                ldm_x4(bHf, smem_u32(tWH + off));
                ldm_x4(bLf, smem_u32(tWL + off));
#pragma unroll
                for (int mi = 0; mi < 4; mi++) {
                    mma16816(acc[mi][nfp * 2 + 0], aHf[mi], bHf);
                    mma16816(acc[mi][nfp * 2 + 1], aHf[mi], bHf + 2);
                }
#pragma unroll
                for (int mi = 0; mi < 4; mi++) {
                    mma16816(acc[mi][nfp * 2 + 0], aHf[mi], bLf);
                    mma16816(acc[mi][nfp * 2 + 1], aHf[mi], bLf + 2);
                }
#pragma unroll
                for (int mi = 0; mi < 4; mi++) {
                    mma16816(acc[mi][nfp * 2 + 0], aLf[mi], bHf);
                    mma16816(acc[mi][nfp * 2 + 1], aLf[mi], bHf + 2);
                }
            }
        }
        __syncthreads();
        if (kb + 2 < nkb) prefetch(kb + 2, buf);
    }

    const int qr = lane >> 2, qc = (lane & 3) * 2;
#pragma unroll
    for (int mi = 0; mi < 4; mi++)
#pragma unroll
        for (int nf = 0; nf < 4; nf++) {
            int n = n0 + wn * 32 + nf * 8 + qc;
            if (n >= Nact) continue;
#pragma unroll
            for (int h = 0; h < 2; h++) {
                int m = m0 + wm * 64 + mi * 16 + qr + h * 8;
                float v0 = acc[mi][nf][h * 2 + 0];
                float v1 = acc[mi][nf][h * 2 + 1];
                if (bias) { v0 += bias[n]; v1 += bias[n + 1]; }
                size_t o = (size_t)m * Nact + n;
                if (R) { v0 += R[o]; v1 += R[o + 1]; }
                C[o] = v0; C[o + 1] = v1;
                bf16 hh, ll;
                if (cH) {
                    split_bf16(v0, hh, ll); cH[o] = hh;     cL[o] = ll;
                    split_bf16(v1, hh, ll); cH[o + 1] = hh; cL[o + 1] = ll;
                }
                if (peH) {
                    size_t pi = (size_t)(m & (NTOK - 1)) * Nact + n;
                    split_bf16(v0 + pe[pi], hh, ll);     peH[o] = hh;     peL[o] = ll;
                    split_bf16(v1 + pe[pi + 1], hh, ll); peH[o + 1] = hh; peL[o + 1] = ll;
                }
            }
        }
}

__global__ void k_wsplit(const float* __restrict__ W, bf16* __restrict__ hi,
                         bf16* __restrict__ lo, int N, int K, int Npad, int Kpad) {
    int idx = blockIdx.x * 256 + threadIdx.x;
    if (idx >= Npad * Kpad) return;
    int n = idx / Kpad, k = idx % Kpad;
    float v = (n < N && k < K) ? W[(size_t)n * K + k] : 0.f;
    bf16 h, l;
    split_bf16(v, h, l);
    hi[idx] = h; lo[idx] = l;
}

__global__ void k_wsplit_cat(const float* __restrict__ W1, const float* __restrict__ W2,
                             bf16* __restrict__ hi, bf16* __restrict__ lo) {
    int idx = blockIdx.x * 256 + threadIdx.x;
    if (idx >= 384 * 320) return;
    int n = idx / 320, k = idx % 320;
    float v = 0.f;
    if (n < 160) v = W1[(size_t)n * 320 + k];
    else if (n < 320) v = W2[(size_t)(n - 160) * 320 + k];
    bf16 h, l;
    split_bf16(v, h, l);
    hi[idx] = h; lo[idx] = l;
}

__global__ void k_biascat(const float* __restrict__ b1, const float* __restrict__ b2,
                          float* __restrict__ dst) {
    int n = threadIdx.x;
    dst[n] = (n < 160) ? b1[n] : ((n < 320) ? b2[n - 160] : 0.f);
}

__global__ void k_tln(const float* __restrict__ x, const float* __restrict__ w,
                      const float* __restrict__ b, bf16* __restrict__ hi,
                      bf16* __restrict__ lo) {
    __shared__ float tile[320 * 33];
    __shared__ float mu[32], rs[32];
    int bq = blockIdx.y;
    int t0 = blockIdx.x * 32;
    int tid = threadIdx.x;
    for (int e = tid; e < 320 * 32; e += 256) {
        int c = e >> 5, tok = e & 31;
        tile[c * 33 + tok] = x[((size_t)(bq * CDIM + c)) * NTOK + t0 + tok];
    }
    __syncthreads();
    int wid = tid >> 5, lane = tid & 31;
#pragma unroll
    for (int k = 0; k < 4; k++) {
        int tok = wid * 4 + k;
        float s = 0.f, v = 0.f;
        for (int c = lane; c < 320; c += 32) {
            float t = tile[c * 33 + tok];
            s += t; v += t * t;
        }
#pragma unroll
        for (int o = 16; o; o >>= 1) {
            s += __shfl_down_sync(0xffffffffu, s, o);
            v += __shfl_down_sync(0xffffffffu, v, o);
        }
        if (lane == 0) {
            float m = s / 320.f;
            mu[tok] = m;
            rs[tok] = rsqrtf(v / 320.f - m * m + 1e-5f);
        }
    }
    __syncthreads();
    for (int e = tid; e < 10240; e += 256) {
        int tok = e / 320, c = e % 320;
        float r = (tile[c * 33 + tok] - mu[tok]) * rs[tok] * w[c] + b[c];
        size_t o = ((size_t)(bq * NTOK + t0 + tok)) * 320 + c;
        bf16 h, l;
        split_bf16(r, h, l);
        hi[o] = h; lo[o] = l;
    }
}

__global__ void k_transpose_out(const float* __restrict__ keys, float* __restrict__ out) {
    __shared__ float tile[32][33];
    int b = blockIdx.z;
    int t0 = blockIdx.x * 32, c0 = blockIdx.y * 32;
#pragma unroll
    for (int i = 0; i < 4; i++) {
        int tt = threadIdx.y + i * 8;
        tile[threadIdx.x][tt] = keys[((size_t)(b * NTOK + t0 + tt)) * CDIM + c0 + threadIdx.x];
    }
    __syncthreads();
#pragma unroll
    for (int i = 0; i < 4; i++) {
        int cc = threadIdx.y + i * 8;
        out[((size_t)(b * CDIM + c0 + cc)) * NTOK + t0 + threadIdx.x] = tile[cc][threadIdx.x];
    }
}

__global__ void k_ln(const float* __restrict__ src, float* __restrict__ dst,
                     const float* __restrict__ w, const float* __restrict__ b,
                     bf16* __restrict__ hi, bf16* __restrict__ lo,
                     const float* __restrict__ pe, bf16* __restrict__ peH,
                     bf16* __restrict__ peL) {
    int row = blockIdx.x;
    int D = blockDim.x;
    float v = src[(size_t)row * D + threadIdx.x];
    float2 sv = blockReduceSum2(v, v * v);
    float m = sv.x / D;
    float var = sv.y / D - m * m;
    float r = (v - m) * rsqrtf(var + 1e-5f) * w[threadIdx.x] + b[threadIdx.x];
    size_t o = (size_t)row * D + threadIdx.x;
    if (dst) dst[o] = r;
    bf16 h, l;
    if (hi) { split_bf16(r, h, l); hi[o] = h; lo[o] = l; }
    if (peH) {
        float pv = r + pe[(size_t)(row & (NTOK - 1)) * D + threadIdx.x];
        split_bf16(pv, h, l);
        peH[o] = h; peL[o] = l;
    }
}

// R11-proven tiny GEMM for 12-row query ops
__global__ void k_tiny(const float* __restrict__ A1, const float* __restrict__ A2,
                       const float* __restrict__ W, const float* __restrict__ bias,
                       const float* __restrict__ R, float* __restrict__ C,
                       int N, int K, int act) {
    int r = blockIdx.y;
    int n = blockIdx.x * 64 + threadIdx.x;
    if (n >= N) return;
    const float* a1 = A1 + (size_t)r * K;
    const float* a2 = A2 ? A2 + (size_t)r * K : nullptr;
    const float* w = W + (size_t)n * K;
    float acc = bias ? bias[n] : 0.f;
    if (a2) { for (int k = 0; k < K; k++) acc += (a1[k] + a2[k]) * w[k]; }
    else    { for (int k = 0; k < K; k++) acc += a1[k] * w[k]; }
    if (act == 1) acc = fmaxf(acc, 0.f);
    if (R) acc += R[(size_t)r * N + n];
    C[(size_t)r * N + n] = acc;
}

// 8-token tiled conv + dt
__global__ void k_convdt8(const float* __restrict__ zx, const float* __restrict__ conv_w,
                          const float* __restrict__ conv_b, const float* __restrict__ dt_bias,
                          float* __restrict__ xbc, float* __restrict__ dtb) {
    __shared__ float sxr[11][CONVD];
    int blk = blockIdx.x;
    int b = blk >> 11;
    int t0 = (blk & 2047) * 8;
    int tid = threadIdx.x;
#pragma unroll
    for (int r = 0; r < 11; r++) {
        int ts = t0 + r - 3;
        const float* src = zx + ((size_t)(b * NTOK + ts)) * DIN + DINNER;
        for (int c = tid; c < CONVD; c += 256)
            sxr[r][c] = (ts >= 0) ? src[c] : 0.f;
    }
    __syncthreads();
    for (int c = tid; c < CONVD; c += 256) {
        float w0 = conv_w[c * 4], w1 = conv_w[c * 4 + 1];
        float w2 = conv_w[c * 4 + 2], w3 = conv_w[c * 4 + 3];
        float cb = conv_b[c];
#pragma unroll
        for (int q = 0; q < 8; q++) {
            float acc = cb + sxr[q][c] * w0 + sxr[q + 1][c] * w1
                      + sxr[q + 2][c] * w2 + sxr[q + 3][c] * w3;
            xbc[((size_t)(b * NTOK + t0 + q)) * CONVD + c] = siluf(acc);
        }
    }
    if (tid < 64) {
        int q = tid >> 3, h = tid & 7;
        float xv = zx[((size_t)(b * NTOK + t0 + q)) * DIN + DINNER + CONVD + h] + dt_bias[h];
        float dt = (xv > 20.f) ? xv : log1pf(expf(xv));
        dtb[(((size_t)(b * NH + h)) << 14) + t0 + q] = dt;
    }
}

__global__ void k_cumsum(const float* __restrict__ dtb, const float* __restrict__ A_log,
                         float* __restrict__ cum, float* __restrict__ csum) {
    int bh = blockIdx.x;
    int h = bh & 7;
    float A = -expf(A_log[h]);
    int c = threadIdx.x;
    size_t base = ((size_t)bh << 14) + (size_t)c * 64;
    float run = 0.f;
    for (int t = 0; t < 64; t++) {
        run += dtb[base + t] * A;
        cum[base + t] = run;
    }
    csum[bh * NCHUNK + c] = run;
}

__global__ void k_chunkstate(const float* __restrict__ xbc, const float* __restrict__ cum,
                             const float* __restrict__ dtb, float* __restrict__ sloc) {
    int idx = blockIdx.x;
    int c = idx & 255, bh = idx >> 8;
    int b = bh >> 3, h = bh & 7;
    __shared__ float sB[64 * 32];
    __shared__ float sx[64 * 80];
    __shared__ float coef[64];
    int tid = threadIdx.x;
    size_t tbase = (size_t)b * NTOK + (size_t)c * 64;
    for (int e = tid; e < 64 * 32; e += 256) {
        int t = e >> 5, n = e & 31;
        sB[e] = xbc[(tbase + t) * CONVD + DINNER + n];
    }
    for (int e = tid; e < 64 * 80; e += 256) {
        int t = e / 80, p = e % 80;
        sx[e] = xbc[(tbase + t) * CONVD + h * HP + p];
    }
    if (tid < 64) {
        size_t cb = ((size_t)bh << 14) + (size_t)c * 64;
        float cl = cum[cb + 63];
        coef[tid] = expf(cl - cum[cb + tid]) * dtb[cb + tid];
    }
    __syncthreads();
    int n = tid >> 3, p0 = (tid & 7) * 10;
    float2 a2[5] = {};
    for (int t = 0; t < 64; t++) {
        float bc = coef[t] * sB[t * 32 + n];
        const float2* xr = (const float2*)&sx[t * 80 + p0];
#pragma unroll
        for (int j = 0; j < 5; j++) {
            float2 xv = xr[j];
            a2[j].x += bc * xv.x;
            a2[j].y += bc * xv.y;
        }
    }
    float2* so = (float2*)&sloc[((size_t)bh * NCHUNK + c) * 2560 + n * 80 + p0];
#pragma unroll
    for (int j = 0; j < 5; j++) so[j] = a2[j];
}

__global__ void k_scan(const float* __restrict__ sloc, const float* __restrict__ csum,
                       float* __restrict__ sbeg) {
    __shared__ float sdec[256];
    int bh = blockIdx.x;
    int e = blockIdx.y * 256 + threadIdx.x;
    sdec[threadIdx.x] = expf(csum[bh * NCHUNK + threadIdx.x]);
    __syncthreads();
    float S = 0.f;
    size_t base = (size_t)bh * NCHUNK * 2560 + e;
    for (int c = 0; c < NCHUNK; c += 4) {
        size_t b0 = base + (size_t)c * 2560;
        float x0 = sloc[b0];
        float x1 = sloc[b0 + 2560];
        float x2 = sloc[b0 + 5120];
        float x3 = sloc[b0 + 7680];
        sbeg[b0] = S;        S = S * sdec[c]     + x0;
        sbeg[b0 + 2560] = S; S = S * sdec[c + 1] + x1;
        sbeg[b0 + 5120] = S; S = S * sdec[c + 2] + x2;
        sbeg[b0 + 7680] = S; S = S * sdec[c + 3] + x3;
    }
}

__global__ void k_chunkout(const float* __restrict__ xbc, const float* __restrict__ cum,
                           const float* __restrict__ dtb, const float* __restrict__ sbeg,
                           const float* __restrict__ Dp, float* __restrict__ y) {
    int idx = blockIdx.x;
    int c = idx & 255, bh = idx >> 8;
    int b = bh >> 3, h = bh & 7;
    __shared__ float sM[64 * 65];
    __shared__ float sC[64 * 33];
    __shared__ float sR[5120];
    __shared__ float sCum[64];
    __shared__ float sDt[64];
    int tid = threadIdx.x;
    size_t tbase = (size_t)b * NTOK + (size_t)c * 64;
    size_t cb = ((size_t)bh << 14) + (size_t)c * 64;
    size_t sb_base = ((size_t)bh * NCHUNK + c) * 2560;
    for (int e = tid; e < 2048; e += 256) {
        int t = e >> 5, n = e & 31;
        sC[t * 33 + n] = xbc[(tbase + t) * CONVD + DINNER + DSTATE + n];
    }
    for (int e = tid; e < 2560; e += 256) sR[e] = sbeg[sb_base + e];
    if (tid < 64) { sCum[tid] = cum[cb + tid]; sDt[tid] = dtb[cb + tid]; }
    __syncthreads();
    int t = tid >> 2, p0 = (tid & 3) * 20;
    float4 a4[5] = {};
    for (int n = 0; n < 32; n++) {
        float cv = sC[t * 33 + n];
        const float4* rr = (const float4*)&sR[n * 80 + p0];
#pragma unroll
        for (int j = 0; j < 5; j++) {
            float4 rv = rr[j];
            a4[j].x += cv * rv.x; a4[j].y += cv * rv.y;
            a4[j].z += cv * rv.z; a4[j].w += cv * rv.w;
        }
    }
    float et = expf(sCum[t]);
#pragma unroll
    for (int j = 0; j < 5; j++) {
        a4[j].x *= et; a4[j].y *= et; a4[j].z *= et; a4[j].w *= et;
    }
    __syncthreads();
    for (int e = tid; e < 2048; e += 256) {
        int s = e >> 5, n = e & 31;
        sR[s * 33 + n] = xbc[(tbase + s) * CONVD + DINNER + n];
    }
    __syncthreads();
    for (int e = tid; e < 4096; e += 256) {
        int tt = e >> 6, s = e & 63;
        float m = 0.f;
        if (s <= tt) {
            float d = 0.f;
#pragma unroll 8
            for (int n = 0; n < 32; n++) d += sC[tt * 33 + n] * sR[s * 33 + n];
            m = d * expf(sCum[tt] - sCum[s]) * sDt[s];
        }
        sM[tt * 65 + s] = m;
    }
    __syncthreads();
    for (int e = tid; e < 5120; e += 256) {
        int s = e / 80, p = e % 80;
        sR[e] = xbc[(tbase + s) * CONVD + h * HP + p];
    }
    __syncthreads();
    for (int s = 0; s < 64; s++) {
        float m = sM[t * 65 + s];
        const float4* rr = (const float4*)&sR[s * 80 + p0];
#pragma unroll
        for (int j = 0; j < 5; j++) {
            float4 rv = rr[j];
            a4[j].x += m * rv.x; a4[j].y += m * rv.y;
            a4[j].z += m * rv.z; a4[j].w += m * rv.w;
        }
    }
    float dph = Dp[h];
    const float4* xr = (const float4*)&sR[t * 80 + p0];
    float4* yo = (float4*)&y[(tbase + t) * DINNER + h * HP + p0];
#pragma unroll
    for (int j = 0; j < 5; j++) {
        float4 xv = xr[j];
        float4 o;
        o.x = a4[j].x + dph * xv.x; o.y = a4[j].y + dph * xv.y;
        o.z = a4[j].z + dph * xv.z; o.w = a4[j].w + dph * xv.w;
        yo[j] = o;
    }
}

__global__ void k_gaterms(const float* __restrict__ y, const float* __restrict__ zx,
                          const float* __restrict__ rms_w,
                          bf16* __restrict__ hi, bf16* __restrict__ lo) {
    size_t row = blockIdx.x;
    int e = threadIdx.x;
    float v = y[row * DINNER + e];
    float z = zx[row * DIN + e];
    v = v * siluf(z);
    float ms = blockReduceSum(v * v) / DINNER;
    float r = v * rsqrtf(ms + 1e-5f) * rms_w[e];
    bf16 h, l;
    split_bf16(r, h, l);
    hi[row * DINNER + e] = h;
    lo[row * DINNER + e] = l;
}

__global__ void k_kpe(const float* __restrict__ gauss, float* __restrict__ kpe) {
    int t = blockIdx.x;
    int j = threadIdx.x;
    int d = t >> 10, hh = (t >> 5) & 31, w = t & 31;
    float g0 = 2.f * ((d + 0.5f) / 16.f) - 1.f;
    float g1 = 2.f * ((hh + 0.5f) / 32.f) - 1.f;
    float g2 = 2.f * ((w + 0.5f) / 32.f) - 1.f;
    float ang = 6.283185307179586f * (g0 * gauss[j] + g1 * gauss[160 + j] + g2 * gauss[320 + j]);
    kpe[(size_t)t * CDIM + j] = sinf(ang);
    kpe[(size_t)t * CDIM + 160 + j] = cosf(ang);
}

__global__ void k_pointemb(const float* __restrict__ coords, const int* __restrict__ labels,
                           const float* __restrict__ gauss, const float* __restrict__ ptab,
                           float* __restrict__ q, float* __restrict__ qpe) {
    int r = blockIdx.x;
    int j = threadIdx.x;
    float c0 = coords[r * 3 + 0] * (2.f / 128.f) - 1.f;
    float c1 = coords[r * 3 + 1] * (2.f / 256.f) - 1.f;
    float c2 = coords[r * 3 + 2] * (2.f / 256.f) - 1.f;
    float ang = 6.283185307179586f * (c0 * gauss[j] + c1 * gauss[160 + j] + c2 * gauss[320 + j]);
    int lab = labels[r];
    float s = sinf(ang) + ptab[lab * CDIM + j];
    float cc = cosf(ang) + ptab[lab * CDIM + 160 + j];
    q[r * CDIM + j] = s;      q[r * CDIM + 160 + j] = cc;
    qpe[r * CDIM + j] = s;    qpe[r * CDIM + 160 + j] = cc;
}

__global__ void k_selfattn(const float* __restrict__ q, const float* __restrict__ k,
                           const float* __restrict__ v, float* __restrict__ o) {
    int b = blockIdx.x >> 2, h = blockIdx.x & 3;
    __shared__ float sc[6][6];
    int tid = threadIdx.x;
    if (tid < 36) {
        int qi = tid / 6, ki = tid % 6;
        float s = 0.f;
        for (int d = 0; d < 80; d++)
            s += q[(b * 6 + qi) * CDIM + h * 80 + d] * k[(b * 6 + ki) * CDIM + h * 80 + d];
        sc[qi][ki] = s * 0.11180339887498948f;
    }
    __syncthreads();
    if (tid < 6) {
        float mx = -1e30f;
        for (int j = 0; j < 6; j++) mx = fmaxf(mx, sc[tid][j]);
        float sum = 0.f;
        for (int j = 0; j < 6; j++) { float e = expf(sc[tid][j] - mx); sc[tid][j] = e; sum += e; }
        float inv = 1.f / sum;
        for (int j = 0; j < 6; j++) sc[tid][j] *= inv;
    }
    __syncthreads();
    for (int e = tid; e < 480; e += 128) {
        int qi = e / 80, d = e % 80;
        float a = 0.f;
        for (int j = 0; j < 6; j++) a += sc[qi][j] * v[(b * 6 + j) * CDIM + h * 80 + d];
        o[(b * 6 + qi) * CDIM + h * 80 + d] = a;
    }
}

__global__ void k_xscore6(const float* __restrict__ q, const float* __restrict__ kimg,
                          float* __restrict__ att, int kstride) {
    int bh = blockIdx.x;
    int b = bh >> 2, h = bh & 3;
    __shared__ float sq[6][40];
    int tid = threadIdx.x;
    if (tid < 240) sq[tid / 40][tid % 40] = q[(b * 6 + tid / 40) * INNERD + h * 40 + tid % 40];
    __syncthreads();
    int key = blockIdx.y * 256 + tid;
    const float* kr = kimg + ((size_t)b * NTOK + key) * kstride + h * 40;
    float kv[40];
#pragma unroll
    for (int d = 0; d < 40; d++) kv[d] = kr[d];
    int r0 = b * 24 + h * 6;
#pragma unroll
    for (int qi = 0; qi < 6; qi++) {
        float s = 0.f;
#pragma unroll
        for (int d = 0; d < 40; d++) s += sq[qi][d] * kv[d];
        att[(size_t)(r0 + qi) * NTOK + key] = s * 0.15811388300841897f;
    }
}

// smem-cached softmax: single DRAM read of the row
__global__ void k_xsoftmax(float* __restrict__ att) {
    extern __shared__ float srow[];
    int r = blockIdx.x, tid = threadIdx.x;
    float* row = att + (size_t)r * NTOK;
    float mx = -1e30f;
    for (int i = tid; i < NTOK; i += 256) {
        float v = row[i];
        srow[i] = v;
        mx = fmaxf(mx, v);
    }
    mx = blockReduceMax(mx);
    float s = 0.f;
    for (int i = tid; i < NTOK; i += 256) {
        float e = expf(srow[i] - mx);
        srow[i] = e;
        s += e;
    }
    s = blockReduceSum(s);
    float inv = 1.f / s;
    for (int i = tid; i < NTOK; i += 256) row[i] = srow[i] * inv;
}

__global__ void k_xout6(const float* __restrict__ att, const float* __restrict__ v,
                        float* __restrict__ part) {
    int bh = blockIdx.x, seg = blockIdx.y;
    int b = bh >> 2, h = bh & 3;
    int r0 = b * 24 + h * 6;
    __shared__ float svv[64 * 40];
    __shared__ float sa[6 * 64];
    int tid = threadIdx.x;
    int qi = tid / 40, d = tid % 40;
    float acc = 0.f;
    int key0 = seg * 2048;
    for (int c = 0; c < 32; c++) {
        int kc = key0 + c * 64;
        for (int e = tid; e < 2560; e += 240) {
            int k = e / 40, dd = e % 40;
            svv[e] = v[((size_t)b * NTOK + kc + k) * INNERD + h * 40 + dd];
        }
        for (int e = tid; e < 384; e += 240)
            sa[e] = att[(size_t)(r0 + e / 64) * NTOK + kc + (e & 63)];
        __syncthreads();
#pragma unroll 8
        for (int k = 0; k < 64; k++) acc += sa[qi * 64 + k] * svv[k * 40 + d];
        __syncthreads();
    }
    part[((bh * 8 + seg) * 6 + qi) * 40 + d] = acc;
}

__global__ void k_xout_c6(const float* __restrict__ part, float* __restrict__ o) {
    int bh = blockIdx.x;
    int b = bh >> 2, h = bh & 3;
    int tid = threadIdx.x;
    int qi = tid / 40, d = tid % 40;
    float s = 0.f;
#pragma unroll
    for (int g = 0; g < 8; g++) s += part[((bh * 8 + g) * 6 + qi) * 40 + d];
    o[(b * 6 + qi) * INNERD + h * 40 + d] = s;
}

__global__ void k_i2t(const float* __restrict__ qimg, const float* __restrict__ ks,
                      const float* __restrict__ vs,
                      bf16* __restrict__ ohi, bf16* __restrict__ olo) {
    __shared__ float sk[960], sv[960];
    int b = blockIdx.y;
    int tid = threadIdx.x;
    for (int e = tid; e < 960; e += 128) { sk[e] = ks[b * 960 + e]; sv[e] = vs[b * 960 + e]; }
    __syncthreads();
    int tok = blockIdx.x * 32 + (tid >> 2);
    int h = tid & 3;
    const float* qrow = qimg + ((size_t)b * NTOK + tok) * 320 + 160 + h * 40;
    float qv[40];
#pragma unroll
    for (int d = 0; d < 40; d++) qv[d] = qrow[d];
    float sc[6];
    float mx = -1e30f;
#pragma unroll
    for (int j = 0; j < 6; j++) {
        float s = 0.f;
#pragma unroll
        for (int d = 0; d < 40; d++) s += qv[d] * sk[j * INNERD + h * 40 + d];
        sc[j] = s * 0.15811388300841897f;
        mx = fmaxf(mx, sc[j]);
    }
    float sum = 0.f;
#pragma unroll
    for (int j = 0; j < 6; j++) { sc[j] = expf(sc[j] - mx); sum += sc[j]; }
    float inv = 1.f / sum;
    size_t rowo = ((size_t)b * NTOK + tok) * 192;
#pragma unroll
    for (int d = 0; d < 40; d++) {
        float a = 0.f;
#pragma unroll
        for (int j = 0; j < 6; j++) a += sc[j] * sv[j * INNERD + h * 40 + d];
        a *= inv;
        bf16 hh, ll;
        split_bf16(a, hh, ll);
        ohi[rowo + h * 40 + d] = hh;
        olo[rowo + h * 40 + d] = ll;
    }
    if (h == 0) {
        bf16 z = __float2bfloat16(0.f);
#pragma unroll
        for (int d = 160; d < 192; d++) { ohi[rowo + d] = z; olo[rowo + d] = z; }
    }
}

extern "C" void kernel_launch(void* const* d_in, const int* in_sizes, int n_in,
                              void* d_out, int out_size) {
    const float* x        = (const float*)d_in[0];
    const float* coords   = (const float*)d_in[1];
    const int*   labels   = (const int*)  d_in[2];
    const float* ln_w     = (const float*)d_in[3];
    const float* ln_b     = (const float*)d_in[4];
    const float* in_w     = (const float*)d_in[5];
    const float* conv_w   = (const float*)d_in[6];
    const float* conv_b   = (const float*)d_in[7];
    const float* dt_bias  = (const float*)d_in[8];
    const float* A_log    = (const float*)d_in[9];
    const float* Dp       = (const float*)d_in[10];
    const float* rms_w    = (const float*)d_in[11];
    const float* out_w    = (const float*)d_in[12];
    const float* pe_gauss = (const float*)d_in[13];
    const float* point_tab= (const float*)d_in[14];
    const float* sa_w     = (const float*)d_in[15];
    const float* sa_b     = (const float*)d_in[16];
    const float* t2i_w    = (const float*)d_in[17];
    const float* t2i_b    = (const float*)d_in[18];
    const float* t2i_ow   = (const float*)d_in[19];
    const float* t2i_ob   = (const float*)d_in[20];
    const float* i2t_w    = (const float*)d_in[21];
    const float* i2t_b    = (const float*)d_in[22];
    const float* i2t_ow   = (const float*)d_in[23];
    const float* i2t_ob   = (const float*)d_in[24];
    const float* norms_w  = (const float*)d_in[25];
    const float* norms_b  = (const float*)d_in[26];
    const float* mlp_w1   = (const float*)d_in[27];
    const float* mlp_b1   = (const float*)d_in[28];
    const float* mlp_w2   = (const float*)d_in[29];
    const float* mlp_b2   = (const float*)d_in[30];
    float* out = (float*)d_out;

    const int SMEM_DYN = 2 * 4 * 128 * 40 * 2;  // 81920
    cudaFuncSetAttribute(k_mma, cudaFuncAttributeMaxDynamicSharedMemorySize, SMEM_DYN);
    const int SMEM_SOFT = NTOK * 4;  // 65536
    cudaFuncSetAttribute(k_xsoftmax, cudaFuncAttributeMaxDynamicSharedMemorySize, SMEM_SOFT);

    float* ar = nullptr;
    cudaGetSymbolAddress((void**)&ar, g_arena);

    float* zx     = ar + OFF_ZX;
    float* xbc    = ar + OFF_XBC;
    float* dtb    = ar + OFF_DTB;
    float* cum    = ar + OFF_CUM;
    float* csum   = ar + OFF_CSUM;
    float* sloc   = ar + OFF_SLOC;
    float* sbeg   = ar + OFF_SBEG;
    float* ybuf   = ar + OFF_Y;
    float* keys   = ar + OFF_KEYS;
    float* kpe    = ar + OFF_KPE;
    float* tkiq   = ar + OFF_TKIQ;
    float* tv     = ar + OFF_TV;
    float* att    = ar + OFF_ATT;
    float* queries= ar + OFF_Q;
    float* qpe    = ar + OFF_QPE;
    float* sq     = ar + OFF_SQ;
    float* sk     = ar + OFF_SK;
    float* sv     = ar + OFF_SV;
    float* so     = ar + OFF_SO;
    float* qs160  = ar + OFF_QS160;
    float* ks160  = ar + OFF_KS160;
    float* vs160  = ar + OFF_VS160;
    float* tatt   = ar + OFF_TATT;
    float* mlph   = ar + OFF_MLPH;
    float* xpart  = ar + OFF_XPART;
    float* bkq    = ar + OFF_BKQ;

    bf16* xnH  = (bf16*)(ar + OFF_XNH);
    bf16* xnL  = (bf16*)(ar + OFF_XNL);
    bf16* yH   = (bf16*)(ar + OFF_YH);
    bf16* yL   = (bf16*)(ar + OFF_YL);
    bf16* kH   = (bf16*)(ar + OFF_KH);
    bf16* kL   = (bf16*)(ar + OFF_KL);
    bf16* kpH  = (bf16*)(ar + OFF_KPH);
    bf16* kpL  = (bf16*)(ar + OFF_KPL);
    bf16* iaH  = (bf16*)(ar + OFF_IAH);
    bf16* iaL  = (bf16*)(ar + OFF_IAL);
    bf16* inwH = (bf16*)(ar + OFF_INWH);
    bf16* inwL = (bf16*)(ar + OFF_INWL);
    bf16* outwH= (bf16*)(ar + OFF_OUTWH);
    bf16* outwL= (bf16*)(ar + OFF_OUTWL);
    bf16* t2iv = (bf16*)(ar + OFF_T2IV);
    bf16* i2tow= (bf16*)(ar + OFF_I2TOW);
    bf16* wkq  = (bf16*)(ar + OFF_WKQ);

    const int MROWS = NBATCH * NTOK;

    k_tln<<<dim3(NTOK / 32, NBATCH), 256>>>(x, ln_w, ln_b, xnH, xnL);
    k_wsplit<<<1760, 256>>>(in_w, inwH, inwL, DIN, CDIM, 1408, 320);
    k_wsplit<<<960, 256>>>(out_w, outwH, outwL, CDIM, DINNER, 384, 640);
    k_mma<<<dim3(11, 256), 256, SMEM_DYN>>>(xnH, xnL, inwH, inwL, nullptr, nullptr,
                                            zx, nullptr, nullptr, nullptr, nullptr, nullptr,
                                            DIN, 320, 10);
    k_convdt8<<<MROWS / 8, 256>>>(zx, conv_w, conv_b, dt_bias, xbc, dtb);

    for (int i = 0; i < 2; i++) {
        k_wsplit_cat<<<480, 256>>>(t2i_w + (size_t)(i * 3 + 1) * INNERD * CDIM,
                                   i2t_w + (size_t)(i * 3 + 0) * INNERD * CDIM,
                                   wkq + i * 245760, wkq + i * 245760 + 122880);
        k_biascat<<<1, 384>>>(t2i_b + (i * 3 + 1) * INNERD, i2t_b + (i * 3 + 0) * INNERD,
                              bkq + i * 384);
        k_wsplit<<<320, 256>>>(t2i_w + (size_t)(i * 3 + 2) * INNERD * CDIM,
                               t2iv + i * 163840, t2iv + i * 163840 + 81920, INNERD, CDIM, 256, 320);
        k_wsplit<<<288, 256>>>(i2t_ow + (size_t)i * CDIM * INNERD,
                               i2tow + i * 147456, i2tow + i * 147456 + 73728, CDIM, INNERD, 384, 192);
    }
    k_kpe<<<NTOK, 160>>>(pe_gauss, kpe);
    k_pointemb<<<12, 160>>>(coords, labels, pe_gauss, point_tab, queries, qpe);

    k_cumsum<<<NBATCH * NH, NCHUNK>>>(dtb, A_log, cum, csum);
    k_chunkstate<<<NBATCH * NH * NCHUNK, 256>>>(xbc, cum, dtb, sloc);
    k_scan<<<dim3(NBATCH * NH, 10), 256>>>(sloc, csum, sbeg);
    k_chunkout<<<NBATCH * NH * NCHUNK, 256>>>(xbc, cum, dtb, sbeg, Dp, ybuf);
    k_gaterms<<<MROWS, DINNER>>>(ybuf, zx, rms_w, yH, yL);
    k_mma<<<dim3(3, 256), 256, SMEM_DYN>>>(yH, yL, outwH, outwL, nullptr, nullptr,
                                           keys, kH, kL, kpe, kpH, kpL, CDIM, 640, 20);

    for (int i = 0; i < 2; i++) {
        const float* swq = sa_w + (size_t)(i * 4 + 0) * CDIM * CDIM;
        const float* swk = sa_w + (size_t)(i * 4 + 1) * CDIM * CDIM;
        const float* swv = sa_w + (size_t)(i * 4 + 2) * CDIM * CDIM;
        const float* swo = sa_w + (size_t)(i * 4 + 3) * CDIM * CDIM;
        const float* sbq = sa_b + (i * 4 + 0) * CDIM;
        const float* sbk = sa_b + (i * 4 + 1) * CDIM;
        const float* sbv = sa_b + (i * 4 + 2) * CDIM;
        const float* sbo = sa_b + (i * 4 + 3) * CDIM;

        const float* pe_q = (i == 0) ? nullptr : qpe;
        k_tiny<<<dim3(5, 12), 64>>>(queries, pe_q, swq, sbq, nullptr, sq, CDIM, CDIM, 0);
        k_tiny<<<dim3(5, 12), 64>>>(queries, pe_q, swk, sbk, nullptr, sk, CDIM, CDIM, 0);
        k_tiny<<<dim3(5, 12), 64>>>(queries, nullptr, swv, sbv, nullptr, sv, CDIM, CDIM, 0);
        k_selfattn<<<8, 128>>>(sq, sk, sv, so);
        k_tiny<<<dim3(5, 12), 64>>>(so, nullptr, swo, sbo, (i == 0) ? nullptr : queries,
                                    queries, CDIM, CDIM, 0);
        k_ln<<<12, CDIM>>>(queries, queries, norms_w + (i * 4 + 0) * CDIM,
                           norms_b + (i * 4 + 0) * CDIM, nullptr, nullptr,
                           nullptr, nullptr, nullptr);

        k_tiny<<<dim3(3, 12), 64>>>(queries, qpe, t2i_w + (size_t)(i * 3 + 0) * INNERD * CDIM,
                                    t2i_b + (i * 3 + 0) * INNERD, nullptr, qs160, INNERD, CDIM, 0);
        k_mma<<<dim3(3, 256), 256, SMEM_DYN>>>(kpH, kpL, wkq + i * 245760, wkq + i * 245760 + 122880,
                                               bkq + i * 384, nullptr,
                                               tkiq, nullptr, nullptr, nullptr, nullptr, nullptr,
                                               320, 320, 10);
        k_mma<<<dim3(2, 256), 256, SMEM_DYN>>>(kH, kL, t2iv + i * 163840, t2iv + i * 163840 + 81920,
                                               t2i_b + (i * 3 + 2) * INNERD, nullptr,
                                               tv, nullptr, nullptr, nullptr, nullptr, nullptr,
                                               INNERD, 320, 10);
        k_xscore6<<<dim3(8, 64), 256>>>(qs160, tkiq, att, 320);
        k_xsoftmax<<<48, 256, SMEM_SOFT>>>(att);
        k_xout6<<<dim3(8, 8), 240>>>(att, tv, xpart);
        k_xout_c6<<<8, 240>>>(xpart, tatt);
        k_tiny<<<dim3(5, 12), 64>>>(tatt, nullptr, t2i_ow + (size_t)i * CDIM * INNERD,
                                    t2i_ob + i * CDIM, queries, queries, CDIM, INNERD, 0);
        k_ln<<<12, CDIM>>>(queries, queries, norms_w + (i * 4 + 1) * CDIM,
                           norms_b + (i * 4 + 1) * CDIM, nullptr, nullptr,
                           nullptr, nullptr, nullptr);

        k_tiny<<<dim3(16, 12), 64>>>(queries, nullptr, mlp_w1 + (size_t)i * MLPD * CDIM,
                                     mlp_b1 + i * MLPD, nullptr, mlph, MLPD, CDIM, 1);
        k_tiny<<<dim3(5, 12), 64>>>(mlph, nullptr, mlp_w2 + (size_t)i * CDIM * MLPD,
                                    mlp_b2 + i * CDIM, queries, queries, CDIM, MLPD, 0);
        k_ln<<<12, CDIM>>>(queries, queries, norms_w + (i * 4 + 2) * CDIM,
                           norms_b + (i * 4 + 2) * CDIM, nullptr, nullptr,
                           nullptr, nullptr, nullptr);

        k_tiny<<<dim3(3, 12), 64>>>(queries, qpe, i2t_w + (size_t)(i * 3 + 1) * INNERD * CDIM,
                                    i2t_b + (i * 3 + 1) * INNERD, nullptr, ks160, INNERD, CDIM, 0);
        k_tiny<<<dim3(3, 12), 64>>>(queries, nullptr, i2t_w + (size_t)(i * 3 + 2) * INNERD * CDIM,
                                    i2t_b + (i * 3 + 2) * INNERD, nullptr, vs160, INNERD, CDIM, 0);
        k_i2t<<<dim3(NTOK / 32, NBATCH), 128>>>(tkiq, ks160, vs160, iaH, iaL);
        k_mma<<<dim3(3, 256), 256, SMEM_DYN>>>(iaH, iaL, i2tow + i * 147456, i2tow + i * 147456 + 73728,
                                               i2t_ob + i * CDIM, keys,
                                               keys, nullptr, nullptr, nullptr, nullptr, nullptr,
                                               CDIM, 192, 6);
        if (i == 0) {
            k_ln<<<MROWS, CDIM>>>(keys, keys, norms_w + (i * 4 + 3) * CDIM,
                                  norms_b + (i * 4 + 3) * CDIM, kH, kL,
                                  kpe, kpH, kpL);
        } else {
            k_ln<<<MROWS, CDIM>>>(keys, keys, norms_w + (i * 4 + 3) * CDIM,
                                  norms_b + (i * 4 + 3) * CDIM, nullptr, nullptr,
                                  nullptr, nullptr, nullptr);
        }
    }

    k_transpose_out<<<dim3(NTOK / 32, CDIM / 32, NBATCH), dim3(32, 8)>>>(keys, out);
}

// round 14
// speedup vs baseline: 1.1088x; 1.0456x over previous
#include <cuda_runtime.h>
#include <cuda_bf16.h>
#include <math.h>
#include <stdint.h>

#define NBATCH 2
#define CDIM 320
#define NTOK 16384
#define DIN 1352
#define DINNER 640
#define CONVD 704
#define DSTATE 32
#define NH 8
#define HP 80
#define NCHUNK 256
#define INNERD 160
#define MLPD 1024

typedef __nv_bfloat16 bf16;

constexpr size_t SZ_XF   = (size_t)NBATCH*NTOK*CDIM;
constexpr size_t SZ_ZX   = (size_t)NBATCH*NTOK*DIN;
constexpr size_t SZ_XBC  = (size_t)NBATCH*NTOK*CONVD;
constexpr size_t SZ_DTB  = (size_t)NBATCH*NH*NTOK;
constexpr size_t SZ_SL   = (size_t)NBATCH*NH*NCHUNK*DSTATE*HP;
constexpr size_t SZ_Y    = (size_t)NBATCH*NTOK*DINNER;
constexpr size_t SZ_KPE  = (size_t)NTOK*CDIM;
constexpr size_t SZ_I160 = (size_t)NBATCH*NTOK*INNERD;
constexpr size_t SZ_ATT  = (size_t)48*NTOK;

constexpr size_t OFF_XF    = 0;
constexpr size_t OFF_ZX    = OFF_XF    + SZ_XF;
constexpr size_t OFF_XBC   = OFF_ZX    + SZ_ZX;
constexpr size_t OFF_DTB   = OFF_XBC   + SZ_XBC;
constexpr size_t OFF_CUM   = OFF_DTB   + SZ_DTB;
constexpr size_t OFF_CSUM  = OFF_CUM   + SZ_DTB;
constexpr size_t OFF_SLOC  = OFF_CSUM  + (size_t)NBATCH*NH*NCHUNK;
constexpr size_t OFF_SBEG  = OFF_SLOC  + SZ_SL;
constexpr size_t OFF_Y     = OFF_SBEG  + SZ_SL;
constexpr size_t OFF_KEYS  = OFF_Y     + SZ_Y;
constexpr size_t OFF_KPE   = OFF_KEYS  + SZ_XF;
constexpr size_t OFF_TKIQ  = OFF_KPE   + SZ_KPE;
constexpr size_t OFF_TV    = OFF_TKIQ  + 2 * SZ_I160;
constexpr size_t OFF_ATT   = OFF_TV    + SZ_I160;
constexpr size_t OFF_Q     = OFF_ATT   + SZ_ATT;
constexpr size_t OFF_QPE   = OFF_Q     + 3840;
constexpr size_t OFF_SQ    = OFF_QPE   + 3840;
constexpr size_t OFF_SK    = OFF_SQ    + 3840;
constexpr size_t OFF_SV    = OFF_SK    + 3840;
constexpr size_t OFF_SO    = OFF_SV    + 3840;
constexpr size_t OFF_QS160 = OFF_SO    + 3840;
constexpr size_t OFF_KS160 = OFF_QS160 + 1920;
constexpr size_t OFF_VS160 = OFF_KS160 + 1920;
constexpr size_t OFF_TATT  = OFF_VS160 + 1920;
constexpr size_t OFF_MLPH  = OFF_TATT  + 1920;
constexpr size_t OFF_XNH   = OFF_MLPH + 12288;
constexpr size_t OFF_XNL   = OFF_XNH + 5242880;
constexpr size_t OFF_YH    = OFF_XNL + 5242880;
constexpr size_t OFF_YL    = OFF_YH  + 10485760;
constexpr size_t OFF_KH    = OFF_YL  + 10485760;
constexpr size_t OFF_KL    = OFF_KH  + 5242880;
constexpr size_t OFF_KPH   = OFF_KL  + 5242880;
constexpr size_t OFF_KPL   = OFF_KPH + 5242880;
constexpr size_t OFF_IAH   = OFF_KPL + 5242880;
constexpr size_t OFF_IAL   = OFF_IAH + 3145728;
constexpr size_t OFF_INWH  = OFF_IAL + 3145728;
constexpr size_t OFF_INWL  = OFF_INWH + 225280;
constexpr size_t OFF_OUTWH = OFF_INWL + 225280;
constexpr size_t OFF_OUTWL = OFF_OUTWH + 122880;
constexpr size_t OFF_T2IV  = OFF_OUTWL + 122880;
constexpr size_t OFF_I2TOW = OFF_T2IV + 163840;
constexpr size_t OFF_XPART = OFF_I2TOW + 147456;
constexpr size_t OFF_WKQ   = OFF_XPART + 30720;
constexpr size_t OFF_BKQ   = OFF_WKQ + 245760;
constexpr size_t ARENA_FLOATS = OFF_BKQ + 768;

__device__ __align__(128) float g_arena[ARENA_FLOATS];

__device__ __forceinline__ uint32_t smem_u32(const void* p) {
    uint32_t a;
    asm("{ .reg .u64 t; cvta.to.shared.u64 t, %1; cvt.u32.u64 %0, t; }" : "=r"(a) : "l"(p));
    return a;
}
__device__ __forceinline__ void ldm_x4(uint32_t* r, uint32_t a) {
    asm volatile("ldmatrix.sync.aligned.m8n8.x4.shared.b16 {%0,%1,%2,%3}, [%4];"
        : "=r"(r[0]), "=r"(r[1]), "=r"(r[2]), "=r"(r[3]) : "r"(a));
}
__device__ __forceinline__ void mma16816(float* c, const uint32_t* a, const uint32_t* b) {
    asm volatile("mma.sync.aligned.m16n8k16.row.col.f32.bf16.bf16.f32 "
        "{%0,%1,%2,%3}, {%4,%5,%6,%7}, {%8,%9}, {%0,%1,%2,%3};"
        : "+f"(c[0]), "+f"(c[1]), "+f"(c[2]), "+f"(c[3])
        : "r"(a[0]), "r"(a[1]), "r"(a[2]), "r"(a[3]), "r"(b[0]), "r"(b[1]));
}
__device__ __forceinline__ void cpasync16(uint32_t dst, const void* src) {
    asm volatile("cp.async.cg.shared.global [%0], [%1], 16;" :: "r"(dst), "l"(src));
}
__device__ __forceinline__ void split_bf16(float v, bf16& h, bf16& l) {
    h = __float2bfloat16(v);
    l = __float2bfloat16(v - __bfloat162float(h));
}

__device__ __forceinline__ float blockReduceSum(float v) {
    __shared__ float sh[33];
    int lane = threadIdx.x & 31, wid = threadIdx.x >> 5;
#pragma unroll
    for (int o = 16; o; o >>= 1) v += __shfl_down_sync(0xffffffffu, v, o);
    if (lane == 0) sh[wid] = v;
    __syncthreads();
    int nw = (blockDim.x + 31) >> 5;
    if (wid == 0) {
        v = (lane < nw) ? sh[lane] : 0.f;
#pragma unroll
        for (int o = 16; o; o >>= 1) v += __shfl_down_sync(0xffffffffu, v, o);
        if (lane == 0) sh[32] = v;
    }
    __syncthreads();
    v = sh[32];
    __syncthreads();
    return v;
}
__device__ __forceinline__ float2 blockReduceSum2(float a, float b) {
    __shared__ float sh[66];
    int lane = threadIdx.x & 31, wid = threadIdx.x >> 5;
#pragma unroll
    for (int o = 16; o; o >>= 1) {
        a += __shfl_down_sync(0xffffffffu, a, o);
        b += __shfl_down_sync(0xffffffffu, b, o);
    }
    if (lane == 0) { sh[wid * 2] = a; sh[wid * 2 + 1] = b; }
    __syncthreads();
    int nw = (blockDim.x + 31) >> 5;
    if (wid == 0) {
        a = (lane < nw) ? sh[lane * 2] : 0.f;
        b = (lane < nw) ? sh[lane * 2 + 1] : 0.f;
#pragma unroll
        for (int o = 16; o; o >>= 1) {
            a += __shfl_down_sync(0xffffffffu, a, o);
            b += __shfl_down_sync(0xffffffffu, b, o);
        }
        if (lane == 0) { sh[64] = a; sh[65] = b; }
    }
    __syncthreads();
    float2 r = make_float2(sh[64], sh[65]);
    __syncthreads();
    return r;
}
__device__ __forceinline__ float blockReduceMax(float v) {
    __shared__ float sh[33];
    int lane = threadIdx.x & 31, wid = threadIdx.x >> 5;
#pragma unroll
    for (int o = 16; o; o >>= 1) v = fmaxf(v, __shfl_down_sync(0xffffffffu, v, o));
    if (lane == 0) sh[wid] = v;
    __syncthreads();
    int nw = (blockDim.x + 31) >> 5;
    if (wid == 0) {
        v = (lane < nw) ? sh[lane] : -1e30f;
#pragma unroll
        for (int o = 16; o; o >>= 1) v = fmaxf(v, __shfl_down_sync(0xffffffffu, v, o));
        if (lane == 0) sh[32] = v;
    }
    __syncthreads();
    v = sh[32];
    __syncthreads();
    return v;
}
__device__ __forceinline__ float siluf(float x) { return x / (1.f + expf(-x)); }

// ---- tensor-core split GEMM (stable since R9) ----
__global__ void __launch_bounds__(256, 2)
k_mma(const bf16* __restrict__ aH, const bf16* __restrict__ aL,
      const bf16* __restrict__ wH, const bf16* __restrict__ wL,
      const float* __restrict__ bias, const float* __restrict__ R,
      float* __restrict__ C, bf16* __restrict__ cH, bf16* __restrict__ cL,
      const float* __restrict__ pe, bf16* __restrict__ peH, bf16* __restrict__ peL,
      int Nact, int Kd, int nkb) {
    extern __shared__ bf16 sm[];
    constexpr int TSZ = 128 * 40;
    const int tid = threadIdx.x;
    const int wid = tid >> 5, lane = tid & 31;
    const int wm = wid & 1, wn = wid >> 1;
    const int m0 = blockIdx.y * 128, n0 = blockIdx.x * 128;

    const bf16* srcs[4] = { aH + (size_t)m0 * Kd, aL + (size_t)m0 * Kd,
                            wH + (size_t)n0 * Kd, wL + (size_t)n0 * Kd };
    const int lrow = tid >> 2, lc8 = (tid & 3) * 8;

    auto prefetch = [&](int kb, int buf) {
#pragma unroll
        for (int q = 0; q < 4; q++) {
            bf16* t = sm + buf * 4 * TSZ + q * TSZ;
#pragma unroll
            for (int l = 0; l < 2; l++) {
                int row = lrow + l * 64;
                cpasync16(smem_u32(t + row * 40 + lc8),
                          srcs[q] + (size_t)row * Kd + kb * 32 + lc8);
            }
        }
        asm volatile("cp.async.commit_group;");
    };

    float acc[4][4][4];
#pragma unroll
    for (int i = 0; i < 4; i++)
#pragma unroll
        for (int j = 0; j < 4; j++)
#pragma unroll
            for (int r = 0; r < 4; r++) acc[i][j][r] = 0.f;

    prefetch(0, 0);
    if (nkb > 1) prefetch(1, 1);

    const int arow = wm * 64 + (((lane >> 3) & 1) << 3) + (lane & 7);
    const int acol = ((lane >> 4) << 3);
    const int brow = wn * 32 + ((lane >> 4) << 3) + (lane & 7);
    const int bcol = (((lane >> 3) & 1) << 3);

    for (int kb = 0; kb < nkb; kb++) {
        if (kb + 1 < nkb) asm volatile("cp.async.wait_group 1;");
        else              asm volatile("cp.async.wait_group 0;");
        __syncthreads();
        const int buf = kb & 1;
        const bf16* tAH = sm + buf * 4 * TSZ;
        const bf16* tAL = tAH + TSZ;
        const bf16* tWH = tAH + 2 * TSZ;
        const bf16* tWL = tAH + 3 * TSZ;
#pragma unroll
        for (int ks = 0; ks < 2; ks++) {
            uint32_t aHf[4][4], aLf[4][4];
#pragma unroll
            for (int mi = 0; mi < 4; mi++) {
                int off = (arow + mi * 16) * 40 + ks * 16 + acol;
                ldm_x4(aHf[mi], smem_u32(tAH + off));
                ldm_x4(aLf[mi], smem_u32(tAL + off));
            }
#pragma unroll
            for (int nfp = 0; nfp < 2; nfp++) {
                uint32_t bHf[4], bLf[4];
                int off = (brow + nfp * 16) * 40 + ks * 16 + bcol;
                ldm_x4(bHf, smem_u32(tWH + off));
                ldm_x4(bLf, smem_u32(tWL + off));
#pragma unroll
                for (int mi = 0; mi < 4; mi++) {
                    mma16816(acc[mi][nfp * 2 + 0], aHf[mi], bHf);
                    mma16816(acc[mi][nfp * 2 + 1], aHf[mi], bHf + 2);
                }
#pragma unroll
                for (int mi = 0; mi < 4; mi++) {
                    mma16816(acc[mi][nfp * 2 + 0], aHf[mi], bLf);
                    mma16816(acc[mi][nfp * 2 + 1], aHf[mi], bLf + 2);
                }
#pragma unroll
                for (int mi = 0; mi < 4; mi++) {
                    mma16816(acc[mi][nfp * 2 + 0], aLf[mi], bHf);
                    mma16816(acc[mi][nfp * 2 + 1], aLf[mi], bHf + 2);
                }
            }
        }
        __syncthreads();
        if (kb + 2 < nkb) prefetch(kb + 2, buf);
    }

    const int qr = lane >> 2, qc = (lane & 3) * 2;
#pragma unroll
    for (int mi = 0; mi < 4; mi++)
#pragma unroll
        for (int nf = 0; nf < 4; nf++) {
            int n = n0 + wn * 32 + nf * 8 + qc;
            if (n >= Nact) continue;
#pragma unroll
            for (int h = 0; h < 2; h++) {
                int m = m0 + wm * 64 + mi * 16 + qr + h * 8;
                float v0 = acc[mi][nf][h * 2 + 0];
                float v1 = acc[mi][nf][h * 2 + 1];
                if (bias) { v0 += bias[n]; v1 += bias[n + 1]; }
                size_t o = (size_t)m * Nact + n;
                if (R) { v0 += R[o]; v1 += R[o + 1]; }
                C[o] = v0; C[o + 1] = v1;
                bf16 hh, ll;
                if (cH) {
                    split_bf16(v0, hh, ll); cH[o] = hh;     cL[o] = ll;
                    split_bf16(v1, hh, ll); cH[o + 1] = hh; cL[o + 1] = ll;
                }
                if (peH) {
                    size_t pi = (size_t)(m & (NTOK - 1)) * Nact + n;
                    split_bf16(v0 + pe[pi], hh, ll);     peH[o] = hh;     peL[o] = ll;
                    split_bf16(v1 + pe[pi + 1], hh, ll); peH[o + 1] = hh; peL[o + 1] = ll;
                }
            }
        }
}

__global__ void k_wsplit(const float* __restrict__ W, bf16* __restrict__ hi,
                         bf16* __restrict__ lo, int N, int K, int Npad, int Kpad) {
    int idx = blockIdx.x * 256 + threadIdx.x;
    if (idx >= Npad * Kpad) return;
    int n = idx / Kpad, k = idx % Kpad;
    float v = (n < N && k < K) ? W[(size_t)n * K + k] : 0.f;
    bf16 h, l;
    split_bf16(v, h, l);
    hi[idx] = h; lo[idx] = l;
}

__global__ void k_wsplit_cat(const float* __restrict__ W1, const float* __restrict__ W2,
                             bf16* __restrict__ hi, bf16* __restrict__ lo) {
    int idx = blockIdx.x * 256 + threadIdx.x;
    if (idx >= 384 * 320) return;
    int n = idx / 320, k = idx % 320;
    float v = 0.f;
    if (n < 160) v = W1[(size_t)n * 320 + k];
    else if (n < 320) v = W2[(size_t)(n - 160) * 320 + k];
    bf16 h, l;
    split_bf16(v, h, l);
    hi[idx] = h; lo[idx] = l;
}

__global__ void k_biascat(const float* __restrict__ b1, const float* __restrict__ b2,
                          float* __restrict__ dst) {
    int n = threadIdx.x;
    dst[n] = (n < 160) ? b1[n] : ((n < 320) ? b2[n - 160] : 0.f);
}

__global__ void k_tln(const float* __restrict__ x, const float* __restrict__ w,
                      const float* __restrict__ b, bf16* __restrict__ hi,
                      bf16* __restrict__ lo) {
    __shared__ float tile[320 * 33];
    __shared__ float mu[32], rs[32];
    int bq = blockIdx.y;
    int t0 = blockIdx.x * 32;
    int tid = threadIdx.x;
    for (int e = tid; e < 320 * 32; e += 256) {
        int c = e >> 5, tok = e & 31;
        tile[c * 33 + tok] = x[((size_t)(bq * CDIM + c)) * NTOK + t0 + tok];
    }
    __syncthreads();
    int wid = tid >> 5, lane = tid & 31;
#pragma unroll
    for (int k = 0; k < 4; k++) {
        int tok = wid * 4 + k;
        float s = 0.f, v = 0.f;
        for (int c = lane; c < 320; c += 32) {
            float t = tile[c * 33 + tok];
            s += t; v += t * t;
        }
#pragma unroll
        for (int o = 16; o; o >>= 1) {
            s += __shfl_down_sync(0xffffffffu, s, o);
            v += __shfl_down_sync(0xffffffffu, v, o);
        }
        if (lane == 0) {
            float m = s / 320.f;
            mu[tok] = m;
            rs[tok] = rsqrtf(v / 320.f - m * m + 1e-5f);
        }
    }
    __syncthreads();
    for (int e = tid; e < 10240; e += 256) {
        int tok = e / 320, c = e % 320;
        float r = (tile[c * 33 + tok] - mu[tok]) * rs[tok] * w[c] + b[c];
        size_t o = ((size_t)(bq * NTOK + t0 + tok)) * 320 + c;
        bf16 h, l;
        split_bf16(r, h, l);
        hi[o] = h; lo[o] = l;
    }
}

__global__ void k_transpose_out(const float* __restrict__ keys, float* __restrict__ out) {
    __shared__ float tile[32][33];
    int b = blockIdx.z;
    int t0 = blockIdx.x * 32, c0 = blockIdx.y * 32;
#pragma unroll
    for (int i = 0; i < 4; i++) {
        int tt = threadIdx.y + i * 8;
        tile[threadIdx.x][tt] = keys[((size_t)(b * NTOK + t0 + tt)) * CDIM + c0 + threadIdx.x];
    }
    __syncthreads();
#pragma unroll
    for (int i = 0; i < 4; i++) {
        int cc = threadIdx.y + i * 8;
        out[((size_t)(b * CDIM + c0 + cc)) * NTOK + t0 + threadIdx.x] = tile[cc][threadIdx.x];
    }
}

__global__ void k_ln(const float* __restrict__ src, float* __restrict__ dst,
                     const float* __restrict__ w, const float* __restrict__ b,
                     bf16* __restrict__ hi, bf16* __restrict__ lo,
                     const float* __restrict__ pe, bf16* __restrict__ peH,
                     bf16* __restrict__ peL) {
    int row = blockIdx.x;
    int D = blockDim.x;
    float v = src[(size_t)row * D + threadIdx.x];
    float2 sv = blockReduceSum2(v, v * v);
    float m = sv.x / D;
    float var = sv.y / D - m * m;
    float r = (v - m) * rsqrtf(var + 1e-5f) * w[threadIdx.x] + b[threadIdx.x];
    size_t o = (size_t)row * D + threadIdx.x;
    if (dst) dst[o] = r;
    bf16 h, l;
    if (hi) { split_bf16(r, h, l); hi[o] = h; lo[o] = l; }
    if (peH) {
        float pv = r + pe[(size_t)(row & (NTOK - 1)) * D + threadIdx.x];
        split_bf16(pv, h, l);
        peH[o] = h; peL[o] = l;
    }
}

__global__ void k_tiny(const float* __restrict__ A1, const float* __restrict__ A2,
                       const float* __restrict__ W, const float* __restrict__ bias,
                       const float* __restrict__ R, float* __restrict__ C,
                       int N, int K, int act) {
    int r = blockIdx.y;
    int n = blockIdx.x * 64 + threadIdx.x;
    if (n >= N) return;
    const float* a1 = A1 + (size_t)r * K;
    const float* a2 = A2 ? A2 + (size_t)r * K : nullptr;
    const float* w = W + (size_t)n * K;
    float acc = bias ? bias[n] : 0.f;
    if (a2) { for (int k = 0; k < K; k++) acc += (a1[k] + a2[k]) * w[k]; }
    else    { for (int k = 0; k < K; k++) acc += a1[k] * w[k]; }
    if (act == 1) acc = fmaxf(acc, 0.f);
    if (R) acc += R[(size_t)r * N + n];
    C[(size_t)r * N + n] = acc;
}

__global__ void k_convdt8(const float* __restrict__ zx, const float* __restrict__ conv_w,
                          const float* __restrict__ conv_b, const float* __restrict__ dt_bias,
                          float* __restrict__ xbc, float* __restrict__ dtb) {
    __shared__ float sxr[11][CONVD];
    int blk = blockIdx.x;
    int b = blk >> 11;
    int t0 = (blk & 2047) * 8;
    int tid = threadIdx.x;
#pragma unroll
    for (int r = 0; r < 11; r++) {
        int ts = t0 + r - 3;
        const float* src = zx + ((size_t)(b * NTOK + ts)) * DIN + DINNER;
        for (int c = tid; c < CONVD; c += 256)
            sxr[r][c] = (ts >= 0) ? src[c] : 0.f;
    }
    __syncthreads();
    for (int c = tid; c < CONVD; c += 256) {
        float w0 = conv_w[c * 4], w1 = conv_w[c * 4 + 1];
        float w2 = conv_w[c * 4 + 2], w3 = conv_w[c * 4 + 3];
        float cb = conv_b[c];
#pragma unroll
        for (int q = 0; q < 8; q++) {
            float acc = cb + sxr[q][c] * w0 + sxr[q + 1][c] * w1
                      + sxr[q + 2][c] * w2 + sxr[q + 3][c] * w3;
            xbc[((size_t)(b * NTOK + t0 + q)) * CONVD + c] = siluf(acc);
        }
    }
    if (tid < 64) {
        int q = tid >> 3, h = tid & 7;
        float xv = zx[((size_t)(b * NTOK + t0 + q)) * DIN + DINNER + CONVD + h] + dt_bias[h];
        float dt = (xv > 20.f) ? xv : log1pf(expf(xv));
        dtb[(((size_t)(b * NH + h)) << 14) + t0 + q] = dt;
    }
}

__global__ void k_cumsum(const float* __restrict__ dtb, const float* __restrict__ A_log,
                         float* __restrict__ cum, float* __restrict__ csum) {
    int bh = blockIdx.x;
    int h = bh & 7;
    float A = -expf(A_log[h]);
    int c = threadIdx.x;
    size_t base = ((size_t)bh << 14) + (size_t)c * 64;
    float run = 0.f;
    for (int t = 0; t < 64; t++) {
        run += dtb[base + t] * A;
        cum[base + t] = run;
    }
    csum[bh * NCHUNK + c] = run;
}

__global__ void k_chunkstate(const float* __restrict__ xbc, const float* __restrict__ cum,
                             const float* __restrict__ dtb, float* __restrict__ sloc) {
    int idx = blockIdx.x;
    int c = idx & 255, bh = idx >> 8;
    int b = bh >> 3, h = bh & 7;
    __shared__ float sB[64 * 32];
    __shared__ float sx[64 * 80];
    __shared__ float coef[64];
    int tid = threadIdx.x;
    size_t tbase = (size_t)b * NTOK + (size_t)c * 64;
    for (int e = tid; e < 64 * 32; e += 256) {
        int t = e >> 5, n = e & 31;
        sB[e] = xbc[(tbase + t) * CONVD + DINNER + n];
    }
    for (int e = tid; e < 64 * 80; e += 256) {
        int t = e / 80, p = e % 80;
        sx[e] = xbc[(tbase + t) * CONVD + h * HP + p];
    }
    if (tid < 64) {
        size_t cb = ((size_t)bh << 14) + (size_t)c * 64;
        float cl = cum[cb + 63];
        coef[tid] = expf(cl - cum[cb + tid]) * dtb[cb + tid];
    }
    __syncthreads();
    int n = tid >> 3, p0 = (tid & 7) * 10;
    float2 a2[5] = {};
    for (int t = 0; t < 64; t++) {
        float bc = coef[t] * sB[t * 32 + n];
        const float2* xr = (const float2*)&sx[t * 80 + p0];
#pragma unroll
        for (int j = 0; j < 5; j++) {
            float2 xv = xr[j];
            a2[j].x += bc * xv.x;
            a2[j].y += bc * xv.y;
        }
    }
    float2* so = (float2*)&sloc[((size_t)bh * NCHUNK + c) * 2560 + n * 80 + p0];
#pragma unroll
    for (int j = 0; j < 5; j++) so[j] = a2[j];
}

__global__ void k_scan(const float* __restrict__ sloc, const float* __restrict__ csum,
                       float* __restrict__ sbeg) {
    __shared__ float sdec[256];
    int bh = blockIdx.x;
    int e = blockIdx.y * 256 + threadIdx.x;
    sdec[threadIdx.x] = expf(csum[bh * NCHUNK + threadIdx.x]);
    __syncthreads();
    float S = 0.f;
    size_t base = (size_t)bh * NCHUNK * 2560 + e;
    for (int c = 0; c < NCHUNK; c += 4) {
        size_t b0 = base + (size_t)c * 2560;
        float x0 = sloc[b0];
        float x1 = sloc[b0 + 2560];
        float x2 = sloc[b0 + 5120];
        float x3 = sloc[b0 + 7680];
        sbeg[b0] = S;        S = S * sdec[c]     + x0;
        sbeg[b0 + 2560] = S; S = S * sdec[c + 1] + x1;
        sbeg[b0 + 5120] = S; S = S * sdec[c + 2] + x2;
        sbeg[b0 + 7680] = S; S = S * sdec[c + 3] + x3;
    }
}

__global__ void k_chunkout(const float* __restrict__ xbc, const float* __restrict__ cum,
                           const float* __restrict__ dtb, const float* __restrict__ sbeg,
                           const float* __restrict__ Dp, float* __restrict__ y) {
    int idx = blockIdx.x;
    int c = idx & 255, bh = idx >> 8;
    int b = bh >> 3, h = bh & 7;
    __shared__ float sM[64 * 65];
    __shared__ float sC[64 * 33];
    __shared__ float sR[5120];
    __shared__ float sCum[64];
    __shared__ float sDt[64];
    int tid = threadIdx.x;
    size_t tbase = (size_t)b * NTOK + (size_t)c * 64;
    size_t cb = ((size_t)bh << 14) + (size_t)c * 64;
    size_t sb_base = ((size_t)bh * NCHUNK + c) * 2560;
    for (int e = tid; e < 2048; e += 256) {
        int t = e >> 5, n = e & 31;
        sC[t * 33 + n] = xbc[(tbase + t) * CONVD + DINNER + DSTATE + n];
    }
    for (int e = tid; e < 2560; e += 256) sR[e] = sbeg[sb_base + e];
    if (tid < 64) { sCum[tid] = cum[cb + tid]; sDt[tid] = dtb[cb + tid]; }
    __syncthreads();
    int t = tid >> 2, p0 = (tid & 3) * 20;
    float4 a4[5] = {};
    for (int n = 0; n < 32; n++) {
        float cv = sC[t * 33 + n];
        const float4* rr = (const float4*)&sR[n * 80 + p0];
#pragma unroll
        for (int j = 0; j < 5; j++) {
            float4 rv = rr[j];
            a4[j].x += cv * rv.x; a4[j].y += cv * rv.y;
            a4[j].z += cv * rv.z; a4[j].w += cv * rv.w;
        }
    }
    float et = expf(sCum[t]);
#pragma unroll
    for (int j = 0; j < 5; j++) {
        a4[j].x *= et; a4[j].y *= et; a4[j].z *= et; a4[j].w *= et;
    }
    __syncthreads();
    for (int e = tid; e < 2048; e += 256) {
        int s = e >> 5, n = e & 31;
        sR[s * 33 + n] = xbc[(tbase + s) * CONVD + DINNER + n];
    }
    __syncthreads();
    for (int e = tid; e < 4096; e += 256) {
        int tt = e >> 6, s = e & 63;
        float m = 0.f;
        if (s <= tt) {
            float d = 0.f;
#pragma unroll 8
            for (int n = 0; n < 32; n++) d += sC[tt * 33 + n] * sR[s * 33 + n];
            m = d * expf(sCum[tt] - sCum[s]) * sDt[s];
        }
        sM[tt * 65 + s] = m;
    }
    __syncthreads();
    for (int e = tid; e < 5120; e += 256) {
        int s = e / 80, p = e % 80;
        sR[e] = xbc[(tbase + s) * CONVD + h * HP + p];
    }
    __syncthreads();
    for (int s = 0; s < 64; s++) {
        float m = sM[t * 65 + s];
        const float4* rr = (const float4*)&sR[s * 80 + p0];
#pragma unroll
        for (int j = 0; j < 5; j++) {
            float4 rv = rr[j];
            a4[j].x += m * rv.x; a4[j].y += m * rv.y;
            a4[j].z += m * rv.z; a4[j].w += m * rv.w;
        }
    }
    float dph = Dp[h];
    const float4* xr = (const float4*)&sR[t * 80 + p0];
    float4* yo = (float4*)&y[(tbase + t) * DINNER + h * HP + p0];
#pragma unroll
    for (int j = 0; j < 5; j++) {
        float4 xv = xr[j];
        float4 o;
        o.x = a4[j].x + dph * xv.x; o.y = a4[j].y + dph * xv.y;
        o.z = a4[j].z + dph * xv.z; o.w = a4[j].w + dph * xv.w;
        yo[j] = o;
    }
}

__global__ void k_gaterms(const float* __restrict__ y, const float* __restrict__ zx,
                          const float* __restrict__ rms_w,
                          bf16* __restrict__ hi, bf16* __restrict__ lo) {
    size_t row = blockIdx.x;
    int e = threadIdx.x;
    float v = y[row * DINNER + e];
    float z = zx[row * DIN + e];
    v = v * siluf(z);
    float ms = blockReduceSum(v * v) / DINNER;
    float r = v * rsqrtf(ms + 1e-5f) * rms_w[e];
    bf16 h, l;
    split_bf16(r, h, l);
    hi[row * DINNER + e] = h;
    lo[row * DINNER + e] = l;
}

__global__ void k_kpe(const float* __restrict__ gauss, float* __restrict__ kpe) {
    int t = blockIdx.x;
    int j = threadIdx.x;
    int d = t >> 10, hh = (t >> 5) & 31, w = t & 31;
    float g0 = 2.f * ((d + 0.5f) / 16.f) - 1.f;
    float g1 = 2.f * ((hh + 0.5f) / 32.f) - 1.f;
    float g2 = 2.f * ((w + 0.5f) / 32.f) - 1.f;
    float ang = 6.283185307179586f * (g0 * gauss[j] + g1 * gauss[160 + j] + g2 * gauss[320 + j]);
    kpe[(size_t)t * CDIM + j] = sinf(ang);
    kpe[(size_t)t * CDIM + 160 + j] = cosf(ang);
}

__global__ void k_pointemb(const float* __restrict__ coords, const int* __restrict__ labels,
                           const float* __restrict__ gauss, const float* __restrict__ ptab,
                           float* __restrict__ q, float* __restrict__ qpe) {
    int r = blockIdx.x;
    int j = threadIdx.x;
    float c0 = coords[r * 3 + 0] * (2.f / 128.f) - 1.f;
    float c1 = coords[r * 3 + 1] * (2.f / 256.f) - 1.f;
    float c2 = coords[r * 3 + 2] * (2.f / 256.f) - 1.f;
    float ang = 6.283185307179586f * (c0 * gauss[j] + c1 * gauss[160 + j] + c2 * gauss[320 + j]);
    int lab = labels[r];
    float s = sinf(ang) + ptab[lab * CDIM + j];
    float cc = cosf(ang) + ptab[lab * CDIM + 160 + j];
    q[r * CDIM + j] = s;      q[r * CDIM + 160 + j] = cc;
    qpe[r * CDIM + j] = s;    qpe[r * CDIM + 160 + j] = cc;
}

__global__ void k_selfattn(const float* __restrict__ q, const float* __restrict__ k,
                           const float* __restrict__ v, float* __restrict__ o) {
    int b = blockIdx.x >> 2, h = blockIdx.x & 3;
    __shared__ float sc[6][6];
    int tid = threadIdx.x;
    if (tid < 36) {
        int qi = tid / 6, ki = tid % 6;
        float s = 0.f;
        for (int d = 0; d < 80; d++)
            s += q[(b * 6 + qi) * CDIM + h * 80 + d] * k[(b * 6 + ki) * CDIM + h * 80 + d];
        sc[qi][ki] = s * 0.11180339887498948f;
    }
    __syncthreads();
    if (tid < 6) {
        float mx = -1e30f;
        for (int j = 0; j < 6; j++) mx = fmaxf(mx, sc[tid][j]);
        float sum = 0.f;
        for (int j = 0; j < 6; j++) { float e = expf(sc[tid][j] - mx); sc[tid][j] = e; sum += e; }
        float inv = 1.f / sum;
        for (int j = 0; j < 6; j++) sc[tid][j] *= inv;
    }
    __syncthreads();
    for (int e = tid; e < 480; e += 128) {
        int qi = e / 80, d = e % 80;
        float a = 0.f;
        for (int j = 0; j < 6; j++) a += sc[qi][j] * v[(b * 6 + j) * CDIM + h * 80 + d];
        o[(b * 6 + qi) * CDIM + h * 80 + d] = a;
    }
}

// fused 6-query score, float4 key loads (2x sector efficiency)
__global__ void k_xscore6(const float* __restrict__ q, const float* __restrict__ kimg,
                          float* __restrict__ att, int kstride) {
    int bh = blockIdx.x;
    int b = bh >> 2, h = bh & 3;
    __shared__ float sq[6][40];
    int tid = threadIdx.x;
    if (tid < 240) sq[tid / 40][tid % 40] = q[(b * 6 + tid / 40) * INNERD + h * 40 + tid % 40];
    __syncthreads();
    int key = blockIdx.y * 256 + tid;
    const float4* kr = (const float4*)(kimg + ((size_t)b * NTOK + key) * kstride + h * 40);
    float kv[40];
#pragma unroll
    for (int d4 = 0; d4 < 10; d4++) {
        float4 v = kr[d4];
        kv[d4 * 4 + 0] = v.x; kv[d4 * 4 + 1] = v.y;
        kv[d4 * 4 + 2] = v.z; kv[d4 * 4 + 3] = v.w;
    }
    int r0 = b * 24 + h * 6;
#pragma unroll
    for (int qi = 0; qi < 6; qi++) {
        float s = 0.f;
#pragma unroll
        for (int d = 0; d < 40; d++) s += sq[qi][d] * kv[d];
        att[(size_t)(r0 + qi) * NTOK + key] = s * 0.15811388300841897f;
    }
}

__global__ void k_xsoftmax(float* __restrict__ att) {
    extern __shared__ float srow[];
    int r = blockIdx.x, tid = threadIdx.x;
    float* row = att + (size_t)r * NTOK;
    float mx = -1e30f;
    for (int i = tid; i < NTOK; i += 256) {
        float v = row[i];
        srow[i] = v;
        mx = fmaxf(mx, v);
    }
    mx = blockReduceMax(mx);
    float s = 0.f;
    for (int i = tid; i < NTOK; i += 256) {
        float e = expf(srow[i] - mx);
        srow[i] = e;
        s += e;
    }
    s = blockReduceSum(s);
    float inv = 1.f / s;
    for (int i = tid; i < NTOK; i += 256) row[i] = srow[i] * inv;
}

// 16-segment weighted sum (128 blocks)
__global__ void k_xout6(const float* __restrict__ att, const float* __restrict__ v,
                        float* __restrict__ part) {
    int bh = blockIdx.x, seg = blockIdx.y;
    int b = bh >> 2, h = bh & 3;
    int r0 = b * 24 + h * 6;
    __shared__ float svv[64 * 40];
    __shared__ float sa[6 * 64];
    int tid = threadIdx.x;
    int qi = tid / 40, d = tid % 40;
    float acc = 0.f;
    int key0 = seg * 1024;
    for (int c = 0; c < 16; c++) {
        int kc = key0 + c * 64;
        for (int e = tid; e < 2560; e += 240) {
            int k = e / 40, dd = e % 40;
            svv[e] = v[((size_t)b * NTOK + kc + k) * INNERD + h * 40 + dd];
        }
        for (int e = tid; e < 384; e += 240)
            sa[e] = att[(size_t)(r0 + e / 64) * NTOK + kc + (e & 63)];
        __syncthreads();
#pragma unroll 8
        for (int k = 0; k < 64; k++) acc += sa[qi * 64 + k] * svv[k * 40 + d];
        __syncthreads();
    }
    part[((bh * 16 + seg) * 6 + qi) * 40 + d] = acc;
}

__global__ void k_xout_c6(const float* __restrict__ part, float* __restrict__ o) {
    int bh = blockIdx.x;
    int b = bh >> 2, h = bh & 3;
    int tid = threadIdx.x;
    int qi = tid / 40, d = tid % 40;
    float s = 0.f;
#pragma unroll
    for (int g = 0; g < 16; g++) s += part[((bh * 16 + g) * 6 + qi) * 40 + d];
    o[(b * 6 + qi) * INNERD + h * 40 + d] = s;
}

// i2t with smem-staged q slice (coalesced reads of tkiq)
__global__ void k_i2t(const float* __restrict__ qimg, const float* __restrict__ ks,
                      const float* __restrict__ vs,
                      bf16* __restrict__ ohi, bf16* __restrict__ olo) {
    __shared__ float sk[960], sv[960];
    __shared__ float s_q[32 * 160];
    int b = blockIdx.y;
    int tid = threadIdx.x;
    int tok0 = blockIdx.x * 32;
    for (int e = tid; e < 960; e += 128) { sk[e] = ks[b * 960 + e]; sv[e] = vs[b * 960 + e]; }
    // stage q: rows tok0..tok0+31, cols 160..319 of tkiq (coalesced)
    for (int e = tid; e < 32 * 160; e += 128) {
        int t = e / 160, j = e % 160;
        s_q[e] = qimg[((size_t)b * NTOK + tok0 + t) * 320 + 160 + j];
    }
    __syncthreads();
    int tok = tid >> 2;
    int h = tid & 3;
    const float* qrow = &s_q[tok * 160 + h * 40];
    float qv[40];
#pragma unroll
    for (int d = 0; d < 40; d++) qv[d] = qrow[d];
    float sc[6];
    float mx = -1e30f;
#pragma unroll
    for (int j = 0; j < 6; j++) {
        float s = 0.f;
#pragma unroll
        for (int d = 0; d < 40; d++) s += qv[d] * sk[j * INNERD + h * 40 + d];
        sc[j] = s * 0.15811388300841897f;
        mx = fmaxf(mx, sc[j]);
    }
    float sum = 0.f;
#pragma unroll
    for (int j = 0; j < 6; j++) { sc[j] = expf(sc[j] - mx); sum += sc[j]; }
    float inv = 1.f / sum;
    size_t rowo = ((size_t)b * NTOK + tok0 + tok) * 192;
#pragma unroll
    for (int d = 0; d < 40; d++) {
        float a = 0.f;
#pragma unroll
        for (int j = 0; j < 6; j++) a += sc[j] * sv[j * INNERD + h * 40 + d];
        a *= inv;
        bf16 hh, ll;
        split_bf16(a, hh, ll);
        ohi[rowo + h * 40 + d] = hh;
        olo[rowo + h * 40 + d] = ll;
    }
    if (h == 0) {
        bf16 z = __float2bfloat16(0.f);
#pragma unroll
        for (int d = 160; d < 192; d++) { ohi[rowo + d] = z; olo[rowo + d] = z; }
    }
}

extern "C" void kernel_launch(void* const* d_in, const int* in_sizes, int n_in,
                              void* d_out, int out_size) {
    const float* x        = (const float*)d_in[0];
    const float* coords   = (const float*)d_in[1];
    const int*   labels   = (const int*)  d_in[2];
    const float* ln_w     = (const float*)d_in[3];
    const float* ln_b     = (const float*)d_in[4];
    const float* in_w     = (const float*)d_in[5];
    const float* conv_w   = (const float*)d_in[6];
    const float* conv_b   = (const float*)d_in[7];
    const float* dt_bias  = (const float*)d_in[8];
    const float* A_log    = (const float*)d_in[9];
    const float* Dp       = (const float*)d_in[10];
    const float* rms_w    = (const float*)d_in[11];
    const float* out_w    = (const float*)d_in[12];
    const float* pe_gauss = (const float*)d_in[13];
    const float* point_tab= (const float*)d_in[14];
    const float* sa_w     = (const float*)d_in[15];
    const float* sa_b     = (const float*)d_in[16];
    const float* t2i_w    = (const float*)d_in[17];
    const float* t2i_b    = (const float*)d_in[18];
    const float* t2i_ow   = (const float*)d_in[19];
    const float* t2i_ob   = (const float*)d_in[20];
    const float* i2t_w    = (const float*)d_in[21];
    const float* i2t_b    = (const float*)d_in[22];
    const float* i2t_ow   = (const float*)d_in[23];
    const float* i2t_ob   = (const float*)d_in[24];
    const float* norms_w  = (const float*)d_in[25];
    const float* norms_b  = (const float*)d_in[26];
    const float* mlp_w1   = (const float*)d_in[27];
    const float* mlp_b1   = (const float*)d_in[28];
    const float* mlp_w2   = (const float*)d_in[29];
    const float* mlp_b2   = (const float*)d_in[30];
    float* out = (float*)d_out;

    const int SMEM_DYN = 2 * 4 * 128 * 40 * 2;  // 81920
    cudaFuncSetAttribute(k_mma, cudaFuncAttributeMaxDynamicSharedMemorySize, SMEM_DYN);
    const int SMEM_SOFT = NTOK * 4;  // 65536
    cudaFuncSetAttribute(k_xsoftmax, cudaFuncAttributeMaxDynamicSharedMemorySize, SMEM_SOFT);

    float* ar = nullptr;
    cudaGetSymbolAddress((void**)&ar, g_arena);

    float* zx     = ar + OFF_ZX;
    float* xbc    = ar + OFF_XBC;
    float* dtb    = ar + OFF_DTB;
    float* cum    = ar + OFF_CUM;
    float* csum   = ar + OFF_CSUM;
    float* sloc   = ar + OFF_SLOC;
    float* sbeg   = ar + OFF_SBEG;
    float* ybuf   = ar + OFF_Y;
    float* keys   = ar + OFF_KEYS;
    float* kpe    = ar + OFF_KPE;
    float* tkiq   = ar + OFF_TKIQ;
    float* tv     = ar + OFF_TV;
    float* att    = ar + OFF_ATT;
    float* queries= ar + OFF_Q;
    float* qpe    = ar + OFF_QPE;
    float* sq     = ar + OFF_SQ;
    float* sk     = ar + OFF_SK;
    float* sv     = ar + OFF_SV;
    float* so     = ar + OFF_SO;
    float* qs160  = ar + OFF_QS160;
    float* ks160  = ar + OFF_KS160;
    float* vs160  = ar + OFF_VS160;
    float* tatt   = ar + OFF_TATT;
    float* mlph   = ar + OFF_MLPH;
    float* xpart  = ar + OFF_XPART;
    float* bkq    = ar + OFF_BKQ;

    bf16* xnH  = (bf16*)(ar + OFF_XNH);
    bf16* xnL  = (bf16*)(ar + OFF_XNL);
    bf16* yH   = (bf16*)(ar + OFF_YH);
    bf16* yL   = (bf16*)(ar + OFF_YL);
    bf16* kH   = (bf16*)(ar + OFF_KH);
    bf16* kL   = (bf16*)(ar + OFF_KL);
    bf16* kpH  = (bf16*)(ar + OFF_KPH);
    bf16* kpL  = (bf16*)(ar + OFF_KPL);
    bf16* iaH  = (bf16*)(ar + OFF_IAH);
    bf16* iaL  = (bf16*)(ar + OFF_IAL);
    bf16* inwH = (bf16*)(ar + OFF_INWH);
    bf16* inwL = (bf16*)(ar + OFF_INWL);
    bf16* outwH= (bf16*)(ar + OFF_OUTWH);
    bf16* outwL= (bf16*)(ar + OFF_OUTWL);
    bf16* t2iv = (bf16*)(ar + OFF_T2IV);
    bf16* i2tow= (bf16*)(ar + OFF_I2TOW);
    bf16* wkq  = (bf16*)(ar + OFF_WKQ);

    const int MROWS = NBATCH * NTOK;

    k_tln<<<dim3(NTOK / 32, NBATCH), 256>>>(x, ln_w, ln_b, xnH, xnL);
    k_wsplit<<<1760, 256>>>(in_w, inwH, inwL, DIN, CDIM, 1408, 320);
    k_wsplit<<<960, 256>>>(out_w, outwH, outwL, CDIM, DINNER, 384, 640);
    k_mma<<<dim3(11, 256), 256, SMEM_DYN>>>(xnH, xnL, inwH, inwL, nullptr, nullptr,
                                            zx, nullptr, nullptr, nullptr, nullptr, nullptr,
                                            DIN, 320, 10);
    k_convdt8<<<MROWS / 8, 256>>>(zx, conv_w, conv_b, dt_bias, xbc, dtb);

    for (int i = 0; i < 2; i++) {
        k_wsplit_cat<<<480, 256>>>(t2i_w + (size_t)(i * 3 + 1) * INNERD * CDIM,
                                   i2t_w + (size_t)(i * 3 + 0) * INNERD * CDIM,
                                   wkq + i * 245760, wkq + i * 245760 + 122880);
        k_biascat<<<1, 384>>>(t2i_b + (i * 3 + 1) * INNERD, i2t_b + (i * 3 + 0) * INNERD,
                              bkq + i * 384);
        k_wsplit<<<320, 256>>>(t2i_w + (size_t)(i * 3 + 2) * INNERD * CDIM,
                               t2iv + i * 163840, t2iv + i * 163840 + 81920, INNERD, CDIM, 256, 320);
        k_wsplit<<<288, 256>>>(i2t_ow + (size_t)i * CDIM * INNERD,
                               i2tow + i * 147456, i2tow + i * 147456 + 73728, CDIM, INNERD, 384, 192);
    }
    k_kpe<<<NTOK, 160>>>(pe_gauss, kpe);
    k_pointemb<<<12, 160>>>(coords, labels, pe_gauss, point_tab, queries, qpe);

    k_cumsum<<<NBATCH * NH, NCHUNK>>>(dtb, A_log, cum, csum);
    k_chunkstate<<<NBATCH * NH * NCHUNK, 256>>>(xbc, cum, dtb, sloc);
    k_scan<<<dim3(NBATCH * NH, 10), 256>>>(sloc, csum, sbeg);
    k_chunkout<<<NBATCH * NH * NCHUNK, 256>>>(xbc, cum, dtb, sbeg, Dp, ybuf);
    k_gaterms<<<MROWS, DINNER>>>(ybuf, zx, rms_w, yH, yL);
    k_mma<<<dim3(3, 256), 256, SMEM_DYN>>>(yH, yL, outwH, outwL, nullptr, nullptr,
                                           keys, kH, kL, kpe, kpH, kpL, CDIM, 640, 20);

    for (int i = 0; i < 2; i++) {
        const float* swq = sa_w + (size_t)(i * 4 + 0) * CDIM * CDIM;
        const float* swk = sa_w + (size_t)(i * 4 + 1) * CDIM * CDIM;
        const float* swv = sa_w + (size_t)(i * 4 + 2) * CDIM * CDIM;
        const float* swo = sa_w + (size_t)(i * 4 + 3) * CDIM * CDIM;
        const float* sbq = sa_b + (i * 4 + 0) * CDIM;
        const float* sbk = sa_b + (i * 4 + 1) * CDIM;
        const float* sbv = sa_b + (i * 4 + 2) * CDIM;
        const float* sbo = sa_b + (i * 4 + 3) * CDIM;

        const float* pe_q = (i == 0) ? nullptr : qpe;
        k_tiny<<<dim3(5, 12), 64>>>(queries, pe_q, swq, sbq, nullptr, sq, CDIM, CDIM, 0);
        k_tiny<<<dim3(5, 12), 64>>>(queries, pe_q, swk, sbk, nullptr, sk, CDIM, CDIM, 0);
        k_tiny<<<dim3(5, 12), 64>>>(queries, nullptr, swv, sbv, nullptr, sv, CDIM, CDIM, 0);
        k_selfattn<<<8, 128>>>(sq, sk, sv, so);
        k_tiny<<<dim3(5, 12), 64>>>(so, nullptr, swo, sbo, (i == 0) ? nullptr : queries,
                                    queries, CDIM, CDIM, 0);
        k_ln<<<12, CDIM>>>(queries, queries, norms_w + (i * 4 + 0) * CDIM,
                           norms_b + (i * 4 + 0) * CDIM, nullptr, nullptr,
                           nullptr, nullptr, nullptr);

        k_tiny<<<dim3(3, 12), 64>>>(queries, qpe, t2i_w + (size_t)(i * 3 + 0) * INNERD * CDIM,
                                    t2i_b + (i * 3 + 0) * INNERD, nullptr, qs160, INNERD, CDIM, 0);
        k_mma<<<dim3(3, 256), 256, SMEM_DYN>>>(kpH, kpL, wkq + i * 245760, wkq + i * 245760 + 122880,
                                               bkq + i * 384, nullptr,
                                               tkiq, nullptr, nullptr, nullptr, nullptr, nullptr,
                                               320, 320, 10);
        k_mma<<<dim3(2, 256), 256, SMEM_DYN>>>(kH, kL, t2iv + i * 163840, t2iv + i * 163840 + 81920,
                                               t2i_b + (i * 3 + 2) * INNERD, nullptr,
                                               tv, nullptr, nullptr, nullptr, nullptr, nullptr,
                                               INNERD, 320, 10);
        k_xscore6<<<dim3(8, 64), 256>>>(qs160, tkiq, att, 320);
        k_xsoftmax<<<48, 256, SMEM_SOFT>>>(att);
        k_xout6<<<dim3(8, 16), 240>>>(att, tv, xpart);
        k_xout_c6<<<8, 240>>>(xpart, tatt);
        k_tiny<<<dim3(5, 12), 64>>>(tatt, nullptr, t2i_ow + (size_t)i * CDIM * INNERD,
                                    t2i_ob + i * CDIM, queries, queries, CDIM, INNERD, 0);
        k_ln<<<12, CDIM>>>(queries, queries, norms_w + (i * 4 + 1) * CDIM,
                           norms_b + (i * 4 + 1) * CDIM, nullptr, nullptr,
                           nullptr, nullptr, nullptr);

        k_tiny<<<dim3(16, 12), 64>>>(queries, nullptr, mlp_w1 + (size_t)i * MLPD * CDIM,
                                     mlp_b1 + i * MLPD, nullptr, mlph, MLPD, CDIM, 1);
        k_tiny<<<dim3(5, 12), 64>>>(mlph, nullptr, mlp_w2 + (size_t)i * CDIM * MLPD,
                                    mlp_b2 + i * CDIM, queries, queries, CDIM, MLPD, 0);
        k_ln<<<12, CDIM>>>(queries, queries, norms_w + (i * 4 + 2) * CDIM,
                           norms_b + (i * 4 + 2) * CDIM, nullptr, nullptr,
                           nullptr, nullptr, nullptr);

        k_tiny<<<dim3(3, 12), 64>>>(queries, qpe, i2t_w + (size_t)(i * 3 + 1) * INNERD * CDIM,
                                    i2t_b + (i * 3 + 1) * INNERD, nullptr, ks160, INNERD, CDIM, 0);
        k_tiny<<<dim3(3, 12), 64>>>(queries, nullptr, i2t_w + (size_t)(i * 3 + 2) * INNERD * CDIM,
                                    i2t_b + (i * 3 + 2) * INNERD, nullptr, vs160, INNERD, CDIM, 0);
        k_i2t<<<dim3(NTOK / 32, NBATCH), 128>>>(tkiq, ks160, vs160, iaH, iaL);
        k_mma<<<dim3(3, 256), 256, SMEM_DYN>>>(iaH, iaL, i2tow + i * 147456, i2tow + i * 147456 + 73728,
                                               i2t_ob + i * CDIM, keys,
                                               keys, nullptr, nullptr, nullptr, nullptr, nullptr,
                                               CDIM, 192, 6);
        if (i == 0) {
            k_ln<<<MROWS, CDIM>>>(keys, keys, norms_w + (i * 4 + 3) * CDIM,
                                  norms_b + (i * 4 + 3) * CDIM, kH, kL,
                                  kpe, kpH, kpL);
        } else {
            k_ln<<<MROWS, CDIM>>>(keys, keys, norms_w + (i * 4 + 3) * CDIM,
                                  norms_b + (i * 4 + 3) * CDIM, nullptr, nullptr,
                                  nullptr, nullptr, nullptr);
        }
    }

    k_transpose_out<<<dim3(NTOK / 32, CDIM / 32, NBATCH), dim3(32, 8)>>>(keys, out);
}

// round 15
// speedup vs baseline: 1.2028x; 1.0848x over previous
#include <cuda_runtime.h>
#include <cuda_bf16.h>
#include <math.h>
#include <stdint.h>

#define NBATCH 2
#define CDIM 320
#define NTOK 16384
#define DIN 1352
#define DINNER 640
#define CONVD 704
#define DSTATE 32
#define NH 8
#define HP 80
#define NCHUNK 256
#define INNERD 160
#define MLPD 1024

typedef __nv_bfloat16 bf16;

constexpr size_t SZ_XF   = (size_t)NBATCH*NTOK*CDIM;
constexpr size_t SZ_ZX   = (size_t)NBATCH*NTOK*DIN;
constexpr size_t SZ_XBC  = (size_t)NBATCH*NTOK*CONVD;
constexpr size_t SZ_DTB  = (size_t)NBATCH*NH*NTOK;
constexpr size_t SZ_SL   = (size_t)NBATCH*NH*NCHUNK*DSTATE*HP;
constexpr size_t SZ_Y    = (size_t)NBATCH*NTOK*DINNER;
constexpr size_t SZ_KPE  = (size_t)NTOK*CDIM;
constexpr size_t SZ_I160 = (size_t)NBATCH*NTOK*INNERD;
constexpr size_t SZ_ATT  = (size_t)48*NTOK;

constexpr size_t OFF_XF    = 0;
constexpr size_t OFF_ZX    = OFF_XF    + SZ_XF;
constexpr size_t OFF_XBC   = OFF_ZX    + SZ_ZX;
constexpr size_t OFF_DTB   = OFF_XBC   + SZ_XBC;
constexpr size_t OFF_CUM   = OFF_DTB   + SZ_DTB;
constexpr size_t OFF_CSUM  = OFF_CUM   + SZ_DTB;
constexpr size_t OFF_SLOC  = OFF_CSUM  + (size_t)NBATCH*NH*NCHUNK;
constexpr size_t OFF_SBEG  = OFF_SLOC  + SZ_SL;
constexpr size_t OFF_Y     = OFF_SBEG  + SZ_SL;
constexpr size_t OFF_KEYS  = OFF_Y     + SZ_Y;
constexpr size_t OFF_KPE   = OFF_KEYS  + SZ_XF;
constexpr size_t OFF_TKIQ  = OFF_KPE   + SZ_KPE;
constexpr size_t OFF_TV    = OFF_TKIQ  + 2 * SZ_I160;
constexpr size_t OFF_ATT   = OFF_TV    + SZ_I160;
constexpr size_t OFF_Q     = OFF_ATT   + SZ_ATT;
constexpr size_t OFF_QPE   = OFF_Q     + 3840;
constexpr size_t OFF_SQ    = OFF_QPE   + 3840;
constexpr size_t OFF_SK    = OFF_SQ    + 3840;
constexpr size_t OFF_SV    = OFF_SK    + 3840;
constexpr size_t OFF_SO    = OFF_SV    + 3840;
constexpr size_t OFF_QS160 = OFF_SO    + 3840;
constexpr size_t OFF_KS160 = OFF_QS160 + 1920;
constexpr size_t OFF_VS160 = OFF_KS160 + 1920;
constexpr size_t OFF_TATT  = OFF_VS160 + 1920;
constexpr size_t OFF_MLPH  = OFF_TATT  + 1920;
constexpr size_t OFF_XNH   = OFF_MLPH + 12288;
constexpr size_t OFF_XNL   = OFF_XNH + 5242880;
constexpr size_t OFF_YH    = OFF_XNL + 5242880;
constexpr size_t OFF_YL    = OFF_YH  + 10485760;
constexpr size_t OFF_KH    = OFF_YL  + 10485760;
constexpr size_t OFF_KL    = OFF_KH  + 5242880;
constexpr size_t OFF_KPH   = OFF_KL  + 5242880;
constexpr size_t OFF_KPL   = OFF_KPH + 5242880;
constexpr size_t OFF_IAH   = OFF_KPL + 5242880;
constexpr size_t OFF_IAL   = OFF_IAH + 3145728;
constexpr size_t OFF_INWH  = OFF_IAL + 3145728;
constexpr size_t OFF_INWL  = OFF_INWH + 225280;
constexpr size_t OFF_OUTWH = OFF_INWL + 225280;
constexpr size_t OFF_OUTWL = OFF_OUTWH + 122880;
constexpr size_t OFF_T2IV  = OFF_OUTWL + 122880;
constexpr size_t OFF_I2TOW = OFF_T2IV + 163840;
constexpr size_t OFF_XPART = OFF_I2TOW + 147456;
constexpr size_t OFF_WKQ   = OFF_XPART + 30720;
constexpr size_t OFF_BKQ   = OFF_WKQ + 245760;
constexpr size_t ARENA_FLOATS = OFF_BKQ + 768;

__device__ __align__(128) float g_arena[ARENA_FLOATS];

__device__ __forceinline__ uint32_t smem_u32(const void* p) {
    uint32_t a;
    asm("{ .reg .u64 t; cvta.to.shared.u64 t, %1; cvt.u32.u64 %0, t; }" : "=r"(a) : "l"(p));
    return a;
}
__device__ __forceinline__ void ldm_x4(uint32_t* r, uint32_t a) {
    asm volatile("ldmatrix.sync.aligned.m8n8.x4.shared.b16 {%0,%1,%2,%3}, [%4];"
        : "=r"(r[0]), "=r"(r[1]), "=r"(r[2]), "=r"(r[3]) : "r"(a));
}
__device__ __forceinline__ void mma16816(float* c, const uint32_t* a, const uint32_t* b) {
    asm volatile("mma.sync.aligned.m16n8k16.row.col.f32.bf16.bf16.f32 "
        "{%0,%1,%2,%3}, {%4,%5,%6,%7}, {%8,%9}, {%0,%1,%2,%3};"
        : "+f"(c[0]), "+f"(c[1]), "+f"(c[2]), "+f"(c[3])
        : "r"(a[0]), "r"(a[1]), "r"(a[2]), "r"(a[3]), "r"(b[0]), "r"(b[1]));
}
__device__ __forceinline__ void cpasync16(uint32_t dst, const void* src) {
    asm volatile("cp.async.cg.shared.global [%0], [%1], 16;" :: "r"(dst), "l"(src));
}
__device__ __forceinline__ void split_bf16(float v, bf16& h, bf16& l) {
    h = __float2bfloat16(v);
    l = __float2bfloat16(v - __bfloat162float(h));
}

__device__ __forceinline__ float blockReduceSum(float v) {
    __shared__ float sh[33];
    int lane = threadIdx.x & 31, wid = threadIdx.x >> 5;
#pragma unroll
    for (int o = 16; o; o >>= 1) v += __shfl_down_sync(0xffffffffu, v, o);
    if (lane == 0) sh[wid] = v;
    __syncthreads();
    int nw = (blockDim.x + 31) >> 5;
    if (wid == 0) {
        v = (lane < nw) ? sh[lane] : 0.f;
#pragma unroll
        for (int o = 16; o; o >>= 1) v += __shfl_down_sync(0xffffffffu, v, o);
        if (lane == 0) sh[32] = v;
    }
    __syncthreads();
    v = sh[32];
    __syncthreads();
    return v;
}
__device__ __forceinline__ float2 blockReduceSum2(float a, float b) {
    __shared__ float sh[66];
    int lane = threadIdx.x & 31, wid = threadIdx.x >> 5;
#pragma unroll
    for (int o = 16; o; o >>= 1) {
        a += __shfl_down_sync(0xffffffffu, a, o);
        b += __shfl_down_sync(0xffffffffu, b, o);
    }
    if (lane == 0) { sh[wid * 2] = a; sh[wid * 2 + 1] = b; }
    __syncthreads();
    int nw = (blockDim.x + 31) >> 5;
    if (wid == 0) {
        a = (lane < nw) ? sh[lane * 2] : 0.f;
        b = (lane < nw) ? sh[lane * 2 + 1] : 0.f;
#pragma unroll
        for (int o = 16; o; o >>= 1) {
            a += __shfl_down_sync(0xffffffffu, a, o);
            b += __shfl_down_sync(0xffffffffu, b, o);
        }
        if (lane == 0) { sh[64] = a; sh[65] = b; }
    }
    __syncthreads();
    float2 r = make_float2(sh[64], sh[65]);
    __syncthreads();
    return r;
}
__device__ __forceinline__ float blockReduceMax(float v) {
    __shared__ float sh[33];
    int lane = threadIdx.x & 31, wid = threadIdx.x >> 5;
#pragma unroll
    for (int o = 16; o; o >>= 1) v = fmaxf(v, __shfl_down_sync(0xffffffffu, v, o));
    if (lane == 0) sh[wid] = v;
    __syncthreads();
    int nw = (blockDim.x + 31) >> 5;
    if (wid == 0) {
        v = (lane < nw) ? sh[lane] : -1e30f;
#pragma unroll
        for (int o = 16; o; o >>= 1) v = fmaxf(v, __shfl_down_sync(0xffffffffu, v, o));
        if (lane == 0) sh[32] = v;
    }
    __syncthreads();
    v = sh[32];
    __syncthreads();
    return v;
}
__device__ __forceinline__ float siluf(float x) { return x / (1.f + expf(-x)); }

// ---- tensor-core split GEMM (stable since R9) ----
__global__ void __launch_bounds__(256, 2)
k_mma(const bf16* __restrict__ aH, const bf16* __restrict__ aL,
      const bf16* __restrict__ wH, const bf16* __restrict__ wL,
      const float* __restrict__ bias, const float* __restrict__ R,
      float* __restrict__ C, bf16* __restrict__ cH, bf16* __restrict__ cL,
      const float* __restrict__ pe, bf16* __restrict__ peH, bf16* __restrict__ peL,
      int Nact, int Kd, int nkb) {
    extern __shared__ bf16 sm[];
    constexpr int TSZ = 128 * 40;
    const int tid = threadIdx.x;
    const int wid = tid >> 5, lane = tid & 31;
    const int wm = wid & 1, wn = wid >> 1;
    const int m0 = blockIdx.y * 128, n0 = blockIdx.x * 128;

    const bf16* srcs[4] = { aH + (size_t)m0 * Kd, aL + (size_t)m0 * Kd,
                            wH + (size_t)n0 * Kd, wL + (size_t)n0 * Kd };
    const int lrow = tid >> 2, lc8 = (tid & 3) * 8;

    auto prefetch = [&](int kb, int buf) {
#pragma unroll
        for (int q = 0; q < 4; q++) {
            bf16* t = sm + buf * 4 * TSZ + q * TSZ;
#pragma unroll
            for (int l = 0; l < 2; l++) {
                int row = lrow + l * 64;
                cpasync16(smem_u32(t + row * 40 + lc8),
                          srcs[q] + (size_t)row * Kd + kb * 32 + lc8);
            }
        }
        asm volatile("cp.async.commit_group;");
    };

    float acc[4][4][4];
#pragma unroll
    for (int i = 0; i < 4; i++)
#pragma unroll
        for (int j = 0; j < 4; j++)
#pragma unroll
            for (int r = 0; r < 4; r++) acc[i][j][r] = 0.f;

    prefetch(0, 0);
    if (nkb > 1) prefetch(1, 1);

    const int arow = wm * 64 + (((lane >> 3) & 1) << 3) + (lane & 7);
    const int acol = ((lane >> 4) << 3);
    const int brow = wn * 32 + ((lane >> 4) << 3) + (lane & 7);
    const int bcol = (((lane >> 3) & 1) << 3);

    for (int kb = 0; kb < nkb; kb++) {
        if (kb + 1 < nkb) asm volatile("cp.async.wait_group 1;");
        else              asm volatile("cp.async.wait_group 0;");
        __syncthreads();
        const int buf = kb & 1;
        const bf16* tAH = sm + buf * 4 * TSZ;
        const bf16* tAL = tAH + TSZ;
        const bf16* tWH = tAH + 2 * TSZ;
        const bf16* tWL = tAH + 3 * TSZ;
#pragma unroll
        for (int ks = 0; ks < 2; ks++) {
            uint32_t aHf[4][4], aLf[4][4];
#pragma unroll
            for (int mi = 0; mi < 4; mi++) {
                int off = (arow + mi * 16) * 40 + ks * 16 + acol;
                ldm_x4(aHf[mi], smem_u32(tAH + off));
                ldm_x4(aLf[mi], smem_u32(tAL + off));
            }
#pragma unroll
            for (int nfp = 0; nfp < 2; nfp++) {
                uint32_t bHf[4], bLf[4];
                int off = (brow + nfp * 16) * 40 + ks * 16 + bcol;
                ldm_x4(bHf, smem_u32(tWH + off));
                ldm_x4(bLf, smem_u32(tWL + off));
#pragma unroll
                for (int mi = 0; mi < 4; mi++) {
                    mma16816(acc[mi][nfp * 2 + 0], aHf[mi], bHf);
                    mma16816(acc[mi][nfp * 2 + 1], aHf[mi], bHf + 2);
                }
#pragma unroll
                for (int mi = 0; mi < 4; mi++) {
                    mma16816(acc[mi][nfp * 2 + 0], aHf[mi], bLf);
                    mma16816(acc[mi][nfp * 2 + 1], aHf[mi], bLf + 2);
                }
#pragma unroll
                for (int mi = 0; mi < 4; mi++) {
                    mma16816(acc[mi][nfp * 2 + 0], aLf[mi], bHf);
                    mma16816(acc[mi][nfp * 2 + 1], aLf[mi], bHf + 2);
                }
            }
        }
        __syncthreads();
        if (kb + 2 < nkb) prefetch(kb + 2, buf);
    }

    const int qr = lane >> 2, qc = (lane & 3) * 2;
#pragma unroll
    for (int mi = 0; mi < 4; mi++)
#pragma unroll
        for (int nf = 0; nf < 4; nf++) {
            int n = n0 + wn * 32 + nf * 8 + qc;
            if (n >= Nact) continue;
#pragma unroll
            for (int h = 0; h < 2; h++) {
                int m = m0 + wm * 64 + mi * 16 + qr + h * 8;
                float v0 = acc[mi][nf][h * 2 + 0];
                float v1 = acc[mi][nf][h * 2 + 1];
                if (bias) { v0 += bias[n]; v1 += bias[n + 1]; }
                size_t o = (size_t)m * Nact + n;
                if (R) { v0 += R[o]; v1 += R[o + 1]; }
                C[o] = v0; C[o + 1] = v1;
                bf16 hh, ll;
                if (cH) {
                    split_bf16(v0, hh, ll); cH[o] = hh;     cL[o] = ll;
                    split_bf16(v1, hh, ll); cH[o + 1] = hh; cL[o + 1] = ll;
                }
                if (peH) {
                    size_t pi = (size_t)(m & (NTOK - 1)) * Nact + n;
                    split_bf16(v0 + pe[pi], hh, ll);     peH[o] = hh;     peL[o] = ll;
                    split_bf16(v1 + pe[pi + 1], hh, ll); peH[o + 1] = hh; peL[o + 1] = ll;
                }
            }
        }
}

__global__ void k_wsplit(const float* __restrict__ W, bf16* __restrict__ hi,
                         bf16* __restrict__ lo, int N, int K, int Npad, int Kpad) {
    int idx = blockIdx.x * 256 + threadIdx.x;
    if (idx >= Npad * Kpad) return;
    int n = idx / Kpad, k = idx % Kpad;
    float v = (n < N && k < K) ? W[(size_t)n * K + k] : 0.f;
    bf16 h, l;
    split_bf16(v, h, l);
    hi[idx] = h; lo[idx] = l;
}

__global__ void k_wsplit_cat(const float* __restrict__ W1, const float* __restrict__ W2,
                             bf16* __restrict__ hi, bf16* __restrict__ lo) {
    int idx = blockIdx.x * 256 + threadIdx.x;
    if (idx >= 384 * 320) return;
    int n = idx / 320, k = idx % 320;
    float v = 0.f;
    if (n < 160) v = W1[(size_t)n * 320 + k];
    else if (n < 320) v = W2[(size_t)(n - 160) * 320 + k];
    bf16 h, l;
    split_bf16(v, h, l);
    hi[idx] = h; lo[idx] = l;
}

__global__ void k_biascat(const float* __restrict__ b1, const float* __restrict__ b2,
                          float* __restrict__ dst) {
    int n = threadIdx.x;
    dst[n] = (n < 160) ? b1[n] : ((n < 320) ? b2[n - 160] : 0.f);
}

__global__ void k_tln(const float* __restrict__ x, const float* __restrict__ w,
                      const float* __restrict__ b, bf16* __restrict__ hi,
                      bf16* __restrict__ lo) {
    __shared__ float tile[320 * 33];
    __shared__ float mu[32], rs[32];
    int bq = blockIdx.y;
    int t0 = blockIdx.x * 32;
    int tid = threadIdx.x;
    for (int e = tid; e < 320 * 32; e += 256) {
        int c = e >> 5, tok = e & 31;
        tile[c * 33 + tok] = x[((size_t)(bq * CDIM + c)) * NTOK + t0 + tok];
    }
    __syncthreads();
    int wid = tid >> 5, lane = tid & 31;
#pragma unroll
    for (int k = 0; k < 4; k++) {
        int tok = wid * 4 + k;
        float s = 0.f, v = 0.f;
        for (int c = lane; c < 320; c += 32) {
            float t = tile[c * 33 + tok];
            s += t; v += t * t;
        }
#pragma unroll
        for (int o = 16; o; o >>= 1) {
            s += __shfl_down_sync(0xffffffffu, s, o);
            v += __shfl_down_sync(0xffffffffu, v, o);
        }
        if (lane == 0) {
            float m = s / 320.f;
            mu[tok] = m;
            rs[tok] = rsqrtf(v / 320.f - m * m + 1e-5f);
        }
    }
    __syncthreads();
    for (int e = tid; e < 10240; e += 256) {
        int tok = e / 320, c = e % 320;
        float r = (tile[c * 33 + tok] - mu[tok]) * rs[tok] * w[c] + b[c];
        size_t o = ((size_t)(bq * NTOK + t0 + tok)) * 320 + c;
        bf16 h, l;
        split_bf16(r, h, l);
        hi[o] = h; lo[o] = l;
    }
}

__global__ void k_transpose_out(const float* __restrict__ keys, float* __restrict__ out) {
    __shared__ float tile[32][33];
    int b = blockIdx.z;
    int t0 = blockIdx.x * 32, c0 = blockIdx.y * 32;
#pragma unroll
    for (int i = 0; i < 4; i++) {
        int tt = threadIdx.y + i * 8;
        tile[threadIdx.x][tt] = keys[((size_t)(b * NTOK + t0 + tt)) * CDIM + c0 + threadIdx.x];
    }
    __syncthreads();
#pragma unroll
    for (int i = 0; i < 4; i++) {
        int cc = threadIdx.y + i * 8;
        out[((size_t)(b * CDIM + c0 + cc)) * NTOK + t0 + threadIdx.x] = tile[cc][threadIdx.x];
    }
}

// 12-row query LN (unchanged)
__global__ void k_ln(const float* __restrict__ src, float* __restrict__ dst,
                     const float* __restrict__ w, const float* __restrict__ b,
                     bf16* __restrict__ hi, bf16* __restrict__ lo,
                     const float* __restrict__ pe, bf16* __restrict__ peH,
                     bf16* __restrict__ peL) {
    int row = blockIdx.x;
    int D = blockDim.x;
    float v = src[(size_t)row * D + threadIdx.x];
    float2 sv = blockReduceSum2(v, v * v);
    float m = sv.x / D;
    float var = sv.y / D - m * m;
    float r = (v - m) * rsqrtf(var + 1e-5f) * w[threadIdx.x] + b[threadIdx.x];
    size_t o = (size_t)row * D + threadIdx.x;
    if (dst) dst[o] = r;
    bf16 h, l;
    if (hi) { split_bf16(r, h, l); hi[o] = h; lo[o] = l; }
    if (peH) {
        float pv = r + pe[(size_t)(row & (NTOK - 1)) * D + threadIdx.x];
        split_bf16(pv, h, l);
        peH[o] = h; peL[o] = l;
    }
}

// warp-per-row LN for 32768-row tensors (no block barriers)
__global__ void k_lnw(const float* __restrict__ src, float* __restrict__ dst,
                      const float* __restrict__ w, const float* __restrict__ b,
                      bf16* __restrict__ hi, bf16* __restrict__ lo,
                      const float* __restrict__ pe, bf16* __restrict__ peH,
                      bf16* __restrict__ peL) {
    int row = blockIdx.x * 4 + (threadIdx.x >> 5);
    int lane = threadIdx.x & 31;
    const float* s = src + (size_t)row * CDIM;
    float v[10];
    float sum = 0.f, sq = 0.f;
#pragma unroll
    for (int j = 0; j < 10; j++) {
        v[j] = s[lane + j * 32];
        sum += v[j]; sq += v[j] * v[j];
    }
#pragma unroll
    for (int o = 16; o; o >>= 1) {
        sum += __shfl_down_sync(0xffffffffu, sum, o);
        sq  += __shfl_down_sync(0xffffffffu, sq, o);
    }
    sum = __shfl_sync(0xffffffffu, sum, 0);
    sq  = __shfl_sync(0xffffffffu, sq, 0);
    float m = sum / 320.f;
    float rs = rsqrtf(sq / 320.f - m * m + 1e-5f);
    size_t o0 = (size_t)row * CDIM;
#pragma unroll
    for (int j = 0; j < 10; j++) {
        int c = lane + j * 32;
        float r = (v[j] - m) * rs * w[c] + b[c];
        if (dst) dst[o0 + c] = r;
        bf16 h, l;
        if (hi) { split_bf16(r, h, l); hi[o0 + c] = h; lo[o0 + c] = l; }
        if (peH) {
            float pv = r + pe[(size_t)(row & (NTOK - 1)) * CDIM + c];
            split_bf16(pv, h, l);
            peH[o0 + c] = h; peL[o0 + c] = l;
        }
    }
}

__global__ void k_tiny(const float* __restrict__ A1, const float* __restrict__ A2,
                       const float* __restrict__ W, const float* __restrict__ bias,
                       const float* __restrict__ R, float* __restrict__ C,
                       int N, int K, int act) {
    int r = blockIdx.y;
    int n = blockIdx.x * 64 + threadIdx.x;
    if (n >= N) return;
    const float* a1 = A1 + (size_t)r * K;
    const float* a2 = A2 ? A2 + (size_t)r * K : nullptr;
    const float* w = W + (size_t)n * K;
    float acc = bias ? bias[n] : 0.f;
    if (a2) { for (int k = 0; k < K; k++) acc += (a1[k] + a2[k]) * w[k]; }
    else    { for (int k = 0; k < K; k++) acc += a1[k] * w[k]; }
    if (act == 1) acc = fmaxf(acc, 0.f);
    if (R) acc += R[(size_t)r * N + n];
    C[(size_t)r * N + n] = acc;
}

// segment-mapped fused tiny GEMM (contiguous weight blocks -> separate output buffers)
// A2 added only for n < a2limit. Output at C[seg*segStride + r*segN + n%segN].
__global__ void k_tiny_seg(const float* __restrict__ A1, const float* __restrict__ A2,
                           const float* __restrict__ W, const float* __restrict__ bias,
                           float* __restrict__ C, int Ntot, int K,
                           int segN, int segStride, int a2limit) {
    int r = blockIdx.y;
    int n = blockIdx.x * 64 + threadIdx.x;
    if (n >= Ntot) return;
    const float* a1 = A1 + (size_t)r * K;
    const float* w = W + (size_t)n * K;
    float acc = bias ? bias[n] : 0.f;
    if (A2 && n < a2limit) {
        const float* a2 = A2 + (size_t)r * K;
        for (int k = 0; k < K; k++) acc += (a1[k] + a2[k]) * w[k];
    } else {
        for (int k = 0; k < K; k++) acc += a1[k] * w[k];
    }
    int seg = n / segN, nn = n - seg * segN;
    C[(size_t)seg * segStride + (size_t)r * segN + nn] = acc;
}

__global__ void k_convdt8(const float* __restrict__ zx, const float* __restrict__ conv_w,
                          const float* __restrict__ conv_b, const float* __restrict__ dt_bias,
                          float* __restrict__ xbc, float* __restrict__ dtb) {
    __shared__ float sxr[11][CONVD];
    int blk = blockIdx.x;
    int b = blk >> 11;
    int t0 = (blk & 2047) * 8;
    int tid = threadIdx.x;
#pragma unroll
    for (int r = 0; r < 11; r++) {
        int ts = t0 + r - 3;
        const float* src = zx + ((size_t)(b * NTOK + ts)) * DIN + DINNER;
        for (int c = tid; c < CONVD; c += 256)
            sxr[r][c] = (ts >= 0) ? src[c] : 0.f;
    }
    __syncthreads();
    for (int c = tid; c < CONVD; c += 256) {
        float w0 = conv_w[c * 4], w1 = conv_w[c * 4 + 1];
        float w2 = conv_w[c * 4 + 2], w3 = conv_w[c * 4 + 3];
        float cb = conv_b[c];
#pragma unroll
        for (int q = 0; q < 8; q++) {
            float acc = cb + sxr[q][c] * w0 + sxr[q + 1][c] * w1
                      + sxr[q + 2][c] * w2 + sxr[q + 3][c] * w3;
            xbc[((size_t)(b * NTOK + t0 + q)) * CONVD + c] = siluf(acc);
        }
    }
    if (tid < 64) {
        int q = tid >> 3, h = tid & 7;
        float xv = zx[((size_t)(b * NTOK + t0 + q)) * DIN + DINNER + CONVD + h] + dt_bias[h];
        float dt = (xv > 20.f) ? xv : log1pf(expf(xv));
        dtb[(((size_t)(b * NH + h)) << 14) + t0 + q] = dt;
    }
}

__global__ void k_cumsum(const float* __restrict__ dtb, const float* __restrict__ A_log,
                         float* __restrict__ cum, float* __restrict__ csum) {
    int bh = blockIdx.x;
    int h = bh & 7;
    float A = -expf(A_log[h]);
    int c = threadIdx.x;
    size_t base = ((size_t)bh << 14) + (size_t)c * 64;
    float run = 0.f;
    for (int t = 0; t < 64; t++) {
        run += dtb[base + t] * A;
        cum[base + t] = run;
    }
    csum[bh * NCHUNK + c] = run;
}

__global__ void k_chunkstate(const float* __restrict__ xbc, const float* __restrict__ cum,
                             const float* __restrict__ dtb, float* __restrict__ sloc) {
    int idx = blockIdx.x;
    int c = idx & 255, bh = idx >> 8;
    int b = bh >> 3, h = bh & 7;
    __shared__ float sB[64 * 32];
    __shared__ float sx[64 * 80];
    __shared__ float coef[64];
    int tid = threadIdx.x;
    size_t tbase = (size_t)b * NTOK + (size_t)c * 64;
    for (int e = tid; e < 64 * 32; e += 256) {
        int t = e >> 5, n = e & 31;
        sB[e] = xbc[(tbase + t) * CONVD + DINNER + n];
    }
    for (int e = tid; e < 64 * 80; e += 256) {
        int t = e / 80, p = e % 80;
        sx[e] = xbc[(tbase + t) * CONVD + h * HP + p];
    }
    if (tid < 64) {
        size_t cb = ((size_t)bh << 14) + (size_t)c * 64;
        float cl = cum[cb + 63];
        coef[tid] = expf(cl - cum[cb + tid]) * dtb[cb + tid];
    }
    __syncthreads();
    int n = tid >> 3, p0 = (tid & 7) * 10;
    float2 a2[5] = {};
    for (int t = 0; t < 64; t++) {
        float bc = coef[t] * sB[t * 32 + n];
        const float2* xr = (const float2*)&sx[t * 80 + p0];
#pragma unroll
        for (int j = 0; j < 5; j++) {
            float2 xv = xr[j];
            a2[j].x += bc * xv.x;
            a2[j].y += bc * xv.y;
        }
    }
    float2* so = (float2*)&sloc[((size_t)bh * NCHUNK + c) * 2560 + n * 80 + p0];
#pragma unroll
    for (int j = 0; j < 5; j++) so[j] = a2[j];
}

__global__ void k_scan(const float* __restrict__ sloc, const float* __restrict__ csum,
                       float* __restrict__ sbeg) {
    __shared__ float sdec[256];
    int bh = blockIdx.x;
    int e = blockIdx.y * 256 + threadIdx.x;
    sdec[threadIdx.x] = expf(csum[bh * NCHUNK + threadIdx.x]);
    __syncthreads();
    float S = 0.f;
    size_t base = (size_t)bh * NCHUNK * 2560 + e;
    for (int c = 0; c < NCHUNK; c += 4) {
        size_t b0 = base + (size_t)c * 2560;
        float x0 = sloc[b0];
        float x1 = sloc[b0 + 2560];
        float x2 = sloc[b0 + 5120];
        float x3 = sloc[b0 + 7680];
        sbeg[b0] = S;        S = S * sdec[c]     + x0;
        sbeg[b0 + 2560] = S; S = S * sdec[c + 1] + x1;
        sbeg[b0 + 5120] = S; S = S * sdec[c + 2] + x2;
        sbeg[b0 + 7680] = S; S = S * sdec[c + 3] + x3;
    }
}

__global__ void k_chunkout(const float* __restrict__ xbc, const float* __restrict__ cum,
                           const float* __restrict__ dtb, const float* __restrict__ sbeg,
                           const float* __restrict__ Dp, float* __restrict__ y) {
    int idx = blockIdx.x;
    int c = idx & 255, bh = idx >> 8;
    int b = bh >> 3, h = bh & 7;
    __shared__ float sM[64 * 65];
    __shared__ float sC[64 * 33];
    __shared__ float sR[5120];
    __shared__ float sCum[64];
    __shared__ float sDt[64];
    int tid = threadIdx.x;
    size_t tbase = (size_t)b * NTOK + (size_t)c * 64;
    size_t cb = ((size_t)bh << 14) + (size_t)c * 64;
    size_t sb_base = ((size_t)bh * NCHUNK + c) * 2560;
    for (int e = tid; e < 2048; e += 256) {
        int t = e >> 5, n = e & 31;
        sC[t * 33 + n] = xbc[(tbase + t) * CONVD + DINNER + DSTATE + n];
    }
    for (int e = tid; e < 2560; e += 256) sR[e] = sbeg[sb_base + e];
    if (tid < 64) { sCum[tid] = cum[cb + tid]; sDt[tid] = dtb[cb + tid]; }
    __syncthreads();
    int t = tid >> 2, p0 = (tid & 3) * 20;
    float4 a4[5] = {};
    for (int n = 0; n < 32; n++) {
        float cv = sC[t * 33 + n];
        const float4* rr = (const float4*)&sR[n * 80 + p0];
#pragma unroll
        for (int j = 0; j < 5; j++) {
            float4 rv = rr[j];
            a4[j].x += cv * rv.x; a4[j].y += cv * rv.y;
            a4[j].z += cv * rv.z; a4[j].w += cv * rv.w;
        }
    }
    float et = expf(sCum[t]);
#pragma unroll
    for (int j = 0; j < 5; j++) {
        a4[j].x *= et; a4[j].y *= et; a4[j].z *= et; a4[j].w *= et;
    }
    __syncthreads();
    for (int e = tid; e < 2048; e += 256) {
        int s = e >> 5, n = e & 31;
        sR[s * 33 + n] = xbc[(tbase + s) * CONVD + DINNER + n];
    }
    __syncthreads();
    for (int e = tid; e < 4096; e += 256) {
        int tt = e >> 6, s = e & 63;
        float m = 0.f;
        if (s <= tt) {
            float d = 0.f;
#pragma unroll 8
            for (int n = 0; n < 32; n++) d += sC[tt * 33 + n] * sR[s * 33 + n];
            m = d * expf(sCum[tt] - sCum[s]) * sDt[s];
        }
        sM[tt * 65 + s] = m;
    }
    __syncthreads();
    for (int e = tid; e < 5120; e += 256) {
        int s = e / 80, p = e % 80;
        sR[e] = xbc[(tbase + s) * CONVD + h * HP + p];
    }
    __syncthreads();
    for (int s = 0; s < 64; s++) {
        float m = sM[t * 65 + s];
        const float4* rr = (const float4*)&sR[s * 80 + p0];
#pragma unroll
        for (int j = 0; j < 5; j++) {
            float4 rv = rr[j];
            a4[j].x += m * rv.x; a4[j].y += m * rv.y;
            a4[j].z += m * rv.z; a4[j].w += m * rv.w;
        }
    }
    float dph = Dp[h];
    const float4* xr = (const float4*)&sR[t * 80 + p0];
    float4* yo = (float4*)&y[(tbase + t) * DINNER + h * HP + p0];
#pragma unroll
    for (int j = 0; j < 5; j++) {
        float4 xv = xr[j];
        float4 o;
        o.x = a4[j].x + dph * xv.x; o.y = a4[j].y + dph * xv.y;
        o.z = a4[j].z + dph * xv.z; o.w = a4[j].w + dph * xv.w;
        yo[j] = o;
    }
}

// warp-per-row gated RMSNorm (4 rows per 128-thread block)
__global__ void k_gatermsw(const float* __restrict__ y, const float* __restrict__ zx,
                           const float* __restrict__ rms_w,
                           bf16* __restrict__ hi, bf16* __restrict__ lo) {
    int row = blockIdx.x * 4 + (threadIdx.x >> 5);
    int lane = threadIdx.x & 31;
    const float* yr = y + (size_t)row * DINNER;
    const float* zr = zx + (size_t)row * DIN;
    float v[20];
    float sq = 0.f;
#pragma unroll
    for (int j = 0; j < 20; j++) {
        int c = lane + j * 32;
        float t = yr[c] * siluf(zr[c]);
        v[j] = t; sq += t * t;
    }
#pragma unroll
    for (int o = 16; o; o >>= 1) sq += __shfl_down_sync(0xffffffffu, sq, o);
    sq = __shfl_sync(0xffffffffu, sq, 0);
    float rs = rsqrtf(sq / DINNER + 1e-5f);
    size_t o0 = (size_t)row * DINNER;
#pragma unroll
    for (int j = 0; j < 20; j++) {
        int c = lane + j * 32;
        float r = v[j] * rs * rms_w[c];
        bf16 h, l;
        split_bf16(r, h, l);
        hi[o0 + c] = h; lo[o0 + c] = l;
    }
}

__global__ void k_kpe(const float* __restrict__ gauss, float* __restrict__ kpe) {
    int t = blockIdx.x;
    int j = threadIdx.x;
    int d = t >> 10, hh = (t >> 5) & 31, w = t & 31;
    float g0 = 2.f * ((d + 0.5f) / 16.f) - 1.f;
    float g1 = 2.f * ((hh + 0.5f) / 32.f) - 1.f;
    float g2 = 2.f * ((w + 0.5f) / 32.f) - 1.f;
    float ang = 6.283185307179586f * (g0 * gauss[j] + g1 * gauss[160 + j] + g2 * gauss[320 + j]);
    kpe[(size_t)t * CDIM + j] = sinf(ang);
    kpe[(size_t)t * CDIM + 160 + j] = cosf(ang);
}

__global__ void k_pointemb(const float* __restrict__ coords, const int* __restrict__ labels,
                           const float* __restrict__ gauss, const float* __restrict__ ptab,
                           float* __restrict__ q, float* __restrict__ qpe) {
    int r = blockIdx.x;
    int j = threadIdx.x;
    float c0 = coords[r * 3 + 0] * (2.f / 128.f) - 1.f;
    float c1 = coords[r * 3 + 1] * (2.f / 256.f) - 1.f;
    float c2 = coords[r * 3 + 2] * (2.f / 256.f) - 1.f;
    float ang = 6.283185307179586f * (c0 * gauss[j] + c1 * gauss[160 + j] + c2 * gauss[320 + j]);
    int lab = labels[r];
    float s = sinf(ang) + ptab[lab * CDIM + j];
    float cc = cosf(ang) + ptab[lab * CDIM + 160 + j];
    q[r * CDIM + j] = s;      q[r * CDIM + 160 + j] = cc;
    qpe[r * CDIM + j] = s;    qpe[r * CDIM + 160 + j] = cc;
}

__global__ void k_selfattn(const float* __restrict__ q, const float* __restrict__ k,
                           const float* __restrict__ v, float* __restrict__ o) {
    int b = blockIdx.x >> 2, h = blockIdx.x & 3;
    __shared__ float sc[6][6];
    int tid = threadIdx.x;
    if (tid < 36) {
        int qi = tid / 6, ki = tid % 6;
        float s = 0.f;
        for (int d = 0; d < 80; d++)
            s += q[(b * 6 + qi) * CDIM + h * 80 + d] * k[(b * 6 + ki) * CDIM + h * 80 + d];
        sc[qi][ki] = s * 0.11180339887498948f;
    }
    __syncthreads();
    if (tid < 6) {
        float mx = -1e30f;
        for (int j = 0; j < 6; j++) mx = fmaxf(mx, sc[tid][j]);
        float sum = 0.f;
        for (int j = 0; j < 6; j++) { float e = expf(sc[tid][j] - mx); sc[tid][j] = e; sum += e; }
        float inv = 1.f / sum;
        for (int j = 0; j < 6; j++) sc[tid][j] *= inv;
    }
    __syncthreads();
    for (int e = tid; e < 480; e += 128) {
        int qi = e / 80, d = e % 80;
        float a = 0.f;
        for (int j = 0; j < 6; j++) a += sc[qi][j] * v[(b * 6 + j) * CDIM + h * 80 + d];
        o[(b * 6 + qi) * CDIM + h * 80 + d] = a;
    }
}

__global__ void k_xscore6(const float* __restrict__ q, const float* __restrict__ kimg,
                          float* __restrict__ att, int kstride) {
    int bh = blockIdx.x;
    int b = bh >> 2, h = bh & 3;
    __shared__ float sq[6][40];
    int tid = threadIdx.x;
    if (tid < 240) sq[tid / 40][tid % 40] = q[(b * 6 + tid / 40) * INNERD + h * 40 + tid % 40];
    __syncthreads();
    int key = blockIdx.y * 256 + tid;
    const float4* kr = (const float4*)(kimg + ((size_t)b * NTOK + key) * kstride + h * 40);
    float kv[40];
#pragma unroll
    for (int d4 = 0; d4 < 10; d4++) {
        float4 v = kr[d4];
        kv[d4 * 4 + 0] = v.x; kv[d4 * 4 + 1] = v.y;
        kv[d4 * 4 + 2] = v.z; kv[d4 * 4 + 3] = v.w;
    }
    int r0 = b * 24 + h * 6;
#pragma unroll
    for (int qi = 0; qi < 6; qi++) {
        float s = 0.f;
#pragma unroll
        for (int d = 0; d < 40; d++) s += sq[qi][d] * kv[d];
        att[(size_t)(r0 + qi) * NTOK + key] = s * 0.15811388300841897f;
    }
}

__global__ void k_xsoftmax(float* __restrict__ att) {
    extern __shared__ float srow[];
    int r = blockIdx.x, tid = threadIdx.x;
    float* row = att + (size_t)r * NTOK;
    float mx = -1e30f;
    for (int i = tid; i < NTOK; i += 256) {
        float v = row[i];
        srow[i] = v;
        mx = fmaxf(mx, v);
    }
    mx = blockReduceMax(mx);
    float s = 0.f;
    for (int i = tid; i < NTOK; i += 256) {
        float e = expf(srow[i] - mx);
        srow[i] = e;
        s += e;
    }
    s = blockReduceSum(s);
    float inv = 1.f / s;
    for (int i = tid; i < NTOK; i += 256) row[i] = srow[i] * inv;
}

__global__ void k_xout6(const float* __restrict__ att, const float* __restrict__ v,
                        float* __restrict__ part) {
    int bh = blockIdx.x, seg = blockIdx.y;
    int b = bh >> 2, h = bh & 3;
    int r0 = b * 24 + h * 6;
    __shared__ float svv[64 * 40];
    __shared__ float sa[6 * 64];
    int tid = threadIdx.x;
    int qi = tid / 40, d = tid % 40;
    float acc = 0.f;
    int key0 = seg * 1024;
    for (int c = 0; c < 16; c++) {
        int kc = key0 + c * 64;
        for (int e = tid; e < 2560; e += 240) {
            int k = e / 40, dd = e % 40;
            svv[e] = v[((size_t)b * NTOK + kc + k) * INNERD + h * 40 + dd];
        }
        for (int e = tid; e < 384; e += 240)
            sa[e] = att[(size_t)(r0 + e / 64) * NTOK + kc + (e & 63)];
        __syncthreads();
#pragma unroll 8
        for (int k = 0; k < 64; k++) acc += sa[qi * 64 + k] * svv[k * 40 + d];
        __syncthreads();
    }
    part[((bh * 16 + seg) * 6 + qi) * 40 + d] = acc;
}

__global__ void k_xout_c6(const float* __restrict__ part, float* __restrict__ o) {
    int bh = blockIdx.x;
    int b = bh >> 2, h = bh & 3;
    int tid = threadIdx.x;
    int qi = tid / 40, d = tid % 40;
    float s = 0.f;
#pragma unroll
    for (int g = 0; g < 16; g++) s += part[((bh * 16 + g) * 6 + qi) * 40 + d];
    o[(b * 6 + qi) * INNERD + h * 40 + d] = s;
}

__global__ void k_i2t(const float* __restrict__ qimg, const float* __restrict__ ks,
                      const float* __restrict__ vs,
                      bf16* __restrict__ ohi, bf16* __restrict__ olo) {
    __shared__ float sk[960], sv[960];
    __shared__ float s_q[32 * 160];
    int b = blockIdx.y;
    int tid = threadIdx.x;
    int tok0 = blockIdx.x * 32;
    for (int e = tid; e < 960; e += 128) { sk[e] = ks[b * 960 + e]; sv[e] = vs[b * 960 + e]; }
    for (int e = tid; e < 32 * 160; e += 128) {
        int t = e / 160, j = e % 160;
        s_q[e] = qimg[((size_t)b * NTOK + tok0 + t) * 320 + 160 + j];
    }
    __syncthreads();
    int tok = tid >> 2;
    int h = tid & 3;
    const float* qrow = &s_q[tok * 160 + h * 40];
    float qv[40];
#pragma unroll
    for (int d = 0; d < 40; d++) qv[d] = qrow[d];
    float sc[6];
    float mx = -1e30f;
#pragma unroll
    for (int j = 0; j < 6; j++) {
        float s = 0.f;
#pragma unroll
        for (int d = 0; d < 40; d++) s += qv[d] * sk[j * INNERD + h * 40 + d];
        sc[j] = s * 0.15811388300841897f;
        mx = fmaxf(mx, sc[j]);
    }
    float sum = 0.f;
#pragma unroll
    for (int j = 0; j < 6; j++) { sc[j] = expf(sc[j] - mx); sum += sc[j]; }
    float inv = 1.f / sum;
    size_t rowo = ((size_t)b * NTOK + tok0 + tok) * 192;
#pragma unroll
    for (int d = 0; d < 40; d++) {
        float a = 0.f;
#pragma unroll
        for (int j = 0; j < 6; j++) a += sc[j] * sv[j * INNERD + h * 40 + d];
        a *= inv;
        bf16 hh, ll;
        split_bf16(a, hh, ll);
        ohi[rowo + h * 40 + d] = hh;
        olo[rowo + h * 40 + d] = ll;
    }
    if (h == 0) {
        bf16 z = __float2bfloat16(0.f);
#pragma unroll
        for (int d = 160; d < 192; d++) { ohi[rowo + d] = z; olo[rowo + d] = z; }
    }
}

extern "C" void kernel_launch(void* const* d_in, const int* in_sizes, int n_in,
                              void* d_out, int out_size) {
    const float* x        = (const float*)d_in[0];
    const float* coords   = (const float*)d_in[1];
    const int*   labels   = (const int*)  d_in[2];
    const float* ln_w     = (const float*)d_in[3];
    const float* ln_b     = (const float*)d_in[4];
    const float* in_w     = (const float*)d_in[5];
    const float* conv_w   = (const float*)d_in[6];
    const float* conv_b   = (const float*)d_in[7];
    const float* dt_bias  = (const float*)d_in[8];
    const float* A_log    = (const float*)d_in[9];
    const float* Dp       = (const float*)d_in[10];
    const float* rms_w    = (const float*)d_in[11];
    const float* out_w    = (const float*)d_in[12];
    const float* pe_gauss = (const float*)d_in[13];
    const float* point_tab= (const float*)d_in[14];
    const float* sa_w     = (const float*)d_in[15];
    const float* sa_b     = (const float*)d_in[16];
    const float* t2i_w    = (const float*)d_in[17];
    const float* t2i_b    = (const float*)d_in[18];
    const float* t2i_ow   = (const float*)d_in[19];
    const float* t2i_ob   = (const float*)d_in[20];
    const float* i2t_w    = (const float*)d_in[21];
    const float* i2t_b    = (const float*)d_in[22];
    const float* i2t_ow   = (const float*)d_in[23];
    const float* i2t_ob   = (const float*)d_in[24];
    const float* norms_w  = (const float*)d_in[25];
    const float* norms_b  = (const float*)d_in[26];
    const float* mlp_w1   = (const float*)d_in[27];
    const float* mlp_b1   = (const float*)d_in[28];
    const float* mlp_w2   = (const float*)d_in[29];
    const float* mlp_b2   = (const float*)d_in[30];
    float* out = (float*)d_out;

    const int SMEM_DYN = 2 * 4 * 128 * 40 * 2;  // 81920
    cudaFuncSetAttribute(k_mma, cudaFuncAttributeMaxDynamicSharedMemorySize, SMEM_DYN);
    const int SMEM_SOFT = NTOK * 4;  // 65536
    cudaFuncSetAttribute(k_xsoftmax, cudaFuncAttributeMaxDynamicSharedMemorySize, SMEM_SOFT);

    float* ar = nullptr;
    cudaGetSymbolAddress((void**)&ar, g_arena);

    float* zx     = ar + OFF_ZX;
    float* xbc    = ar + OFF_XBC;
    float* dtb    = ar + OFF_DTB;
    float* cum    = ar + OFF_CUM;
    float* csum   = ar + OFF_CSUM;
    float* sloc   = ar + OFF_SLOC;
    float* sbeg   = ar + OFF_SBEG;
    float* ybuf   = ar + OFF_Y;
    float* keys   = ar + OFF_KEYS;
    float* kpe    = ar + OFF_KPE;
    float* tkiq   = ar + OFF_TKIQ;
    float* tv     = ar + OFF_TV;
    float* att    = ar + OFF_ATT;
    float* queries= ar + OFF_Q;
    float* qpe    = ar + OFF_QPE;
    float* sq     = ar + OFF_SQ;
    float* sk     = ar + OFF_SK;
    float* sv     = ar + OFF_SV;
    float* so     = ar + OFF_SO;
    float* qs160  = ar + OFF_QS160;
    float* ks160  = ar + OFF_KS160;
    float* vs160  = ar + OFF_VS160;
    float* tatt   = ar + OFF_TATT;
    float* mlph   = ar + OFF_MLPH;
    float* xpart  = ar + OFF_XPART;
    float* bkq    = ar + OFF_BKQ;

    bf16* xnH  = (bf16*)(ar + OFF_XNH);
    bf16* xnL  = (bf16*)(ar + OFF_XNL);
    bf16* yH   = (bf16*)(ar + OFF_YH);
    bf16* yL   = (bf16*)(ar + OFF_YL);
    bf16* kH   = (bf16*)(ar + OFF_KH);
    bf16* kL   = (bf16*)(ar + OFF_KL);
    bf16* kpH  = (bf16*)(ar + OFF_KPH);
    bf16* kpL  = (bf16*)(ar + OFF_KPL);
    bf16* iaH  = (bf16*)(ar + OFF_IAH);
    bf16* iaL  = (bf16*)(ar + OFF_IAL);
    bf16* inwH = (bf16*)(ar + OFF_INWH);
    bf16* inwL = (bf16*)(ar + OFF_INWL);
    bf16* outwH= (bf16*)(ar + OFF_OUTWH);
    bf16* outwL= (bf16*)(ar + OFF_OUTWL);
    bf16* t2iv = (bf16*)(ar + OFF_T2IV);
    bf16* i2tow= (bf16*)(ar + OFF_I2TOW);
    bf16* wkq  = (bf16*)(ar + OFF_WKQ);

    const int MROWS = NBATCH * NTOK;

    // #1 tln, #2 wsplit(in_w), #3 k_mma(in_proj), #4 convdt8 (profiled this round)
    k_tln<<<dim3(NTOK / 32, NBATCH), 256>>>(x, ln_w, ln_b, xnH, xnL);
    k_wsplit<<<1760, 256>>>(in_w, inwH, inwL, DIN, CDIM, 1408, 320);
    k_mma<<<dim3(11, 256), 256, SMEM_DYN>>>(xnH, xnL, inwH, inwL, nullptr, nullptr,
                                            zx, nullptr, nullptr, nullptr, nullptr, nullptr,
                                            DIN, 320, 10);
    k_convdt8<<<MROWS / 8, 256>>>(zx, conv_w, conv_b, dt_bias, xbc, dtb);

    k_wsplit<<<960, 256>>>(out_w, outwH, outwL, CDIM, DINNER, 384, 640);
    for (int i = 0; i < 2; i++) {
        k_wsplit_cat<<<480, 256>>>(t2i_w + (size_t)(i * 3 + 1) * INNERD * CDIM,
                                   i2t_w + (size_t)(i * 3 + 0) * INNERD * CDIM,
                                   wkq + i * 245760, wkq + i * 245760 + 122880);
        k_biascat<<<1, 384>>>(t2i_b + (i * 3 + 1) * INNERD, i2t_b + (i * 3 + 0) * INNERD,
                              bkq + i * 384);
        k_wsplit<<<320, 256>>>(t2i_w + (size_t)(i * 3 + 2) * INNERD * CDIM,
                               t2iv + i * 163840, t2iv + i * 163840 + 81920, INNERD, CDIM, 256, 320);
        k_wsplit<<<288, 256>>>(i2t_ow + (size_t)i * CDIM * INNERD,
                               i2tow + i * 147456, i2tow + i * 147456 + 73728, CDIM, INNERD, 384, 192);
    }
    k_kpe<<<NTOK, 160>>>(pe_gauss, kpe);
    k_pointemb<<<12, 160>>>(coords, labels, pe_gauss, point_tab, queries, qpe);

    k_cumsum<<<NBATCH * NH, NCHUNK>>>(dtb, A_log, cum, csum);
    k_chunkstate<<<NBATCH * NH * NCHUNK, 256>>>(xbc, cum, dtb, sloc);
    k_scan<<<dim3(NBATCH * NH, 10), 256>>>(sloc, csum, sbeg);
    k_chunkout<<<NBATCH * NH * NCHUNK, 256>>>(xbc, cum, dtb, sbeg, Dp, ybuf);
    k_gatermsw<<<MROWS / 4, 128>>>(ybuf, zx, rms_w, yH, yL);
    k_mma<<<dim3(3, 256), 256, SMEM_DYN>>>(yH, yL, outwH, outwL, nullptr, nullptr,
                                           keys, kH, kL, kpe, kpH, kpL, CDIM, 640, 20);

    for (int i = 0; i < 2; i++) {
        const float* swq = sa_w + (size_t)(i * 4 + 0) * CDIM * CDIM;
        const float* swo = sa_w + (size_t)(i * 4 + 3) * CDIM * CDIM;
        const float* sbq = sa_b + (i * 4 + 0) * CDIM;
        const float* sbo = sa_b + (i * 4 + 3) * CDIM;

        // fused qkv: weights sa_w[i][0..2] contiguous; pe applies to q,k only (n<640), none at i=0
        int a2lim = (i == 0) ? 0 : 640;
        k_tiny_seg<<<dim3(15, 12), 64>>>(queries, qpe, swq, sbq, sq, 960, CDIM,
                                         320, 3840, a2lim);
        k_selfattn<<<8, 128>>>(sq, sk, sv, so);
        k_tiny<<<dim3(5, 12), 64>>>(so, nullptr, swo, sbo, (i == 0) ? nullptr : queries,
                                    queries, CDIM, CDIM, 0);
        k_ln<<<12, CDIM>>>(queries, queries, norms_w + (i * 4 + 0) * CDIM,
                           norms_b + (i * 4 + 0) * CDIM, nullptr, nullptr,
                           nullptr, nullptr, nullptr);

        k_tiny<<<dim3(3, 12), 64>>>(queries, qpe, t2i_w + (size_t)(i * 3 + 0) * INNERD * CDIM,
                                    t2i_b + (i * 3 + 0) * INNERD, nullptr, qs160, INNERD, CDIM, 0);
        k_mma<<<dim3(3, 256), 256, SMEM_DYN>>>(kpH, kpL, wkq + i * 245760, wkq + i * 245760 + 122880,
                                               bkq + i * 384, nullptr,
                                               tkiq, nullptr, nullptr, nullptr, nullptr, nullptr,
                                               320, 320, 10);
        k_mma<<<dim3(2, 256), 256, SMEM_DYN>>>(kH, kL, t2iv + i * 163840, t2iv + i * 163840 + 81920,
                                               t2i_b + (i * 3 + 2) * INNERD, nullptr,
                                               tv, nullptr, nullptr, nullptr, nullptr, nullptr,
                                               INNERD, 320, 10);
        k_xscore6<<<dim3(8, 64), 256>>>(qs160, tkiq, att, 320);
        k_xsoftmax<<<48, 256, SMEM_SOFT>>>(att);
        k_xout6<<<dim3(8, 16), 240>>>(att, tv, xpart);
        k_xout_c6<<<8, 240>>>(xpart, tatt);
        k_tiny<<<dim3(5, 12), 64>>>(tatt, nullptr, t2i_ow + (size_t)i * CDIM * INNERD,
                                    t2i_ob + i * CDIM, queries, queries, CDIM, INNERD, 0);
        k_ln<<<12, CDIM>>>(queries, queries, norms_w + (i * 4 + 1) * CDIM,
                           norms_b + (i * 4 + 1) * CDIM, nullptr, nullptr,
                           nullptr, nullptr, nullptr);

        k_tiny<<<dim3(16, 12), 64>>>(queries, nullptr, mlp_w1 + (size_t)i * MLPD * CDIM,
                                     mlp_b1 + i * MLPD, nullptr, mlph, MLPD, CDIM, 1);
        k_tiny<<<dim3(5, 12), 64>>>(mlph, nullptr, mlp_w2 + (size_t)i * CDIM * MLPD,
                                    mlp_b2 + i * CDIM, queries, queries, CDIM, MLPD, 0);
        k_ln<<<12, CDIM>>>(queries, queries, norms_w + (i * 4 + 2) * CDIM,
                           norms_b + (i * 4 + 2) * CDIM, nullptr, nullptr,
                           nullptr, nullptr, nullptr);

        // fused ks/vs: i2t_w[i][1..2] contiguous; pe applies to ks only (n<160)
        k_tiny_seg<<<dim3(5, 12), 64>>>(queries, qpe,
                                        i2t_w + (size_t)(i * 3 + 1) * INNERD * CDIM,
                                        i2t_b + (i * 3 + 1) * INNERD, ks160, 320, CDIM,
                                        160, 1920, 160);
        k_i2t<<<dim3(NTOK / 32, NBATCH), 128>>>(tkiq, ks160, vs160, iaH, iaL);
        k_mma<<<dim3(3, 256), 256, SMEM_DYN>>>(iaH, iaL, i2tow + i * 147456, i2tow + i * 147456 + 73728,
                                               i2t_ob + i * CDIM, keys,
                                               keys, nullptr, nullptr, nullptr, nullptr, nullptr,
                                               CDIM, 192, 6);
        if (i == 0) {
            k_lnw<<<MROWS / 4, 128>>>(keys, keys, norms_w + (i * 4 + 3) * CDIM,
                                      norms_b + (i * 4 + 3) * CDIM, kH, kL,
                                      kpe, kpH, kpL);
        } else {
            k_lnw<<<MROWS / 4, 128>>>(keys, keys, norms_w + (i * 4 + 3) * CDIM,
                                      norms_b + (i * 4 + 3) * CDIM, nullptr, nullptr,
                                      nullptr, nullptr, nullptr);
        }
    }

    k_transpose_out<<<dim3(NTOK / 32, CDIM / 32, NBATCH), dim3(32, 8)>>>(keys, out);
}